// round 1
// baseline (speedup 1.0000x reference)
#include <cuda_runtime.h>

// Problem sizes (fixed)
#define MB      4096      // B*S rows
#define DMODEL  1024
#define NHEAD   16
#define HDIM    64
#define SEQ     2048
#define FF      4096

// ---------------- scratch (device globals; no allocs allowed) ----------------
__device__ __align__(128) float g_Q [MB * DMODEL];   // [B,H,S,HD]
__device__ __align__(128) float g_K [MB * DMODEL];
__device__ __align__(128) float g_V [MB * DMODEL];
__device__ __align__(128) float g_O [MB * DMODEL];   // attention out [B,H,S,HD]
__device__ __align__(128) float g_t1[MB * DMODEL];   // X + attn_proj (pre-LN1)
__device__ __align__(128) float g_y [MB * DMODEL];   // LN1 output
__device__ __align__(128) float g_ff[MB * FF];       // relu(y@W1+b1)
__device__ __align__(128) float g_z [MB * DMODEL];   // y + ffn (pre-LN2)

// =============================== GEMM ========================================
// 128x128 tile, BK=16, 256 threads, 8x8 per-thread microtile, reg-prefetch.
// MODE 0/1/2: C = X @ Wq/k/v[h] + b    -> g_Q/g_K/g_V   (B layout [H,D,HD])
// MODE 3   : C = O @ Wo + bo + X       -> g_t1          (A layout [B,H,S,HD])
// MODE 4   : C = relu(y @ W1 + b1)     -> g_ff
// MODE 5   : C = ff @ W2 + b2 + y      -> g_z
constexpr int BM = 128, BN = 128, BK = 16;

template<int MODE>
__device__ __forceinline__ void load_frag(
    const float* __restrict__ A, const float* __restrict__ Bm,
    int m0, int n0, int k0, int aRow, int aK, int bK, int bN,
    float4& ra0, float4& ra1, float4& rb0, float4& rb1)
{
    constexpr int Kd = (MODE == 5) ? FF : DMODEL;
    const float* ap;
    if constexpr (MODE == 3) {
        int m = m0 + aRow, k = k0 + aK;
        int b = m >> 11, s = m & 2047, h = k >> 6, e = k & 63;
        ap = A + ((((size_t)(b * NHEAD + h) * SEQ) + s) * HDIM + e);
    } else {
        ap = A + (size_t)(m0 + aRow) * Kd + (k0 + aK);
    }
    ra0 = *(const float4*)ap;
    ra1 = *(const float4*)(ap + 4);

    int k = k0 + bK;
    if constexpr (MODE <= 2) {
        int n = n0 + bN;
        rb0 = *(const float4*)(Bm + (size_t)(n >> 6) * (DMODEL * HDIM)
                                  + (size_t)k * HDIM + (n & 63));
        int n2 = n + 4;
        rb1 = *(const float4*)(Bm + (size_t)(n2 >> 6) * (DMODEL * HDIM)
                                  + (size_t)k * HDIM + (n2 & 63));
    } else {
        constexpr int ldb = (MODE == 4) ? FF : DMODEL;
        const float* bp = Bm + (size_t)k * ldb + n0 + bN;
        rb0 = *(const float4*)bp;
        rb1 = *(const float4*)(bp + 4);
    }
}

template<int MODE>
__global__ __launch_bounds__(256)
void gemm128(const float* __restrict__ Aarg, const float* __restrict__ Bm,
             const float* __restrict__ bias, const float* __restrict__ addv)
{
    constexpr int Kd = (MODE == 5) ? FF : DMODEL;
    __shared__ __align__(16) float As[BK][BM + 4];
    __shared__ __align__(16) float Bs[BK][BN];

    const int tid  = threadIdx.x;
    const int m0   = blockIdx.y * BM, n0 = blockIdx.x * BN;
    const int ty   = tid >> 4, tx = tid & 15;
    const int aRow = tid >> 1, aK = (tid & 1) * 8;
    const int bK   = tid >> 4, bN = (tid & 15) * 8;

    const float* A;
    if constexpr (MODE <= 2)      A = Aarg;
    else if constexpr (MODE == 3) A = g_O;
    else if constexpr (MODE == 4) A = g_y;
    else                          A = g_ff;

    float acc[8][8];
    #pragma unroll
    for (int i = 0; i < 8; i++)
        #pragma unroll
        for (int j = 0; j < 8; j++) acc[i][j] = 0.f;

    float4 ra0, ra1, rb0, rb1;
    load_frag<MODE>(A, Bm, m0, n0, 0, aRow, aK, bK, bN, ra0, ra1, rb0, rb1);

    for (int k0 = 0; k0 < Kd; k0 += BK) {
        As[aK + 0][aRow] = ra0.x; As[aK + 1][aRow] = ra0.y;
        As[aK + 2][aRow] = ra0.z; As[aK + 3][aRow] = ra0.w;
        As[aK + 4][aRow] = ra1.x; As[aK + 5][aRow] = ra1.y;
        As[aK + 6][aRow] = ra1.z; As[aK + 7][aRow] = ra1.w;
        *(float4*)&Bs[bK][bN]     = rb0;
        *(float4*)&Bs[bK][bN + 4] = rb1;
        __syncthreads();
        if (k0 + BK < Kd)
            load_frag<MODE>(A, Bm, m0, n0, k0 + BK, aRow, aK, bK, bN, ra0, ra1, rb0, rb1);
        #pragma unroll
        for (int kk = 0; kk < BK; kk++) {
            float4 a0 = *(const float4*)&As[kk][ty * 8];
            float4 a1 = *(const float4*)&As[kk][ty * 8 + 4];
            float4 b0 = *(const float4*)&Bs[kk][tx * 8];
            float4 b1 = *(const float4*)&Bs[kk][tx * 8 + 4];
            float av[8] = {a0.x, a0.y, a0.z, a0.w, a1.x, a1.y, a1.z, a1.w};
            float bv[8] = {b0.x, b0.y, b0.z, b0.w, b1.x, b1.y, b1.z, b1.w};
            #pragma unroll
            for (int i = 0; i < 8; i++)
                #pragma unroll
                for (int j = 0; j < 8; j++)
                    acc[i][j] = fmaf(av[i], bv[j], acc[i][j]);
        }
        __syncthreads();
    }

    float* outp;
    if constexpr (MODE == 0)      outp = g_Q;
    else if constexpr (MODE == 1) outp = g_K;
    else if constexpr (MODE == 2) outp = g_V;
    else if constexpr (MODE == 3) outp = g_t1;
    else if constexpr (MODE == 4) outp = g_ff;
    else                          outp = g_z;

    #pragma unroll
    for (int i = 0; i < 8; i++) {
        int m = m0 + ty * 8 + i;
        #pragma unroll
        for (int j = 0; j < 8; j++) {
            int n = n0 + tx * 8 + j;
            float v = acc[i][j] + bias[n];
            if constexpr (MODE <= 2) {
                int b = m >> 11, s = m & 2047, h = n >> 6, e = n & 63;
                outp[(((size_t)(b * NHEAD + h) * SEQ) + s) * HDIM + e] = v;
            } else if constexpr (MODE == 3) {
                size_t idx = (size_t)m * DMODEL + n;
                outp[idx] = v + addv[idx];
            } else if constexpr (MODE == 4) {
                outp[(size_t)m * FF + n] = fmaxf(v, 0.f);
            } else {
                size_t idx = (size_t)m * DMODEL + n;
                outp[idx] = v + g_y[idx];
            }
        }
    }
}

// ============================ Flash attention ================================
// grid (32 q-tiles, 32 bh), 256 threads. 64 q-rows x HD=64 output per block,
// KV in 64-wide tiles, online softmax. smem: Qs/Kt/Vs/Ps each [64][68] fp32.
__global__ __launch_bounds__(256)
void attn_kernel()
{
    extern __shared__ __align__(16) float sm[];
    float* Qs = sm;                 // [64][68]  Q (pre-scaled by 1/8)
    float* Kt = Qs + 64 * 68;       // [64][68]  K transposed: Kt[k][c]
    float* Vs = Kt + 64 * 68;       // [64][68]  V: Vs[c][e]
    float* Ps = Vs + 64 * 68;       // [64][68]  probs

    const int tid = threadIdx.x;
    const int ty  = tid >> 4, tx = tid & 15;
    const int bh  = blockIdx.y;
    const int q0  = blockIdx.x * 64;

    const float* Qb = g_Q + (size_t)bh * SEQ * HDIM;
    const float* Kb = g_K + (size_t)bh * SEQ * HDIM;
    const float* Vb = g_V + (size_t)bh * SEQ * HDIM;
    float*       Ob = g_O + (size_t)bh * SEQ * HDIM;

    {   // load Q tile, scaled by 1/sqrt(HD)=0.125
        int r = tid >> 2;
        int c = (tid & 3) * 16;
        const float4* src = (const float4*)(Qb + (size_t)(q0 + r) * HDIM + c);
        #pragma unroll
        for (int w = 0; w < 4; w++) {
            float4 v = src[w];
            float* d = &Qs[r * 68 + c + w * 4];
            d[0] = v.x * 0.125f; d[1] = v.y * 0.125f;
            d[2] = v.z * 0.125f; d[3] = v.w * 0.125f;
        }
    }

    float m_i[4], l_i[4], acc[4][4];
    #pragma unroll
    for (int i = 0; i < 4; i++) {
        m_i[i] = -1e30f; l_i[i] = 0.f;
        #pragma unroll
        for (int j = 0; j < 4; j++) acc[i][j] = 0.f;
    }

    for (int j0 = 0; j0 < SEQ; j0 += 64) {
        __syncthreads();   // prior iter's Kt/Vs/Ps reads done; also covers Qs store (iter 0)
        {   // load K (transposed) and V tiles
            int r = tid >> 2;
            int c = (tid & 3) * 16;
            const float4* ks = (const float4*)(Kb + (size_t)(j0 + r) * HDIM + c);
            const float4* vp = (const float4*)(Vb + (size_t)(j0 + r) * HDIM + c);
            #pragma unroll
            for (int w = 0; w < 4; w++) {
                float4 kv = ks[w];
                Kt[(c + w * 4 + 0) * 68 + r] = kv.x;
                Kt[(c + w * 4 + 1) * 68 + r] = kv.y;
                Kt[(c + w * 4 + 2) * 68 + r] = kv.z;
                Kt[(c + w * 4 + 3) * 68 + r] = kv.w;
                *(float4*)&Vs[r * 68 + c + w * 4] = vp[w];
            }
        }
        __syncthreads();

        // S = (Q/8) K^T  : thread tile rows ty*4.., cols tx*4..
        float s[4][4];
        #pragma unroll
        for (int i = 0; i < 4; i++)
            #pragma unroll
            for (int j = 0; j < 4; j++) s[i][j] = 0.f;
        #pragma unroll 8
        for (int k = 0; k < 64; k++) {
            float a0 = Qs[(ty * 4 + 0) * 68 + k];
            float a1 = Qs[(ty * 4 + 1) * 68 + k];
            float a2 = Qs[(ty * 4 + 2) * 68 + k];
            float a3 = Qs[(ty * 4 + 3) * 68 + k];
            float4 b4 = *(const float4*)&Kt[k * 68 + tx * 4];
            s[0][0] = fmaf(a0, b4.x, s[0][0]); s[0][1] = fmaf(a0, b4.y, s[0][1]);
            s[0][2] = fmaf(a0, b4.z, s[0][2]); s[0][3] = fmaf(a0, b4.w, s[0][3]);
            s[1][0] = fmaf(a1, b4.x, s[1][0]); s[1][1] = fmaf(a1, b4.y, s[1][1]);
            s[1][2] = fmaf(a1, b4.z, s[1][2]); s[1][3] = fmaf(a1, b4.w, s[1][3]);
            s[2][0] = fmaf(a2, b4.x, s[2][0]); s[2][1] = fmaf(a2, b4.y, s[2][1]);
            s[2][2] = fmaf(a2, b4.z, s[2][2]); s[2][3] = fmaf(a2, b4.w, s[2][3]);
            s[3][0] = fmaf(a3, b4.x, s[3][0]); s[3][1] = fmaf(a3, b4.y, s[3][1]);
            s[3][2] = fmaf(a3, b4.z, s[3][2]); s[3][3] = fmaf(a3, b4.w, s[3][3]);
        }

        // online softmax update (row stats shared across the 16-lane tx group)
        #pragma unroll
        for (int i = 0; i < 4; i++) {
            float pm = fmaxf(fmaxf(s[i][0], s[i][1]), fmaxf(s[i][2], s[i][3]));
            #pragma unroll
            for (int o = 8; o >= 1; o >>= 1)
                pm = fmaxf(pm, __shfl_xor_sync(0xffffffffu, pm, o));
            float mn   = fmaxf(m_i[i], pm);
            float corr = __expf(m_i[i] - mn);
            float rs = 0.f;
            #pragma unroll
            for (int j = 0; j < 4; j++) {
                float p = __expf(s[i][j] - mn);
                s[i][j] = p; rs += p;
            }
            #pragma unroll
            for (int o = 8; o >= 1; o >>= 1)
                rs += __shfl_xor_sync(0xffffffffu, rs, o);
            l_i[i] = l_i[i] * corr + rs;
            m_i[i] = mn;
            #pragma unroll
            for (int j = 0; j < 4; j++) acc[i][j] *= corr;
        }

        #pragma unroll
        for (int i = 0; i < 4; i++)
            *(float4*)&Ps[(ty * 4 + i) * 68 + tx * 4] =
                make_float4(s[i][0], s[i][1], s[i][2], s[i][3]);
        __syncthreads();

        // acc += P @ V
        #pragma unroll 8
        for (int k = 0; k < 64; k++) {
            float a0 = Ps[(ty * 4 + 0) * 68 + k];
            float a1 = Ps[(ty * 4 + 1) * 68 + k];
            float a2 = Ps[(ty * 4 + 2) * 68 + k];
            float a3 = Ps[(ty * 4 + 3) * 68 + k];
            float4 b4 = *(const float4*)&Vs[k * 68 + tx * 4];
            acc[0][0] = fmaf(a0, b4.x, acc[0][0]); acc[0][1] = fmaf(a0, b4.y, acc[0][1]);
            acc[0][2] = fmaf(a0, b4.z, acc[0][2]); acc[0][3] = fmaf(a0, b4.w, acc[0][3]);
            acc[1][0] = fmaf(a1, b4.x, acc[1][0]); acc[1][1] = fmaf(a1, b4.y, acc[1][1]);
            acc[1][2] = fmaf(a1, b4.z, acc[1][2]); acc[1][3] = fmaf(a1, b4.w, acc[1][3]);
            acc[2][0] = fmaf(a2, b4.x, acc[2][0]); acc[2][1] = fmaf(a2, b4.y, acc[2][1]);
            acc[2][2] = fmaf(a2, b4.z, acc[2][2]); acc[2][3] = fmaf(a2, b4.w, acc[2][3]);
            acc[3][0] = fmaf(a3, b4.x, acc[3][0]); acc[3][1] = fmaf(a3, b4.y, acc[3][1]);
            acc[3][2] = fmaf(a3, b4.z, acc[3][2]); acc[3][3] = fmaf(a3, b4.w, acc[3][3]);
        }
    }

    #pragma unroll
    for (int i = 0; i < 4; i++) {
        float inv = 1.f / l_i[i];
        #pragma unroll
        for (int j = 0; j < 4; j++)
            Ob[(size_t)(q0 + ty * 4 + i) * HDIM + tx * 4 + j] = acc[i][j] * inv;
    }
}

// =============================== LayerNorm ===================================
// one row (1024) per block, 256 threads, two-pass (mean then var).
__global__ __launch_bounds__(256)
void ln_kernel(const float* __restrict__ g, const float* __restrict__ b,
               float* __restrict__ dstArg, int which)
{
    __shared__ float red[8];
    __shared__ float bc;
    const int tid = threadIdx.x;
    const int row = blockIdx.x;
    const float* src = (which == 0) ? g_t1 : g_z;
    float*       dst = (which == 0) ? g_y  : dstArg;

    float4 v = ((const float4*)(src + (size_t)row * DMODEL))[tid];
    float s = v.x + v.y + v.z + v.w;
    #pragma unroll
    for (int o = 16; o >= 1; o >>= 1) s += __shfl_xor_sync(0xffffffffu, s, o);
    if ((tid & 31) == 0) red[tid >> 5] = s;
    __syncthreads();
    if (tid == 0) {
        float t = 0.f;
        #pragma unroll
        for (int i = 0; i < 8; i++) t += red[i];
        bc = t;
    }
    __syncthreads();
    float mu = bc * (1.f / DMODEL);
    float dx = v.x - mu, dy = v.y - mu, dz = v.z - mu, dw = v.w - mu;
    float s2 = dx * dx + dy * dy + dz * dz + dw * dw;
    #pragma unroll
    for (int o = 16; o >= 1; o >>= 1) s2 += __shfl_xor_sync(0xffffffffu, s2, o);
    __syncthreads();
    if ((tid & 31) == 0) red[tid >> 5] = s2;
    __syncthreads();
    if (tid == 0) {
        float t = 0.f;
        #pragma unroll
        for (int i = 0; i < 8; i++) t += red[i];
        bc = t;
    }
    __syncthreads();
    float rstd = rsqrtf(bc * (1.f / DMODEL) + 1e-5f);
    float4 gg = ((const float4*)g)[tid];
    float4 bb = ((const float4*)b)[tid];
    float4 o4;
    o4.x = dx * rstd * gg.x + bb.x;
    o4.y = dy * rstd * gg.y + bb.y;
    o4.z = dz * rstd * gg.z + bb.z;
    o4.w = dw * rstd * gg.w + bb.w;
    ((float4*)(dst + (size_t)row * DMODEL))[tid] = o4;
}

// ================================ launch =====================================
extern "C" void kernel_launch(void* const* d_in, const int* in_sizes, int n_in,
                              void* d_out, int out_size)
{
    (void)in_sizes; (void)n_in; (void)out_size;
    const float* X   = (const float*)d_in[0];
    const float* Wq  = (const float*)d_in[1];
    const float* bq  = (const float*)d_in[2];
    const float* Wk  = (const float*)d_in[3];
    const float* bk  = (const float*)d_in[4];
    const float* Wv  = (const float*)d_in[5];
    const float* bv  = (const float*)d_in[6];
    const float* Wo  = (const float*)d_in[7];
    const float* bo  = (const float*)d_in[8];
    const float* l1g = (const float*)d_in[9];
    const float* l1b = (const float*)d_in[10];
    const float* W1  = (const float*)d_in[11];
    const float* b1  = (const float*)d_in[12];
    const float* W2  = (const float*)d_in[13];
    const float* b2  = (const float*)d_in[14];
    const float* l2g = (const float*)d_in[15];
    const float* l2b = (const float*)d_in[16];

    const int attn_smem = 4 * 64 * 68 * 4;   // 69632 B
    cudaFuncSetAttribute(attn_kernel, cudaFuncAttributeMaxDynamicSharedMemorySize, attn_smem);

    dim3 thr(256);
    gemm128<0><<<dim3(8, 32), thr>>>(X, Wq, bq, nullptr);
    gemm128<1><<<dim3(8, 32), thr>>>(X, Wk, bk, nullptr);
    gemm128<2><<<dim3(8, 32), thr>>>(X, Wv, bv, nullptr);
    attn_kernel<<<dim3(32, 32), thr, attn_smem>>>();
    gemm128<3><<<dim3(8, 32), thr>>>(nullptr, Wo, bo, X);
    ln_kernel<<<4096, thr>>>(l1g, l1b, nullptr, 0);
    gemm128<4><<<dim3(32, 32), thr>>>(nullptr, W1, b1, nullptr);
    gemm128<5><<<dim3(8, 32), thr>>>(nullptr, W2, b2, nullptr);
    ln_kernel<<<4096, thr>>>(l2g, l2b, (float*)d_out, 1);
}

// round 4
// speedup vs baseline: 1.5277x; 1.5277x over previous
#include <cuda_runtime.h>
#include <cuda_bf16.h>
#include <cstdint>

#define MB      4096
#define DMODEL  1024
#define NHEAD   16
#define HDIM    64
#define SEQ     2048
#define FF      4096

// ------------------------------ scratch globals ------------------------------
__device__ __align__(128) __nv_bfloat16 g_Xh [MB * DMODEL];
__device__ __align__(128) __nv_bfloat16 g_Xl [MB * DMODEL];
__device__ __align__(128) __nv_bfloat16 g_Wqh[DMODEL * DMODEL];
__device__ __align__(128) __nv_bfloat16 g_Wql[DMODEL * DMODEL];
__device__ __align__(128) __nv_bfloat16 g_Wkh[DMODEL * DMODEL];
__device__ __align__(128) __nv_bfloat16 g_Wkl[DMODEL * DMODEL];
__device__ __align__(128) __nv_bfloat16 g_Wvh[DMODEL * DMODEL];
__device__ __align__(128) __nv_bfloat16 g_Wvl[DMODEL * DMODEL];
__device__ __align__(128) __nv_bfloat16 g_Woh[DMODEL * DMODEL];
__device__ __align__(128) __nv_bfloat16 g_Wol[DMODEL * DMODEL];
__device__ __align__(128) __nv_bfloat16 g_W1h[FF * DMODEL];
__device__ __align__(128) __nv_bfloat16 g_W1l[FF * DMODEL];
__device__ __align__(128) __nv_bfloat16 g_W2h[DMODEL * FF];
__device__ __align__(128) __nv_bfloat16 g_W2l[DMODEL * FF];

__device__ __align__(128) float g_Q [MB * DMODEL];   // [B,H,S,HD] fp32
__device__ __align__(128) float g_K [MB * DMODEL];
__device__ __align__(128) float g_V [MB * DMODEL];
__device__ __align__(128) __nv_bfloat16 g_Oh[MB * DMODEL];  // attn out [M, H*HD]
__device__ __align__(128) __nv_bfloat16 g_Ol[MB * DMODEL];
__device__ __align__(128) float g_t1[MB * DMODEL];
__device__ __align__(128) float g_y [MB * DMODEL];
__device__ __align__(128) __nv_bfloat16 g_yh[MB * DMODEL];
__device__ __align__(128) __nv_bfloat16 g_yl[MB * DMODEL];
__device__ __align__(128) __nv_bfloat16 g_ffh[MB * FF];
__device__ __align__(128) __nv_bfloat16 g_ffl[MB * FF];
__device__ __align__(128) float g_z [MB * DMODEL];

// ------------------------------ helpers --------------------------------------
__device__ __forceinline__ uint32_t smem_u32(const void* p) {
    uint32_t a;
    asm("{ .reg .u64 t; cvta.to.shared.u64 t, %1; cvt.u32.u64 %0, t; }"
        : "=r"(a) : "l"(p));
    return a;
}
__device__ __forceinline__ void cpasync16(uint32_t s, const void* g) {
    asm volatile("cp.async.cg.shared.global [%0], [%1], 16;"
                 :: "r"(s), "l"(g) : "memory");
}
__device__ __forceinline__ void ldsm4(uint32_t* r, uint32_t addr) {
    asm volatile("ldmatrix.sync.aligned.m8n8.x4.shared.b16 {%0,%1,%2,%3}, [%4];"
        : "=r"(r[0]), "=r"(r[1]), "=r"(r[2]), "=r"(r[3]) : "r"(addr));
}
__device__ __forceinline__ void mma_bf16(float* c, const uint32_t* a, const uint32_t* b) {
    asm volatile("mma.sync.aligned.m16n8k16.row.col.f32.bf16.bf16.f32 "
        "{%0,%1,%2,%3}, {%4,%5,%6,%7}, {%8,%9}, {%0,%1,%2,%3};"
        : "+f"(c[0]), "+f"(c[1]), "+f"(c[2]), "+f"(c[3])
        : "r"(a[0]), "r"(a[1]), "r"(a[2]), "r"(a[3]), "r"(b[0]), "r"(b[1]));
}

__device__ __forceinline__ __nv_bfloat16 bf_hi(float x) { return __float2bfloat16(x); }
__device__ __forceinline__ __nv_bfloat16 bf_lo(float x, __nv_bfloat16 h) {
    return __float2bfloat16(x - __bfloat162float(h));
}

// ------------------------- conversion kernels --------------------------------
__global__ __launch_bounds__(256)
void conv_X(const float* __restrict__ X)
{
    int i = (blockIdx.x * 256 + threadIdx.x) * 4;
    float4 v = *(const float4*)(X + i);
    __nv_bfloat16 h0 = bf_hi(v.x), h1 = bf_hi(v.y), h2 = bf_hi(v.z), h3 = bf_hi(v.w);
    __nv_bfloat162* ph = (__nv_bfloat162*)(g_Xh + i);
    __nv_bfloat162* pl = (__nv_bfloat162*)(g_Xl + i);
    ph[0] = __nv_bfloat162(h0, h1); ph[1] = __nv_bfloat162(h2, h3);
    pl[0] = __nv_bfloat162(bf_lo(v.x, h0), bf_lo(v.y, h1));
    pl[1] = __nv_bfloat162(bf_lo(v.z, h2), bf_lo(v.w, h3));
}

// transpose fp32 [K,N] (or QKV [H,K,64]) -> bf16 hi/lo [N,K]
__global__ __launch_bounds__(256)
void conv_w(const float* __restrict__ in, int K, int N, int sel)
{
    __nv_bfloat16 *oh, *ol;
    switch (sel) {
        case 0: oh = g_Wqh; ol = g_Wql; break;
        case 1: oh = g_Wkh; ol = g_Wkl; break;
        case 2: oh = g_Wvh; ol = g_Wvl; break;
        case 3: oh = g_Woh; ol = g_Wol; break;
        case 4: oh = g_W1h; ol = g_W1l; break;
        default: oh = g_W2h; ol = g_W2l; break;
    }
    const bool qkv = sel < 3;
    __shared__ float tile[32][33];
    int tx = threadIdx.x & 31, ty = threadIdx.x >> 5;      // 32 x 8
    int n0 = blockIdx.x * 32, k0 = blockIdx.y * 32;
    #pragma unroll
    for (int j = 0; j < 4; j++) {
        int k = k0 + ty + j * 8, n = n0 + tx;
        size_t idx = qkv ? ((size_t)(n >> 6) * K * 64 + (size_t)k * 64 + (n & 63))
                         : ((size_t)k * N + n);
        tile[ty + j * 8][tx] = in[idx];
    }
    __syncthreads();
    #pragma unroll
    for (int j = 0; j < 4; j++) {
        int n = n0 + ty + j * 8, k = k0 + tx;
        float v = tile[tx][ty + j * 8];
        __nv_bfloat16 h = bf_hi(v);
        oh[(size_t)n * K + k] = h;
        ol[(size_t)n * K + k] = bf_lo(v, h);
    }
}

// ------------------------------ mma.sync GEMM --------------------------------
// CTA 128x256, 8 warps (2x4), warp tile 64x64, BK=32, double-buffered cp.async.
// bf16 hi/lo 3-term split with fp32 accumulators.
// Smem per stage: Ah(10240) Al(10240) Bh(20480) Bl(20480) = 61440B (80B rows).
template<int MODE>
__global__ __launch_bounds__(256)
void gemm_mma(const float* __restrict__ bias, const float* __restrict__ resid)
{
    constexpr int KD  = (MODE == 5) ? FF : DMODEL;
    constexpr int NC  = KD / 32;
    constexpr int BUF = 61440;

    extern __shared__ char smraw[];
    const uint32_t sbase = smem_u32(smraw);

    const int tid  = threadIdx.x;
    const int wid  = tid >> 5, lane = tid & 31;
    const int wr   = wid >> 2, wc = wid & 3;
    const int m0   = blockIdx.y * 128, n0 = blockIdx.x * 256;

    const __nv_bfloat16 *Ah, *Al, *Bh, *Bl;
    if constexpr (MODE == 0) { Ah = g_Xh; Al = g_Xl; Bh = g_Wqh; Bl = g_Wql; }
    else if constexpr (MODE == 1) { Ah = g_Xh; Al = g_Xl; Bh = g_Wkh; Bl = g_Wkl; }
    else if constexpr (MODE == 2) { Ah = g_Xh; Al = g_Xl; Bh = g_Wvh; Bl = g_Wvl; }
    else if constexpr (MODE == 3) { Ah = g_Oh; Al = g_Ol; Bh = g_Woh; Bl = g_Wol; }
    else if constexpr (MODE == 4) { Ah = g_yh; Al = g_yl; Bh = g_W1h; Bl = g_W1l; }
    else                          { Ah = g_ffh; Al = g_ffl; Bh = g_W2h; Bl = g_W2l; }

    const __nv_bfloat16* rowAh = Ah + (size_t)m0 * KD;
    const __nv_bfloat16* rowAl = Al + (size_t)m0 * KD;
    const __nv_bfloat16* rowBh = Bh + (size_t)n0 * KD;
    const __nv_bfloat16* rowBl = Bl + (size_t)n0 * KD;

    const int aRow = tid >> 1, aCol2 = (tid & 1) * 2;      // A: 2 chunks/thread/mat
    const int bRow = tid;                                   // B: 4 chunks/thread/mat

    auto issue = [&](int k0, int buf) {
        uint32_t sb = sbase + buf * BUF;
        #pragma unroll
        for (int i = 0; i < 2; i++) {
            int col = aCol2 + i;
            const __nv_bfloat16* gh = rowAh + (size_t)aRow * KD + k0 + col * 8;
            const __nv_bfloat16* gl = rowAl + (size_t)aRow * KD + k0 + col * 8;
            uint32_t so = aRow * 80 + col * 16;
            cpasync16(sb + so, gh);
            cpasync16(sb + 10240 + so, gl);
        }
        #pragma unroll
        for (int col = 0; col < 4; col++) {
            const __nv_bfloat16* gh = rowBh + (size_t)bRow * KD + k0 + col * 8;
            const __nv_bfloat16* gl = rowBl + (size_t)bRow * KD + k0 + col * 8;
            uint32_t so = bRow * 80 + col * 16;
            cpasync16(sb + 20480 + so, gh);
            cpasync16(sb + 40960 + so, gl);
        }
        asm volatile("cp.async.commit_group;" ::: "memory");
    };

    float c[4][8][4];
    #pragma unroll
    for (int i = 0; i < 4; i++)
        #pragma unroll
        for (int j = 0; j < 8; j++)
            #pragma unroll
            for (int q = 0; q < 4; q++) c[i][j][q] = 0.f;

    const int arow = ((lane >> 3) & 1) * 8 + (lane & 7);
    const int achk = lane >> 4;
    const int brow = ((lane >> 4) & 1) * 8 + (lane & 7);
    const int bchk = (lane >> 3) & 1;
    const uint32_t aAddr0 = sbase + (uint32_t)(wr * 64 + arow) * 80 + achk * 16;
    const uint32_t bAddr0 = sbase + 20480 + (uint32_t)(wc * 64 + brow) * 80 + bchk * 16;

    issue(0, 0);

    for (int ct = 0; ct < NC; ct++) {
        if (ct + 1 < NC) {
            issue((ct + 1) * 32, (ct + 1) & 1);
            asm volatile("cp.async.wait_group 1;" ::: "memory");
        } else {
            asm volatile("cp.async.wait_group 0;" ::: "memory");
        }
        __syncthreads();
        const uint32_t off = (ct & 1) ? BUF : 0u;
        #pragma unroll
        for (int ks = 0; ks < 2; ks++) {
            uint32_t bh[4][4], bl[4][4];
            #pragma unroll
            for (int t4 = 0; t4 < 4; t4++) {
                uint32_t ba = bAddr0 + off + t4 * (16 * 80) + ks * 32;
                ldsm4(bh[t4], ba);
                ldsm4(bl[t4], ba + 20480);
            }
            #pragma unroll
            for (int mi = 0; mi < 4; mi++) {
                uint32_t ah[4], al[4];
                uint32_t aa = aAddr0 + off + mi * (16 * 80) + ks * 32;
                ldsm4(ah, aa);
                ldsm4(al, aa + 10240);
                #pragma unroll
                for (int nj = 0; nj < 8; nj++) {
                    const uint32_t* bph = &bh[nj >> 1][(nj & 1) * 2];
                    const uint32_t* bpl = &bl[nj >> 1][(nj & 1) * 2];
                    mma_bf16(c[mi][nj], ah, bph);
                    mma_bf16(c[mi][nj], ah, bpl);
                    mma_bf16(c[mi][nj], al, bph);
                }
            }
        }
        __syncthreads();
    }

    // ------------------------------ epilogue ---------------------------------
    const int qrow = lane >> 2, qcol = (lane & 3) * 2;
    const int mrow0 = m0 + wr * 64;
    const int ncol0 = n0 + wc * 64;

    float2 bias2[8];
    #pragma unroll
    for (int nj = 0; nj < 8; nj++) {
        int n = ncol0 + nj * 8 + qcol;
        bias2[nj] = *(const float2*)(bias + n);
    }

    #pragma unroll
    for (int mi = 0; mi < 4; mi++) {
        #pragma unroll
        for (int half = 0; half < 2; half++) {
            int m = mrow0 + mi * 16 + qrow + half * 8;
            #pragma unroll
            for (int nj = 0; nj < 8; nj++) {
                int n = ncol0 + nj * 8 + qcol;
                float v0 = c[mi][nj][half * 2 + 0] + bias2[nj].x;
                float v1 = c[mi][nj][half * 2 + 1] + bias2[nj].y;
                if constexpr (MODE <= 2) {
                    float* out = (MODE == 0) ? g_Q : (MODE == 1) ? g_K : g_V;
                    int b = m >> 11, s = m & 2047, h = n >> 6, e = n & 63;
                    float2* p = (float2*)(out + (((size_t)(b * NHEAD + h) * SEQ) + s) * HDIM + e);
                    *p = make_float2(v0, v1);
                } else if constexpr (MODE == 3) {
                    size_t idx = (size_t)m * DMODEL + n;
                    float2 rv = *(const float2*)(resid + idx);
                    *(float2*)(g_t1 + idx) = make_float2(v0 + rv.x, v1 + rv.y);
                } else if constexpr (MODE == 4) {
                    v0 = fmaxf(v0, 0.f); v1 = fmaxf(v1, 0.f);
                    __nv_bfloat16 h0 = bf_hi(v0), h1 = bf_hi(v1);
                    size_t idx = (size_t)m * FF + n;
                    *(__nv_bfloat162*)(g_ffh + idx) = __nv_bfloat162(h0, h1);
                    *(__nv_bfloat162*)(g_ffl + idx) = __nv_bfloat162(bf_lo(v0, h0), bf_lo(v1, h1));
                } else {
                    size_t idx = (size_t)m * DMODEL + n;
                    float2 rv = *(const float2*)(g_y + idx);
                    *(float2*)(g_z + idx) = make_float2(v0 + rv.x, v1 + rv.y);
                }
            }
        }
    }
}

// ============================ Flash attention (fp32) =========================
__global__ __launch_bounds__(256)
void attn_kernel()
{
    extern __shared__ __align__(16) float sm[];
    float* Qs = sm;
    float* Kt = Qs + 64 * 68;
    float* Vs = Kt + 64 * 68;
    float* Ps = Vs + 64 * 68;

    const int tid = threadIdx.x;
    const int ty  = tid >> 4, tx = tid & 15;
    const int bh  = blockIdx.y;
    const int q0  = blockIdx.x * 64;

    const float* Qb = g_Q + (size_t)bh * SEQ * HDIM;
    const float* Kb = g_K + (size_t)bh * SEQ * HDIM;
    const float* Vb = g_V + (size_t)bh * SEQ * HDIM;

    {
        int r = tid >> 2, c = (tid & 3) * 16;
        const float4* src = (const float4*)(Qb + (size_t)(q0 + r) * HDIM + c);
        #pragma unroll
        for (int w = 0; w < 4; w++) {
            float4 v = src[w];
            float* d = &Qs[r * 68 + c + w * 4];
            d[0] = v.x * 0.125f; d[1] = v.y * 0.125f;
            d[2] = v.z * 0.125f; d[3] = v.w * 0.125f;
        }
    }

    float m_i[4], l_i[4], acc[4][4];
    #pragma unroll
    for (int i = 0; i < 4; i++) {
        m_i[i] = -1e30f; l_i[i] = 0.f;
        #pragma unroll
        for (int j = 0; j < 4; j++) acc[i][j] = 0.f;
    }

    for (int j0 = 0; j0 < SEQ; j0 += 64) {
        __syncthreads();
        {
            int r = tid >> 2, c = (tid & 3) * 16;
            const float4* ks = (const float4*)(Kb + (size_t)(j0 + r) * HDIM + c);
            const float4* vp = (const float4*)(Vb + (size_t)(j0 + r) * HDIM + c);
            #pragma unroll
            for (int w = 0; w < 4; w++) {
                float4 kv = ks[w];
                Kt[(c + w * 4 + 0) * 68 + r] = kv.x;
                Kt[(c + w * 4 + 1) * 68 + r] = kv.y;
                Kt[(c + w * 4 + 2) * 68 + r] = kv.z;
                Kt[(c + w * 4 + 3) * 68 + r] = kv.w;
                *(float4*)&Vs[r * 68 + c + w * 4] = vp[w];
            }
        }
        __syncthreads();

        float s[4][4];
        #pragma unroll
        for (int i = 0; i < 4; i++)
            #pragma unroll
            for (int j = 0; j < 4; j++) s[i][j] = 0.f;
        #pragma unroll 8
        for (int k = 0; k < 64; k++) {
            float a0 = Qs[(ty * 4 + 0) * 68 + k];
            float a1 = Qs[(ty * 4 + 1) * 68 + k];
            float a2 = Qs[(ty * 4 + 2) * 68 + k];
            float a3 = Qs[(ty * 4 + 3) * 68 + k];
            float4 b4 = *(const float4*)&Kt[k * 68 + tx * 4];
            s[0][0] = fmaf(a0, b4.x, s[0][0]); s[0][1] = fmaf(a0, b4.y, s[0][1]);
            s[0][2] = fmaf(a0, b4.z, s[0][2]); s[0][3] = fmaf(a0, b4.w, s[0][3]);
            s[1][0] = fmaf(a1, b4.x, s[1][0]); s[1][1] = fmaf(a1, b4.y, s[1][1]);
            s[1][2] = fmaf(a1, b4.z, s[1][2]); s[1][3] = fmaf(a1, b4.w, s[1][3]);
            s[2][0] = fmaf(a2, b4.x, s[2][0]); s[2][1] = fmaf(a2, b4.y, s[2][1]);
            s[2][2] = fmaf(a2, b4.z, s[2][2]); s[2][3] = fmaf(a2, b4.w, s[2][3]);
            s[3][0] = fmaf(a3, b4.x, s[3][0]); s[3][1] = fmaf(a3, b4.y, s[3][1]);
            s[3][2] = fmaf(a3, b4.z, s[3][2]); s[3][3] = fmaf(a3, b4.w, s[3][3]);
        }

        #pragma unroll
        for (int i = 0; i < 4; i++) {
            float pm = fmaxf(fmaxf(s[i][0], s[i][1]), fmaxf(s[i][2], s[i][3]));
            #pragma unroll
            for (int o = 8; o >= 1; o >>= 1)
                pm = fmaxf(pm, __shfl_xor_sync(0xffffffffu, pm, o));
            float mn   = fmaxf(m_i[i], pm);
            float corr = __expf(m_i[i] - mn);
            float rs = 0.f;
            #pragma unroll
            for (int j = 0; j < 4; j++) {
                float p = __expf(s[i][j] - mn);
                s[i][j] = p; rs += p;
            }
            #pragma unroll
            for (int o = 8; o >= 1; o >>= 1)
                rs += __shfl_xor_sync(0xffffffffu, rs, o);
            l_i[i] = l_i[i] * corr + rs;
            m_i[i] = mn;
            #pragma unroll
            for (int j = 0; j < 4; j++) acc[i][j] *= corr;
        }

        #pragma unroll
        for (int i = 0; i < 4; i++)
            *(float4*)&Ps[(ty * 4 + i) * 68 + tx * 4] =
                make_float4(s[i][0], s[i][1], s[i][2], s[i][3]);
        __syncthreads();

        #pragma unroll 8
        for (int k = 0; k < 64; k++) {
            float a0 = Ps[(ty * 4 + 0) * 68 + k];
            float a1 = Ps[(ty * 4 + 1) * 68 + k];
            float a2 = Ps[(ty * 4 + 2) * 68 + k];
            float a3 = Ps[(ty * 4 + 3) * 68 + k];
            float4 b4 = *(const float4*)&Vs[k * 68 + tx * 4];
            acc[0][0] = fmaf(a0, b4.x, acc[0][0]); acc[0][1] = fmaf(a0, b4.y, acc[0][1]);
            acc[0][2] = fmaf(a0, b4.z, acc[0][2]); acc[0][3] = fmaf(a0, b4.w, acc[0][3]);
            acc[1][0] = fmaf(a1, b4.x, acc[1][0]); acc[1][1] = fmaf(a1, b4.y, acc[1][1]);
            acc[1][2] = fmaf(a1, b4.z, acc[1][2]); acc[1][3] = fmaf(a1, b4.w, acc[1][3]);
            acc[2][0] = fmaf(a2, b4.x, acc[2][0]); acc[2][1] = fmaf(a2, b4.y, acc[2][1]);
            acc[2][2] = fmaf(a2, b4.z, acc[2][2]); acc[2][3] = fmaf(a2, b4.w, acc[2][3]);
            acc[3][0] = fmaf(a3, b4.x, acc[3][0]); acc[3][1] = fmaf(a3, b4.y, acc[3][1]);
            acc[3][2] = fmaf(a3, b4.z, acc[3][2]); acc[3][3] = fmaf(a3, b4.w, acc[3][3]);
        }
    }

    const int b = bh >> 4, h = bh & 15;
    __nv_bfloat16* OhB = g_Oh + ((size_t)b * SEQ) * DMODEL + (size_t)h * HDIM;
    __nv_bfloat16* OlB = g_Ol + ((size_t)b * SEQ) * DMODEL + (size_t)h * HDIM;
    #pragma unroll
    for (int i = 0; i < 4; i++) {
        float inv = 1.f / l_i[i];
        size_t roff = (size_t)(q0 + ty * 4 + i) * DMODEL + tx * 4;
        #pragma unroll
        for (int j = 0; j < 4; j++) {
            float o = acc[i][j] * inv;
            __nv_bfloat16 hh = bf_hi(o);
            OhB[roff + j] = hh;
            OlB[roff + j] = bf_lo(o, hh);
        }
    }
}

// =============================== LayerNorm ===================================
__global__ __launch_bounds__(256)
void ln_kernel(const float* __restrict__ g, const float* __restrict__ b,
               float* __restrict__ dstArg, int which)
{
    __shared__ float red[8];
    __shared__ float bc;
    const int tid = threadIdx.x;
    const int row = blockIdx.x;
    const float* src = (which == 0) ? g_t1 : g_z;
    float*       dst = (which == 0) ? g_y  : dstArg;

    float4 v = ((const float4*)(src + (size_t)row * DMODEL))[tid];
    float s = v.x + v.y + v.z + v.w;
    #pragma unroll
    for (int o = 16; o >= 1; o >>= 1) s += __shfl_xor_sync(0xffffffffu, s, o);
    if ((tid & 31) == 0) red[tid >> 5] = s;
    __syncthreads();
    if (tid == 0) {
        float t = 0.f;
        #pragma unroll
        for (int i = 0; i < 8; i++) t += red[i];
        bc = t;
    }
    __syncthreads();
    float mu = bc * (1.f / DMODEL);
    float dx = v.x - mu, dy = v.y - mu, dz = v.z - mu, dw = v.w - mu;
    float s2 = dx * dx + dy * dy + dz * dz + dw * dw;
    #pragma unroll
    for (int o = 16; o >= 1; o >>= 1) s2 += __shfl_xor_sync(0xffffffffu, s2, o);
    __syncthreads();
    if ((tid & 31) == 0) red[tid >> 5] = s2;
    __syncthreads();
    if (tid == 0) {
        float t = 0.f;
        #pragma unroll
        for (int i = 0; i < 8; i++) t += red[i];
        bc = t;
    }
    __syncthreads();
    float rstd = rsqrtf(bc * (1.f / DMODEL) + 1e-5f);
    float4 gg = ((const float4*)g)[tid];
    float4 bb = ((const float4*)b)[tid];
    float4 o4;
    o4.x = dx * rstd * gg.x + bb.x;
    o4.y = dy * rstd * gg.y + bb.y;
    o4.z = dz * rstd * gg.z + bb.z;
    o4.w = dw * rstd * gg.w + bb.w;
    ((float4*)(dst + (size_t)row * DMODEL))[tid] = o4;
    if (which == 0) {
        size_t idx = (size_t)row * DMODEL + tid * 4;
        __nv_bfloat16 h0 = bf_hi(o4.x), h1 = bf_hi(o4.y), h2 = bf_hi(o4.z), h3 = bf_hi(o4.w);
        *(__nv_bfloat162*)(g_yh + idx)     = __nv_bfloat162(h0, h1);
        *(__nv_bfloat162*)(g_yh + idx + 2) = __nv_bfloat162(h2, h3);
        *(__nv_bfloat162*)(g_yl + idx)     = __nv_bfloat162(bf_lo(o4.x, h0), bf_lo(o4.y, h1));
        *(__nv_bfloat162*)(g_yl + idx + 2) = __nv_bfloat162(bf_lo(o4.z, h2), bf_lo(o4.w, h3));
    }
}

// ================================ launch =====================================
extern "C" void kernel_launch(void* const* d_in, const int* in_sizes, int n_in,
                              void* d_out, int out_size)
{
    (void)in_sizes; (void)n_in; (void)out_size;
    const float* X   = (const float*)d_in[0];
    const float* Wq  = (const float*)d_in[1];
    const float* bq  = (const float*)d_in[2];
    const float* Wk  = (const float*)d_in[3];
    const float* bk  = (const float*)d_in[4];
    const float* Wv  = (const float*)d_in[5];
    const float* bv  = (const float*)d_in[6];
    const float* Wo  = (const float*)d_in[7];
    const float* bo  = (const float*)d_in[8];
    const float* l1g = (const float*)d_in[9];
    const float* l1b = (const float*)d_in[10];
    const float* W1  = (const float*)d_in[11];
    const float* b1  = (const float*)d_in[12];
    const float* W2  = (const float*)d_in[13];
    const float* b2  = (const float*)d_in[14];
    const float* l2g = (const float*)d_in[15];
    const float* l2b = (const float*)d_in[16];

    const int gemm_smem = 2 * 61440;   // 122880
    cudaFuncSetAttribute(gemm_mma<0>, cudaFuncAttributeMaxDynamicSharedMemorySize, gemm_smem);
    cudaFuncSetAttribute(gemm_mma<1>, cudaFuncAttributeMaxDynamicSharedMemorySize, gemm_smem);
    cudaFuncSetAttribute(gemm_mma<2>, cudaFuncAttributeMaxDynamicSharedMemorySize, gemm_smem);
    cudaFuncSetAttribute(gemm_mma<3>, cudaFuncAttributeMaxDynamicSharedMemorySize, gemm_smem);
    cudaFuncSetAttribute(gemm_mma<4>, cudaFuncAttributeMaxDynamicSharedMemorySize, gemm_smem);
    cudaFuncSetAttribute(gemm_mma<5>, cudaFuncAttributeMaxDynamicSharedMemorySize, gemm_smem);
    const int attn_smem = 4 * 64 * 68 * 4;
    cudaFuncSetAttribute(attn_kernel, cudaFuncAttributeMaxDynamicSharedMemorySize, attn_smem);

    dim3 thr(256);

    conv_X<<<MB * DMODEL / (256 * 4), thr>>>(X);
    conv_w<<<dim3(32, 32),  thr>>>(Wq, 1024, 1024, 0);
    conv_w<<<dim3(32, 32),  thr>>>(Wk, 1024, 1024, 1);
    conv_w<<<dim3(32, 32),  thr>>>(Wv, 1024, 1024, 2);
    conv_w<<<dim3(32, 32),  thr>>>(Wo, 1024, 1024, 3);
    conv_w<<<dim3(128, 32), thr>>>(W1, 1024, 4096, 4);
    conv_w<<<dim3(32, 128), thr>>>(W2, 4096, 1024, 5);

    gemm_mma<0><<<dim3(4, 32), thr, gemm_smem>>>(bq, nullptr);
    gemm_mma<1><<<dim3(4, 32), thr, gemm_smem>>>(bk, nullptr);
    gemm_mma<2><<<dim3(4, 32), thr, gemm_smem>>>(bv, nullptr);

    attn_kernel<<<dim3(32, 32), thr, attn_smem>>>();

    gemm_mma<3><<<dim3(4, 32), thr, gemm_smem>>>(bo, X);
    ln_kernel<<<MB, thr>>>(l1g, l1b, nullptr, 0);

    gemm_mma<4><<<dim3(16, 32), thr, gemm_smem>>>(b1, nullptr);
    gemm_mma<5><<<dim3(4, 32), thr, gemm_smem>>>(b2, nullptr);
    ln_kernel<<<MB, thr>>>(l2g, l2b, (float*)d_out, 1);
}

// round 5
// speedup vs baseline: 2.1145x; 1.3842x over previous
#include <cuda_runtime.h>
#include <cuda_bf16.h>
#include <cstdint>

#define MB      4096
#define DMODEL  1024
#define NHEAD   16
#define HDIM    64
#define SEQ     2048
#define FF      4096

// ------------------------------ scratch globals ------------------------------
__device__ __align__(128) __nv_bfloat16 g_Xh [MB * DMODEL];
__device__ __align__(128) __nv_bfloat16 g_Xl [MB * DMODEL];
__device__ __align__(128) __nv_bfloat16 g_Wqh[DMODEL * DMODEL];
__device__ __align__(128) __nv_bfloat16 g_Wql[DMODEL * DMODEL];
__device__ __align__(128) __nv_bfloat16 g_Wkh[DMODEL * DMODEL];
__device__ __align__(128) __nv_bfloat16 g_Wkl[DMODEL * DMODEL];
__device__ __align__(128) __nv_bfloat16 g_Wvh[DMODEL * DMODEL];
__device__ __align__(128) __nv_bfloat16 g_Wvl[DMODEL * DMODEL];
__device__ __align__(128) __nv_bfloat16 g_Woh[DMODEL * DMODEL];
__device__ __align__(128) __nv_bfloat16 g_Wol[DMODEL * DMODEL];
__device__ __align__(128) __nv_bfloat16 g_W1h[FF * DMODEL];
__device__ __align__(128) __nv_bfloat16 g_W1l[FF * DMODEL];
__device__ __align__(128) __nv_bfloat16 g_W2h[DMODEL * FF];
__device__ __align__(128) __nv_bfloat16 g_W2l[DMODEL * FF];

// Q/K/V in bf16 hi/lo, layout [B,H,S,HD]; Q pre-scaled by 1/8
__device__ __align__(128) __nv_bfloat16 g_Qh[MB * DMODEL];
__device__ __align__(128) __nv_bfloat16 g_Ql[MB * DMODEL];
__device__ __align__(128) __nv_bfloat16 g_Kh[MB * DMODEL];
__device__ __align__(128) __nv_bfloat16 g_Kl[MB * DMODEL];
__device__ __align__(128) __nv_bfloat16 g_Vh[MB * DMODEL];
__device__ __align__(128) __nv_bfloat16 g_Vl[MB * DMODEL];

__device__ __align__(128) __nv_bfloat16 g_Oh[MB * DMODEL];  // attn out [M, H*HD]
__device__ __align__(128) __nv_bfloat16 g_Ol[MB * DMODEL];
__device__ __align__(128) float g_t1[MB * DMODEL];
__device__ __align__(128) float g_y [MB * DMODEL];
__device__ __align__(128) __nv_bfloat16 g_yh[MB * DMODEL];
__device__ __align__(128) __nv_bfloat16 g_yl[MB * DMODEL];
__device__ __align__(128) __nv_bfloat16 g_ffh[MB * FF];
__device__ __align__(128) __nv_bfloat16 g_ffl[MB * FF];
__device__ __align__(128) float g_z [MB * DMODEL];

// ------------------------------ helpers --------------------------------------
__device__ __forceinline__ uint32_t smem_u32(const void* p) {
    uint32_t a;
    asm("{ .reg .u64 t; cvta.to.shared.u64 t, %1; cvt.u32.u64 %0, t; }"
        : "=r"(a) : "l"(p));
    return a;
}
__device__ __forceinline__ void cpasync16(uint32_t s, const void* g) {
    asm volatile("cp.async.cg.shared.global [%0], [%1], 16;"
                 :: "r"(s), "l"(g) : "memory");
}
__device__ __forceinline__ void ldsm4(uint32_t* r, uint32_t addr) {
    asm volatile("ldmatrix.sync.aligned.m8n8.x4.shared.b16 {%0,%1,%2,%3}, [%4];"
        : "=r"(r[0]), "=r"(r[1]), "=r"(r[2]), "=r"(r[3]) : "r"(addr));
}
__device__ __forceinline__ void ldsm4t(uint32_t* r, uint32_t addr) {
    asm volatile("ldmatrix.sync.aligned.m8n8.x4.trans.shared.b16 {%0,%1,%2,%3}, [%4];"
        : "=r"(r[0]), "=r"(r[1]), "=r"(r[2]), "=r"(r[3]) : "r"(addr));
}
__device__ __forceinline__ void mma_bf16(float* c, const uint32_t* a, const uint32_t* b) {
    asm volatile("mma.sync.aligned.m16n8k16.row.col.f32.bf16.bf16.f32 "
        "{%0,%1,%2,%3}, {%4,%5,%6,%7}, {%8,%9}, {%0,%1,%2,%3};"
        : "+f"(c[0]), "+f"(c[1]), "+f"(c[2]), "+f"(c[3])
        : "r"(a[0]), "r"(a[1]), "r"(a[2]), "r"(a[3]), "r"(b[0]), "r"(b[1]));
}

__device__ __forceinline__ __nv_bfloat16 bf_hi(float x) { return __float2bfloat16(x); }
__device__ __forceinline__ __nv_bfloat16 bf_lo(float x, __nv_bfloat16 h) {
    return __float2bfloat16(x - __bfloat162float(h));
}
__device__ __forceinline__ void pack_hilo(uint32_t& ph, uint32_t& pl, float x, float y) {
    __nv_bfloat16 hx = bf_hi(x), hy = bf_hi(y);
    __nv_bfloat162 vh(hx, hy), vl(bf_lo(x, hx), bf_lo(y, hy));
    ph = *(uint32_t*)&vh; pl = *(uint32_t*)&vl;
}

// ------------------------- conversion kernels --------------------------------
__global__ __launch_bounds__(256)
void conv_X(const float* __restrict__ X)
{
    int i = (blockIdx.x * 256 + threadIdx.x) * 4;
    float4 v = *(const float4*)(X + i);
    __nv_bfloat16 h0 = bf_hi(v.x), h1 = bf_hi(v.y), h2 = bf_hi(v.z), h3 = bf_hi(v.w);
    __nv_bfloat162* ph = (__nv_bfloat162*)(g_Xh + i);
    __nv_bfloat162* pl = (__nv_bfloat162*)(g_Xl + i);
    ph[0] = __nv_bfloat162(h0, h1); ph[1] = __nv_bfloat162(h2, h3);
    pl[0] = __nv_bfloat162(bf_lo(v.x, h0), bf_lo(v.y, h1));
    pl[1] = __nv_bfloat162(bf_lo(v.z, h2), bf_lo(v.w, h3));
}

__global__ __launch_bounds__(256)
void conv_w(const float* __restrict__ in, int K, int N, int sel)
{
    __nv_bfloat16 *oh, *ol;
    switch (sel) {
        case 0: oh = g_Wqh; ol = g_Wql; break;
        case 1: oh = g_Wkh; ol = g_Wkl; break;
        case 2: oh = g_Wvh; ol = g_Wvl; break;
        case 3: oh = g_Woh; ol = g_Wol; break;
        case 4: oh = g_W1h; ol = g_W1l; break;
        default: oh = g_W2h; ol = g_W2l; break;
    }
    const bool qkv = sel < 3;
    __shared__ float tile[32][33];
    int tx = threadIdx.x & 31, ty = threadIdx.x >> 5;
    int n0 = blockIdx.x * 32, k0 = blockIdx.y * 32;
    #pragma unroll
    for (int j = 0; j < 4; j++) {
        int k = k0 + ty + j * 8, n = n0 + tx;
        size_t idx = qkv ? ((size_t)(n >> 6) * K * 64 + (size_t)k * 64 + (n & 63))
                         : ((size_t)k * N + n);
        tile[ty + j * 8][tx] = in[idx];
    }
    __syncthreads();
    #pragma unroll
    for (int j = 0; j < 4; j++) {
        int n = n0 + ty + j * 8, k = k0 + tx;
        float v = tile[tx][ty + j * 8];
        __nv_bfloat16 h = bf_hi(v);
        oh[(size_t)n * K + k] = h;
        ol[(size_t)n * K + k] = bf_lo(v, h);
    }
}

// ------------------------------ mma.sync GEMM --------------------------------
template<int MODE>
__global__ __launch_bounds__(256)
void gemm_mma(const float* __restrict__ bias, const float* __restrict__ resid)
{
    constexpr int KD  = (MODE == 5) ? FF : DMODEL;
    constexpr int NC  = KD / 32;
    constexpr int BUF = 61440;

    extern __shared__ char smraw[];
    const uint32_t sbase = smem_u32(smraw);

    const int tid  = threadIdx.x;
    const int wid  = tid >> 5, lane = tid & 31;
    const int wr   = wid >> 2, wc = wid & 3;
    const int m0   = blockIdx.y * 128, n0 = blockIdx.x * 256;

    const __nv_bfloat16 *Ah, *Al, *Bh, *Bl;
    if constexpr (MODE == 0) { Ah = g_Xh; Al = g_Xl; Bh = g_Wqh; Bl = g_Wql; }
    else if constexpr (MODE == 1) { Ah = g_Xh; Al = g_Xl; Bh = g_Wkh; Bl = g_Wkl; }
    else if constexpr (MODE == 2) { Ah = g_Xh; Al = g_Xl; Bh = g_Wvh; Bl = g_Wvl; }
    else if constexpr (MODE == 3) { Ah = g_Oh; Al = g_Ol; Bh = g_Woh; Bl = g_Wol; }
    else if constexpr (MODE == 4) { Ah = g_yh; Al = g_yl; Bh = g_W1h; Bl = g_W1l; }
    else                          { Ah = g_ffh; Al = g_ffl; Bh = g_W2h; Bl = g_W2l; }

    const __nv_bfloat16* rowAh = Ah + (size_t)m0 * KD;
    const __nv_bfloat16* rowAl = Al + (size_t)m0 * KD;
    const __nv_bfloat16* rowBh = Bh + (size_t)n0 * KD;
    const __nv_bfloat16* rowBl = Bl + (size_t)n0 * KD;

    const int aRow = tid >> 1, aCol2 = (tid & 1) * 2;
    const int bRow = tid;

    auto issue = [&](int k0, int buf) {
        uint32_t sb = sbase + buf * BUF;
        #pragma unroll
        for (int i = 0; i < 2; i++) {
            int col = aCol2 + i;
            const __nv_bfloat16* gh = rowAh + (size_t)aRow * KD + k0 + col * 8;
            const __nv_bfloat16* gl = rowAl + (size_t)aRow * KD + k0 + col * 8;
            uint32_t so = aRow * 80 + col * 16;
            cpasync16(sb + so, gh);
            cpasync16(sb + 10240 + so, gl);
        }
        #pragma unroll
        for (int col = 0; col < 4; col++) {
            const __nv_bfloat16* gh = rowBh + (size_t)bRow * KD + k0 + col * 8;
            const __nv_bfloat16* gl = rowBl + (size_t)bRow * KD + k0 + col * 8;
            uint32_t so = bRow * 80 + col * 16;
            cpasync16(sb + 20480 + so, gh);
            cpasync16(sb + 40960 + so, gl);
        }
        asm volatile("cp.async.commit_group;" ::: "memory");
    };

    float c[4][8][4];
    #pragma unroll
    for (int i = 0; i < 4; i++)
        #pragma unroll
        for (int j = 0; j < 8; j++)
            #pragma unroll
            for (int q = 0; q < 4; q++) c[i][j][q] = 0.f;

    const int arow = ((lane >> 3) & 1) * 8 + (lane & 7);
    const int achk = lane >> 4;
    const int brow = ((lane >> 4) & 1) * 8 + (lane & 7);
    const int bchk = (lane >> 3) & 1;
    const uint32_t aAddr0 = sbase + (uint32_t)(wr * 64 + arow) * 80 + achk * 16;
    const uint32_t bAddr0 = sbase + 20480 + (uint32_t)(wc * 64 + brow) * 80 + bchk * 16;

    issue(0, 0);

    for (int ct = 0; ct < NC; ct++) {
        if (ct + 1 < NC) {
            issue((ct + 1) * 32, (ct + 1) & 1);
            asm volatile("cp.async.wait_group 1;" ::: "memory");
        } else {
            asm volatile("cp.async.wait_group 0;" ::: "memory");
        }
        __syncthreads();
        const uint32_t off = (ct & 1) ? BUF : 0u;
        #pragma unroll
        for (int ks = 0; ks < 2; ks++) {
            uint32_t bh[4][4], bl[4][4];
            #pragma unroll
            for (int t4 = 0; t4 < 4; t4++) {
                uint32_t ba = bAddr0 + off + t4 * (16 * 80) + ks * 32;
                ldsm4(bh[t4], ba);
                ldsm4(bl[t4], ba + 20480);
            }
            #pragma unroll
            for (int mi = 0; mi < 4; mi++) {
                uint32_t ah[4], al[4];
                uint32_t aa = aAddr0 + off + mi * (16 * 80) + ks * 32;
                ldsm4(ah, aa);
                ldsm4(al, aa + 10240);
                #pragma unroll
                for (int nj = 0; nj < 8; nj++) {
                    const uint32_t* bph = &bh[nj >> 1][(nj & 1) * 2];
                    const uint32_t* bpl = &bl[nj >> 1][(nj & 1) * 2];
                    mma_bf16(c[mi][nj], ah, bph);
                    mma_bf16(c[mi][nj], ah, bpl);
                    mma_bf16(c[mi][nj], al, bph);
                }
            }
        }
        __syncthreads();
    }

    // ------------------------------ epilogue ---------------------------------
    const int qrow = lane >> 2, qcol = (lane & 3) * 2;
    const int mrow0 = m0 + wr * 64;
    const int ncol0 = n0 + wc * 64;

    float2 bias2[8];
    #pragma unroll
    for (int nj = 0; nj < 8; nj++) {
        int n = ncol0 + nj * 8 + qcol;
        bias2[nj] = *(const float2*)(bias + n);
    }

    #pragma unroll
    for (int mi = 0; mi < 4; mi++) {
        #pragma unroll
        for (int half = 0; half < 2; half++) {
            int m = mrow0 + mi * 16 + qrow + half * 8;
            #pragma unroll
            for (int nj = 0; nj < 8; nj++) {
                int n = ncol0 + nj * 8 + qcol;
                float v0 = c[mi][nj][half * 2 + 0] + bias2[nj].x;
                float v1 = c[mi][nj][half * 2 + 1] + bias2[nj].y;
                if constexpr (MODE <= 2) {
                    // write bf16 hi/lo into [B,H,S,HD]; fold 1/8 into Q
                    if constexpr (MODE == 0) { v0 *= 0.125f; v1 *= 0.125f; }
                    __nv_bfloat16 *oh = (MODE == 0) ? g_Qh : (MODE == 1) ? g_Kh : g_Vh;
                    __nv_bfloat16 *ol = (MODE == 0) ? g_Ql : (MODE == 1) ? g_Kl : g_Vl;
                    int b = m >> 11, s = m & 2047, h = n >> 6, e = n & 63;
                    size_t idx = (((size_t)(b * NHEAD + h) * SEQ) + s) * HDIM + e;
                    __nv_bfloat16 h0 = bf_hi(v0), h1 = bf_hi(v1);
                    *(__nv_bfloat162*)(oh + idx) = __nv_bfloat162(h0, h1);
                    *(__nv_bfloat162*)(ol + idx) = __nv_bfloat162(bf_lo(v0, h0), bf_lo(v1, h1));
                } else if constexpr (MODE == 3) {
                    size_t idx = (size_t)m * DMODEL + n;
                    float2 rv = *(const float2*)(resid + idx);
                    *(float2*)(g_t1 + idx) = make_float2(v0 + rv.x, v1 + rv.y);
                } else if constexpr (MODE == 4) {
                    v0 = fmaxf(v0, 0.f); v1 = fmaxf(v1, 0.f);
                    __nv_bfloat16 h0 = bf_hi(v0), h1 = bf_hi(v1);
                    size_t idx = (size_t)m * FF + n;
                    *(__nv_bfloat162*)(g_ffh + idx) = __nv_bfloat162(h0, h1);
                    *(__nv_bfloat162*)(g_ffl + idx) = __nv_bfloat162(bf_lo(v0, h0), bf_lo(v1, h1));
                } else {
                    size_t idx = (size_t)m * DMODEL + n;
                    float2 rv = *(const float2*)(g_y + idx);
                    *(float2*)(g_z + idx) = make_float2(v0 + rv.x, v1 + rv.y);
                }
            }
        }
    }
}

// ======================= Flash attention (mma.sync bf16) =====================
// CTA: 128 q-rows x one (b,h). 8 warps; warp = 16 q-rows x full 64-wide KV tile.
// S = (Q/8)K^T via 3-term hi/lo mma; online softmax on fragments; P repacked in
// registers to A-frags; PV via 3-term hi/lo mma with ldmatrix.trans on V.
// smem (bf16, 72-elem = 144B rows):
//   Qh 0..18432, Ql 18432..36864; KV stages at 36864 + st*36864:
//   Kh +0, Kl +9216, Vh +18432, Vl +27648  (each 64x72x2 = 9216B)
__global__ __launch_bounds__(256, 2)
void attn_mma()
{
    extern __shared__ char smraw[];
    const uint32_t sb = smem_u32(smraw);
    const int tid = threadIdx.x, lane = tid & 31, w = tid >> 5;
    const int bh = blockIdx.y;
    const int q0 = blockIdx.x * 128;

    const __nv_bfloat16* Qhb = g_Qh + (size_t)bh * SEQ * HDIM;
    const __nv_bfloat16* Qlb = g_Ql + (size_t)bh * SEQ * HDIM;
    const __nv_bfloat16* Khb = g_Kh + (size_t)bh * SEQ * HDIM;
    const __nv_bfloat16* Klb = g_Kl + (size_t)bh * SEQ * HDIM;
    const __nv_bfloat16* Vhb = g_Vh + (size_t)bh * SEQ * HDIM;
    const __nv_bfloat16* Vlb = g_Vl + (size_t)bh * SEQ * HDIM;

    // ---- load Q tile (once): 128 rows x 64, hi+lo
    {
        int row = tid >> 1, c0 = (tid & 1) * 4;
        const __nv_bfloat16* gh = Qhb + (size_t)(q0 + row) * HDIM;
        const __nv_bfloat16* gl = Qlb + (size_t)(q0 + row) * HDIM;
        #pragma unroll
        for (int i = 0; i < 4; i++) {
            uint32_t so = row * 144 + (c0 + i) * 16;
            cpasync16(sb + so,         gh + (c0 + i) * 8);
            cpasync16(sb + 18432 + so, gl + (c0 + i) * 8);
        }
    }

    // ---- KV stage loader
    auto kv_issue = [&](int j, int st) {
        uint32_t base = sb + 36864 + st * 36864;
        int row = tid >> 2, c4 = (tid & 3) * 2;
        size_t goff = (size_t)(j * 64 + row) * HDIM;
        const __nv_bfloat16* srcs[4] = { Khb + goff, Klb + goff, Vhb + goff, Vlb + goff };
        #pragma unroll
        for (int t = 0; t < 4; t++) {
            #pragma unroll
            for (int i = 0; i < 2; i++) {
                uint32_t so = t * 9216 + row * 144 + (c4 + i) * 16;
                cpasync16(base + so, srcs[t] + (c4 + i) * 8);
            }
        }
        asm volatile("cp.async.commit_group;" ::: "memory");
    };

    kv_issue(0, 0);   // group 0 = Q + KV stage0

    // per-lane fragment address components
    const int arow = ((lane >> 3) & 1) * 8 + (lane & 7);  // A (Q) pattern
    const int achk = lane >> 4;
    const int brow = ((lane >> 4) & 1) * 8 + (lane & 7);  // B (K) pattern
    const int bchk = (lane >> 3) & 1;
    const uint32_t qAddr0 = sb + (uint32_t)(w * 16 + arow) * 144 + achk * 16;
    // V trans-ldmatrix address components
    const int vrow = ((lane >> 3) & 1) * 8 + (lane & 7);
    const int vcol = (lane >> 4) * 8;

    float acc[8][4];
    #pragma unroll
    for (int j = 0; j < 8; j++)
        #pragma unroll
        for (int q = 0; q < 4; q++) acc[j][q] = 0.f;
    float m0 = -1e30f, m1 = -1e30f, l0 = 0.f, l1 = 0.f;

    for (int jt = 0; jt < SEQ / 64; jt++) {
        if (jt + 1 < SEQ / 64) {
            kv_issue(jt + 1, (jt + 1) & 1);
            asm volatile("cp.async.wait_group 1;" ::: "memory");
        } else {
            asm volatile("cp.async.wait_group 0;" ::: "memory");
        }
        __syncthreads();
        const uint32_t stg = sb + 36864 + (jt & 1) * 36864;

        // ---- S = Q K^T (fp32 frags), 3-term hi/lo
        float s[8][4];
        #pragma unroll
        for (int j = 0; j < 8; j++)
            #pragma unroll
            for (int q = 0; q < 4; q++) s[j][q] = 0.f;

        #pragma unroll
        for (int t = 0; t < 4; t++) {           // hd k-tile
            uint32_t qh4[4], ql4[4];
            uint32_t qa = qAddr0 + t * 32;
            ldsm4(qh4, qa);
            ldsm4(ql4, qa + 18432);
            #pragma unroll
            for (int np = 0; np < 4; np++) {    // kv n-tile pairs
                uint32_t kh4[4], kl4[4];
                uint32_t ka = stg + (uint32_t)(np * 16 + brow) * 144 + t * 32 + bchk * 16;
                ldsm4(kh4, ka);
                ldsm4(kl4, ka + 9216);
                mma_bf16(s[2 * np],     qh4, &kh4[0]);
                mma_bf16(s[2 * np],     qh4, &kl4[0]);
                mma_bf16(s[2 * np],     ql4, &kh4[0]);
                mma_bf16(s[2 * np + 1], qh4, &kh4[2]);
                mma_bf16(s[2 * np + 1], qh4, &kl4[2]);
                mma_bf16(s[2 * np + 1], ql4, &kh4[2]);
            }
        }

        // ---- online softmax (rows r = lane>>2 and r+8)
        float mx0 = -1e30f, mx1 = -1e30f;
        #pragma unroll
        for (int j = 0; j < 8; j++) {
            mx0 = fmaxf(mx0, fmaxf(s[j][0], s[j][1]));
            mx1 = fmaxf(mx1, fmaxf(s[j][2], s[j][3]));
        }
        mx0 = fmaxf(mx0, __shfl_xor_sync(0xffffffffu, mx0, 1));
        mx0 = fmaxf(mx0, __shfl_xor_sync(0xffffffffu, mx0, 2));
        mx1 = fmaxf(mx1, __shfl_xor_sync(0xffffffffu, mx1, 1));
        mx1 = fmaxf(mx1, __shfl_xor_sync(0xffffffffu, mx1, 2));
        float mn0 = fmaxf(m0, mx0), mn1 = fmaxf(m1, mx1);
        float cr0 = __expf(m0 - mn0), cr1 = __expf(m1 - mn1);
        float sum0 = 0.f, sum1 = 0.f;
        #pragma unroll
        for (int j = 0; j < 8; j++) {
            s[j][0] = __expf(s[j][0] - mn0); sum0 += s[j][0];
            s[j][1] = __expf(s[j][1] - mn0); sum0 += s[j][1];
            s[j][2] = __expf(s[j][2] - mn1); sum1 += s[j][2];
            s[j][3] = __expf(s[j][3] - mn1); sum1 += s[j][3];
        }
        sum0 += __shfl_xor_sync(0xffffffffu, sum0, 1);
        sum0 += __shfl_xor_sync(0xffffffffu, sum0, 2);
        sum1 += __shfl_xor_sync(0xffffffffu, sum1, 1);
        sum1 += __shfl_xor_sync(0xffffffffu, sum1, 2);
        l0 = l0 * cr0 + sum0;  m0 = mn0;
        l1 = l1 * cr1 + sum1;  m1 = mn1;
        #pragma unroll
        for (int j = 0; j < 8; j++) {
            acc[j][0] *= cr0; acc[j][1] *= cr0;
            acc[j][2] *= cr1; acc[j][3] *= cr1;
        }

        // ---- PV: P repacked to A-frags in registers; V via ldmatrix.trans
        #pragma unroll
        for (int t = 0; t < 4; t++) {           // kv k-tile (16)
            uint32_t ph[4], pl[4];
            pack_hilo(ph[0], pl[0], s[2 * t][0],     s[2 * t][1]);
            pack_hilo(ph[1], pl[1], s[2 * t][2],     s[2 * t][3]);
            pack_hilo(ph[2], pl[2], s[2 * t + 1][0], s[2 * t + 1][1]);
            pack_hilo(ph[3], pl[3], s[2 * t + 1][2], s[2 * t + 1][3]);
            #pragma unroll
            for (int jp = 0; jp < 4; jp++) {    // hd n-tile pairs
                uint32_t vh4[4], vl4[4];
                uint32_t va = stg + 18432
                            + (uint32_t)(16 * t + vrow) * 144 + (16 * jp + vcol) * 2;
                ldsm4t(vh4, va);
                ldsm4t(vl4, va + 9216);
                mma_bf16(acc[2 * jp],     ph, &vh4[0]);
                mma_bf16(acc[2 * jp],     ph, &vl4[0]);
                mma_bf16(acc[2 * jp],     pl, &vh4[0]);
                mma_bf16(acc[2 * jp + 1], ph, &vh4[2]);
                mma_bf16(acc[2 * jp + 1], ph, &vl4[2]);
                mma_bf16(acc[2 * jp + 1], pl, &vh4[2]);
            }
        }
        __syncthreads();
    }

    // ---- epilogue: O as bf16 hi/lo in [M, H*HD]
    const int b = bh >> 4, h = bh & 15;
    const int r = lane >> 2, m2 = (lane & 3) * 2;
    const float inv0 = 1.f / l0, inv1 = 1.f / l1;
    const int row0 = q0 + w * 16 + r;
    __nv_bfloat16* OhB = g_Oh + ((size_t)b * SEQ) * DMODEL + (size_t)h * HDIM;
    __nv_bfloat16* OlB = g_Ol + ((size_t)b * SEQ) * DMODEL + (size_t)h * HDIM;
    #pragma unroll
    for (int j = 0; j < 8; j++) {
        int col = 8 * j + m2;
        {
            float o0 = acc[j][0] * inv0, o1 = acc[j][1] * inv0;
            __nv_bfloat16 h0 = bf_hi(o0), h1 = bf_hi(o1);
            size_t idx = (size_t)row0 * DMODEL + col;
            *(__nv_bfloat162*)(OhB + idx) = __nv_bfloat162(h0, h1);
            *(__nv_bfloat162*)(OlB + idx) = __nv_bfloat162(bf_lo(o0, h0), bf_lo(o1, h1));
        }
        {
            float o2 = acc[j][2] * inv1, o3 = acc[j][3] * inv1;
            __nv_bfloat16 h2 = bf_hi(o2), h3 = bf_hi(o3);
            size_t idx = (size_t)(row0 + 8) * DMODEL + col;
            *(__nv_bfloat162*)(OhB + idx) = __nv_bfloat162(h2, h3);
            *(__nv_bfloat162*)(OlB + idx) = __nv_bfloat162(bf_lo(o2, h2), bf_lo(o3, h3));
        }
    }
}

// =============================== LayerNorm ===================================
__global__ __launch_bounds__(256)
void ln_kernel(const float* __restrict__ g, const float* __restrict__ b,
               float* __restrict__ dstArg, int which)
{
    __shared__ float red[8];
    __shared__ float bc;
    const int tid = threadIdx.x;
    const int row = blockIdx.x;
    const float* src = (which == 0) ? g_t1 : g_z;
    float*       dst = (which == 0) ? g_y  : dstArg;

    float4 v = ((const float4*)(src + (size_t)row * DMODEL))[tid];
    float s = v.x + v.y + v.z + v.w;
    #pragma unroll
    for (int o = 16; o >= 1; o >>= 1) s += __shfl_xor_sync(0xffffffffu, s, o);
    if ((tid & 31) == 0) red[tid >> 5] = s;
    __syncthreads();
    if (tid == 0) {
        float t = 0.f;
        #pragma unroll
        for (int i = 0; i < 8; i++) t += red[i];
        bc = t;
    }
    __syncthreads();
    float mu = bc * (1.f / DMODEL);
    float dx = v.x - mu, dy = v.y - mu, dz = v.z - mu, dw = v.w - mu;
    float s2 = dx * dx + dy * dy + dz * dz + dw * dw;
    #pragma unroll
    for (int o = 16; o >= 1; o >>= 1) s2 += __shfl_xor_sync(0xffffffffu, s2, o);
    __syncthreads();
    if ((tid & 31) == 0) red[tid >> 5] = s2;
    __syncthreads();
    if (tid == 0) {
        float t = 0.f;
        #pragma unroll
        for (int i = 0; i < 8; i++) t += red[i];
        bc = t;
    }
    __syncthreads();
    float rstd = rsqrtf(bc * (1.f / DMODEL) + 1e-5f);
    float4 gg = ((const float4*)g)[tid];
    float4 bb = ((const float4*)b)[tid];
    float4 o4;
    o4.x = dx * rstd * gg.x + bb.x;
    o4.y = dy * rstd * gg.y + bb.y;
    o4.z = dz * rstd * gg.z + bb.z;
    o4.w = dw * rstd * gg.w + bb.w;
    ((float4*)(dst + (size_t)row * DMODEL))[tid] = o4;
    if (which == 0) {
        size_t idx = (size_t)row * DMODEL + tid * 4;
        __nv_bfloat16 h0 = bf_hi(o4.x), h1 = bf_hi(o4.y), h2 = bf_hi(o4.z), h3 = bf_hi(o4.w);
        *(__nv_bfloat162*)(g_yh + idx)     = __nv_bfloat162(h0, h1);
        *(__nv_bfloat162*)(g_yh + idx + 2) = __nv_bfloat162(h2, h3);
        *(__nv_bfloat162*)(g_yl + idx)     = __nv_bfloat162(bf_lo(o4.x, h0), bf_lo(o4.y, h1));
        *(__nv_bfloat162*)(g_yl + idx + 2) = __nv_bfloat162(bf_lo(o4.z, h2), bf_lo(o4.w, h3));
    }
}

// ================================ launch =====================================
extern "C" void kernel_launch(void* const* d_in, const int* in_sizes, int n_in,
                              void* d_out, int out_size)
{
    (void)in_sizes; (void)n_in; (void)out_size;
    const float* X   = (const float*)d_in[0];
    const float* Wq  = (const float*)d_in[1];
    const float* bq  = (const float*)d_in[2];
    const float* Wk  = (const float*)d_in[3];
    const float* bk  = (const float*)d_in[4];
    const float* Wv  = (const float*)d_in[5];
    const float* bv  = (const float*)d_in[6];
    const float* Wo  = (const float*)d_in[7];
    const float* bo  = (const float*)d_in[8];
    const float* l1g = (const float*)d_in[9];
    const float* l1b = (const float*)d_in[10];
    const float* W1  = (const float*)d_in[11];
    const float* b1  = (const float*)d_in[12];
    const float* W2  = (const float*)d_in[13];
    const float* b2  = (const float*)d_in[14];
    const float* l2g = (const float*)d_in[15];
    const float* l2b = (const float*)d_in[16];

    const int gemm_smem = 2 * 61440;   // 122880
    cudaFuncSetAttribute(gemm_mma<0>, cudaFuncAttributeMaxDynamicSharedMemorySize, gemm_smem);
    cudaFuncSetAttribute(gemm_mma<1>, cudaFuncAttributeMaxDynamicSharedMemorySize, gemm_smem);
    cudaFuncSetAttribute(gemm_mma<2>, cudaFuncAttributeMaxDynamicSharedMemorySize, gemm_smem);
    cudaFuncSetAttribute(gemm_mma<3>, cudaFuncAttributeMaxDynamicSharedMemorySize, gemm_smem);
    cudaFuncSetAttribute(gemm_mma<4>, cudaFuncAttributeMaxDynamicSharedMemorySize, gemm_smem);
    cudaFuncSetAttribute(gemm_mma<5>, cudaFuncAttributeMaxDynamicSharedMemorySize, gemm_smem);
    const int attn_smem = 36864 + 2 * 36864;   // 110592
    cudaFuncSetAttribute(attn_mma, cudaFuncAttributeMaxDynamicSharedMemorySize, attn_smem);

    dim3 thr(256);

    conv_X<<<MB * DMODEL / (256 * 4), thr>>>(X);
    conv_w<<<dim3(32, 32),  thr>>>(Wq, 1024, 1024, 0);
    conv_w<<<dim3(32, 32),  thr>>>(Wk, 1024, 1024, 1);
    conv_w<<<dim3(32, 32),  thr>>>(Wv, 1024, 1024, 2);
    conv_w<<<dim3(32, 32),  thr>>>(Wo, 1024, 1024, 3);
    conv_w<<<dim3(128, 32), thr>>>(W1, 1024, 4096, 4);
    conv_w<<<dim3(32, 128), thr>>>(W2, 4096, 1024, 5);

    gemm_mma<0><<<dim3(4, 32), thr, gemm_smem>>>(bq, nullptr);
    gemm_mma<1><<<dim3(4, 32), thr, gemm_smem>>>(bk, nullptr);
    gemm_mma<2><<<dim3(4, 32), thr, gemm_smem>>>(bv, nullptr);

    attn_mma<<<dim3(16, 32), thr, attn_smem>>>();

    gemm_mma<3><<<dim3(4, 32), thr, gemm_smem>>>(bo, X);
    ln_kernel<<<MB, thr>>>(l1g, l1b, nullptr, 0);

    gemm_mma<4><<<dim3(16, 32), thr, gemm_smem>>>(b1, nullptr);
    gemm_mma<5><<<dim3(4, 32), thr, gemm_smem>>>(b2, nullptr);
    ln_kernel<<<MB, thr>>>(l2g, l2b, (float*)d_out, 1);
}

// round 9
// speedup vs baseline: 3.0097x; 1.4234x over previous
#include <cuda_runtime.h>
#include <cuda_bf16.h>
#include <cstdint>

#define MB      4096
#define DMODEL  1024
#define NHEAD   16
#define HDIM    64
#define SEQ     2048
#define FF      4096

// ------------------------- pooled scratch (lifetime-overlaid) ----------------
// Phases: 1) X->Xq  2) QKV gemms (Xq -> Q/K/V)  3) attn (QKV -> O)
// 4) O->Oq  5) gemm3 (Oq,X -> t1)  6) ln1 (t1 -> y, yq)  7) gemm4 (yq -> ff)
// 8) ff->fq  9) gemm5 (fq,y -> z)  10) ln2 (z -> out)
// Disjoint-lifetime overlays: ff(0..64M) over QKV+O; fq(64..96M) over Xq;
// z over t1; yq over Oq.
constexpr size_t MiB = 1024u * 1024u;
__device__ __align__(1024) unsigned char g_pool[136 * MiB];

constexpr size_t OFF_QH  = 0 * MiB;     // bf16 8MB each
constexpr size_t OFF_QL  = 8 * MiB;
constexpr size_t OFF_KH  = 16 * MiB;
constexpr size_t OFF_KL  = 24 * MiB;
constexpr size_t OFF_VH  = 32 * MiB;
constexpr size_t OFF_VL  = 40 * MiB;
constexpr size_t OFF_O   = 48 * MiB;    // fp32 16MB        (phase 3-4)
constexpr size_t OFF_FF  = 0 * MiB;     // fp32 64MB        (phase 7-8; QKV+O dead)
constexpr size_t OFF_XQH = 64 * MiB;    // s8 4MB           (phase 1-2)
constexpr size_t OFF_XQL = 68 * MiB;
constexpr size_t OFF_FQH = 64 * MiB;    // s8 16MB each     (phase 8-9; Xq dead)
constexpr size_t OFF_FQL = 80 * MiB;
constexpr size_t OFF_T1  = 96 * MiB;    // fp32 16MB        (phase 5-6)
constexpr size_t OFF_Z   = 96 * MiB;    // fp32 16MB        (phase 9-10; t1 dead)
constexpr size_t OFF_Y   = 112 * MiB;   // fp32 16MB        (phase 6-9)
constexpr size_t OFF_OQH = 128 * MiB;   // s8 4MB each      (phase 4-5)
constexpr size_t OFF_OQL = 132 * MiB;
constexpr size_t OFF_YQH = 128 * MiB;   // s8 4MB each      (phase 6-7; Oq dead)
constexpr size_t OFF_YQL = 132 * MiB;

// quantized transposed weights [N][K] + scales (live whole run; ~24MB)
__device__ __align__(128) signed char g_Wqh_q[DMODEL * DMODEL], g_Wql_q[DMODEL * DMODEL];
__device__ __align__(128) signed char g_Wkh_q[DMODEL * DMODEL], g_Wkl_q[DMODEL * DMODEL];
__device__ __align__(128) signed char g_Wvh_q[DMODEL * DMODEL], g_Wvl_q[DMODEL * DMODEL];
__device__ __align__(128) signed char g_Woh_q[DMODEL * DMODEL], g_Wol_q[DMODEL * DMODEL];
__device__ __align__(128) signed char g_W1h_q[FF * DMODEL],     g_W1l_q[FF * DMODEL];
__device__ __align__(128) signed char g_W2h_q[DMODEL * FF],     g_W2l_q[DMODEL * FF];
__device__ __align__(128) float g_wmax[9216];   // Wq 0, Wk 1024, Wv 2048, Wo 3072, W2 4096, W1 5120
__device__ __align__(128) float g_sX [MB];
__device__ __align__(128) float g_sO [MB];
__device__ __align__(128) float g_sy [MB];
__device__ __align__(128) float g_sff[MB];

// ------------------------------ helpers --------------------------------------
__device__ __forceinline__ uint32_t smem_u32(const void* p) {
    uint32_t a;
    asm("{ .reg .u64 t; cvta.to.shared.u64 t, %1; cvt.u32.u64 %0, t; }"
        : "=r"(a) : "l"(p));
    return a;
}
__device__ __forceinline__ void cpasync16(uint32_t s, const void* g) {
    asm volatile("cp.async.cg.shared.global [%0], [%1], 16;"
                 :: "r"(s), "l"(g) : "memory");
}
__device__ __forceinline__ void ldsm4(uint32_t* r, uint32_t addr) {
    asm volatile("ldmatrix.sync.aligned.m8n8.x4.shared.b16 {%0,%1,%2,%3}, [%4];"
        : "=r"(r[0]), "=r"(r[1]), "=r"(r[2]), "=r"(r[3]) : "r"(addr));
}
__device__ __forceinline__ void ldsm4t(uint32_t* r, uint32_t addr) {
    asm volatile("ldmatrix.sync.aligned.m8n8.x4.trans.shared.b16 {%0,%1,%2,%3}, [%4];"
        : "=r"(r[0]), "=r"(r[1]), "=r"(r[2]), "=r"(r[3]) : "r"(addr));
}
__device__ __forceinline__ void mma_bf16(float* c, const uint32_t* a, const uint32_t* b) {
    asm volatile("mma.sync.aligned.m16n8k16.row.col.f32.bf16.bf16.f32 "
        "{%0,%1,%2,%3}, {%4,%5,%6,%7}, {%8,%9}, {%0,%1,%2,%3};"
        : "+f"(c[0]), "+f"(c[1]), "+f"(c[2]), "+f"(c[3])
        : "r"(a[0]), "r"(a[1]), "r"(a[2]), "r"(a[3]), "r"(b[0]), "r"(b[1]));
}
__device__ __forceinline__ void mma_s8(int* c, const uint32_t* a, const uint32_t* b) {
    asm volatile("mma.sync.aligned.m16n8k32.row.col.s32.s8.s8.s32 "
        "{%0,%1,%2,%3}, {%4,%5,%6,%7}, {%8,%9}, {%0,%1,%2,%3};"
        : "+r"(c[0]), "+r"(c[1]), "+r"(c[2]), "+r"(c[3])
        : "r"(a[0]), "r"(a[1]), "r"(a[2]), "r"(a[3]), "r"(b[0]), "r"(b[1]));
}

__device__ __forceinline__ __nv_bfloat16 bf_hi(float x) { return __float2bfloat16(x); }
__device__ __forceinline__ __nv_bfloat16 bf_lo(float x, __nv_bfloat16 h) {
    return __float2bfloat16(x - __bfloat162float(h));
}
__device__ __forceinline__ void pack_hilo(uint32_t& ph, uint32_t& pl, float x, float y) {
    __nv_bfloat16 hx = bf_hi(x), hy = bf_hi(y);
    __nv_bfloat162 vh(hx, hy), vl(bf_lo(x, hx), bf_lo(y, hy));
    ph = *(uint32_t*)&vh; pl = *(uint32_t*)&vl;
}
__device__ __forceinline__ void q_split(float q, signed char& hi, signed char& lo) {
    int h = __float2int_rn(q);
    int l = __float2int_rn((q - (float)h) * 256.f);
    l = max(-127, min(127, l));
    hi = (signed char)h;
    lo = (signed char)l;
}

// ------------------------- quantization kernels ------------------------------
// SEL 0: X(arg) -> Xq/sX ; SEL 1: O(pool) -> Oq/sO ; SEL 2: ff(pool) -> fq/sff
template<int C, int SEL>
__global__ __launch_bounds__(256)
void quant_rows(const float* __restrict__ srcArg)
{
    const float* src;
    signed char *qh, *ql;
    float* smax;
    if constexpr (SEL == 0) {
        src = srcArg;
        qh = (signed char*)(g_pool + OFF_XQH); ql = (signed char*)(g_pool + OFF_XQL);
        smax = g_sX;
    } else if constexpr (SEL == 1) {
        src = (const float*)(g_pool + OFF_O);
        qh = (signed char*)(g_pool + OFF_OQH); ql = (signed char*)(g_pool + OFF_OQL);
        smax = g_sO;
    } else {
        src = (const float*)(g_pool + OFF_FF);
        qh = (signed char*)(g_pool + OFF_FQH); ql = (signed char*)(g_pool + OFF_FQL);
        smax = g_sff;
    }

    __shared__ float red[8];
    __shared__ float bc;
    const int tid = threadIdx.x, row = blockIdx.x;
    constexpr int V = C / 1024;
    const float4* s4 = (const float4*)(src + (size_t)row * C);
    float4 v[V];
    float mx = 0.f;
    #pragma unroll
    for (int i = 0; i < V; i++) {
        v[i] = s4[tid + i * 256];
        mx = fmaxf(mx, fmaxf(fmaxf(fabsf(v[i].x), fabsf(v[i].y)),
                             fmaxf(fabsf(v[i].z), fabsf(v[i].w))));
    }
    #pragma unroll
    for (int o = 16; o >= 1; o >>= 1) mx = fmaxf(mx, __shfl_xor_sync(0xffffffffu, mx, o));
    if ((tid & 31) == 0) red[tid >> 5] = mx;
    __syncthreads();
    if (tid == 0) {
        float t = 1e-20f;
        #pragma unroll
        for (int i = 0; i < 8; i++) t = fmaxf(t, red[i]);
        bc = t; smax[row] = t;
    }
    __syncthreads();
    const float inv = 127.f / bc;
    #pragma unroll
    for (int i = 0; i < V; i++) {
        char4 h4, l4;
        q_split(v[i].x * inv, h4.x, l4.x);
        q_split(v[i].y * inv, h4.y, l4.y);
        q_split(v[i].z * inv, h4.z, l4.z);
        q_split(v[i].w * inv, h4.w, l4.w);
        size_t idx = (size_t)row * C + (tid + i * 256) * 4;
        *(char4*)(qh + idx) = h4;
        *(char4*)(ql + idx) = l4;
    }
}

__global__ __launch_bounds__(256)
void zero_wmax() { int i = blockIdx.x * 256 + threadIdx.x; if (i < 9216) g_wmax[i] = 0.f; }

__global__ __launch_bounds__(256)
void wcolmax(const float* __restrict__ w, int K, int N, int qkv, int moff)
{
    int n = blockIdx.x * 256 + threadIdx.x;
    int kspan = K / 8;
    int k0 = blockIdx.y * kspan;
    float m = 0.f;
    for (int k = k0; k < k0 + kspan; k++) {
        size_t idx = qkv ? ((size_t)(n >> 6) * K * 64 + (size_t)k * 64 + (n & 63))
                         : ((size_t)k * N + n);
        m = fmaxf(m, fabsf(w[idx]));
    }
    atomicMax((unsigned int*)&g_wmax[moff + n], __float_as_uint(m));
}

__global__ __launch_bounds__(256)
void conv_wq(const float* __restrict__ in, int K, int N, int sel, int moff)
{
    signed char *oh, *ol;
    switch (sel) {
        case 0: oh = g_Wqh_q; ol = g_Wql_q; break;
        case 1: oh = g_Wkh_q; ol = g_Wkl_q; break;
        case 2: oh = g_Wvh_q; ol = g_Wvl_q; break;
        case 3: oh = g_Woh_q; ol = g_Wol_q; break;
        case 4: oh = g_W1h_q; ol = g_W1l_q; break;
        default: oh = g_W2h_q; ol = g_W2l_q; break;
    }
    const bool qkv = sel < 3;
    __shared__ float tile[32][33];
    int tx = threadIdx.x & 31, ty = threadIdx.x >> 5;
    int n0 = blockIdx.x * 32, k0 = blockIdx.y * 32;
    #pragma unroll
    for (int j = 0; j < 4; j++) {
        int k = k0 + ty + j * 8, n = n0 + tx;
        size_t idx = qkv ? ((size_t)(n >> 6) * K * 64 + (size_t)k * 64 + (n & 63))
                         : ((size_t)k * N + n);
        tile[ty + j * 8][tx] = in[idx];
    }
    __syncthreads();
    #pragma unroll
    for (int j = 0; j < 4; j++) {
        int n = n0 + ty + j * 8, k = k0 + tx;
        float inv = 127.f / fmaxf(g_wmax[moff + n], 1e-20f);
        signed char hi, lo;
        q_split(tile[tx][ty + j * 8] * inv, hi, lo);
        oh[(size_t)n * K + k] = hi;
        ol[(size_t)n * K + k] = lo;
    }
}

// ------------------------------ int8 GEMM ------------------------------------
// CTA 128(M)x64(N), 8 warps (4m x 2n), warp tile 32x32, BK=64, double-buffered.
// acc1 = hi*hi ; acc2 = hi*lo + lo*hi ; out = maxA*maxB/16129*(acc1 + acc2/256)
// smem/stage: Ah(10240) Al(10240) Bh(5120) Bl(5120) = 30720 (80B rows)
template<int MODE>
__global__ __launch_bounds__(256)
void gemm_i8(const float* __restrict__ bias, const float* __restrict__ resid)
{
    constexpr int KD  = (MODE == 5) ? FF : DMODEL;
    constexpr int NC  = KD / 64;
    constexpr int STG = 30720;

    extern __shared__ char smraw[];
    const uint32_t sb = smem_u32(smraw);

    const int tid = threadIdx.x, wid = tid >> 5, lane = tid & 31;
    const int wr = wid >> 1, wc = wid & 1;
    const int m0 = blockIdx.y * 128, n0 = blockIdx.x * 64;

    const signed char *Ah, *Al, *Bh, *Bl;
    const float *sAm, *sBm;
    if constexpr (MODE == 0) {
        Ah = (const signed char*)(g_pool + OFF_XQH); Al = (const signed char*)(g_pool + OFF_XQL);
        Bh = g_Wqh_q; Bl = g_Wql_q; sAm = g_sX; sBm = g_wmax + 0;
    } else if constexpr (MODE == 1) {
        Ah = (const signed char*)(g_pool + OFF_XQH); Al = (const signed char*)(g_pool + OFF_XQL);
        Bh = g_Wkh_q; Bl = g_Wkl_q; sAm = g_sX; sBm = g_wmax + 1024;
    } else if constexpr (MODE == 2) {
        Ah = (const signed char*)(g_pool + OFF_XQH); Al = (const signed char*)(g_pool + OFF_XQL);
        Bh = g_Wvh_q; Bl = g_Wvl_q; sAm = g_sX; sBm = g_wmax + 2048;
    } else if constexpr (MODE == 3) {
        Ah = (const signed char*)(g_pool + OFF_OQH); Al = (const signed char*)(g_pool + OFF_OQL);
        Bh = g_Woh_q; Bl = g_Wol_q; sAm = g_sO; sBm = g_wmax + 3072;
    } else if constexpr (MODE == 4) {
        Ah = (const signed char*)(g_pool + OFF_YQH); Al = (const signed char*)(g_pool + OFF_YQL);
        Bh = g_W1h_q; Bl = g_W1l_q; sAm = g_sy; sBm = g_wmax + 5120;
    } else {
        Ah = (const signed char*)(g_pool + OFF_FQH); Al = (const signed char*)(g_pool + OFF_FQL);
        Bh = g_W2h_q; Bl = g_W2l_q; sAm = g_sff; sBm = g_wmax + 4096;
    }

    const signed char* rAh = Ah + (size_t)m0 * KD;
    const signed char* rAl = Al + (size_t)m0 * KD;
    const signed char* rBh = Bh + (size_t)n0 * KD;
    const signed char* rBl = Bl + (size_t)n0 * KD;

    const int aldRow = tid >> 1, aldC0 = (tid & 1) * 2;   // A: 2 chunks/thread/mat
    const int bldRow = tid >> 2, bldC  = tid & 3;         // B: 1 chunk/thread/mat

    auto issue = [&](int k0, int st) {
        uint32_t base = sb + st * STG;
        #pragma unroll
        for (int i = 0; i < 2; i++) {
            int c = aldC0 + i;
            cpasync16(base + aldRow * 80 + c * 16,
                      rAh + (size_t)aldRow * KD + k0 + c * 16);
            cpasync16(base + 10240 + aldRow * 80 + c * 16,
                      rAl + (size_t)aldRow * KD + k0 + c * 16);
        }
        cpasync16(base + 20480 + bldRow * 80 + bldC * 16,
                  rBh + (size_t)bldRow * KD + k0 + bldC * 16);
        cpasync16(base + 25600 + bldRow * 80 + bldC * 16,
                  rBl + (size_t)bldRow * KD + k0 + bldC * 16);
        asm volatile("cp.async.commit_group;" ::: "memory");
    };

    int acc1[2][4][4], acc2[2][4][4];
    #pragma unroll
    for (int i = 0; i < 2; i++)
        #pragma unroll
        for (int j = 0; j < 4; j++)
            #pragma unroll
            for (int q = 0; q < 4; q++) { acc1[i][j][q] = 0; acc2[i][j][q] = 0; }

    const int arow = ((lane >> 3) & 1) * 8 + (lane & 7);
    const int achk = lane >> 4;
    const uint32_t aA0 = sb + (uint32_t)(wr * 32 + arow) * 80 + achk * 16;
    const uint32_t bA0 = sb + 20480 + (uint32_t)(wc * 32 + arow) * 80 + achk * 16;

    issue(0, 0);

    for (int ct = 0; ct < NC; ct++) {
        if (ct + 1 < NC) {
            issue((ct + 1) * 64, (ct + 1) & 1);
            asm volatile("cp.async.wait_group 1;" ::: "memory");
        } else {
            asm volatile("cp.async.wait_group 0;" ::: "memory");
        }
        __syncthreads();
        const uint32_t off = (ct & 1) ? (uint32_t)STG : 0u;
        #pragma unroll
        for (int s = 0; s < 2; s++) {
            uint32_t bh[2][4], bl[2][4];
            #pragma unroll
            for (int bj = 0; bj < 2; bj++) {
                uint32_t ba = bA0 + off + bj * (16 * 80) + s * 32;
                ldsm4(bh[bj], ba);
                ldsm4(bl[bj], ba + 5120);
            }
            #pragma unroll
            for (int mi = 0; mi < 2; mi++) {
                uint32_t ah[4], al[4];
                uint32_t aa = aA0 + off + mi * (16 * 80) + s * 32;
                ldsm4(ah, aa);
                ldsm4(al, aa + 10240);
                #pragma unroll
                for (int nj = 0; nj < 4; nj++) {
                    int bj = nj >> 1, oc = nj & 1;
                    uint32_t bfh[2] = { bh[bj][oc], bh[bj][oc + 2] };
                    uint32_t bfl[2] = { bl[bj][oc], bl[bj][oc + 2] };
                    mma_s8(acc1[mi][nj], ah, bfh);
                    mma_s8(acc2[mi][nj], ah, bfl);
                    mma_s8(acc2[mi][nj], al, bfh);
                }
            }
        }
        __syncthreads();
    }

    // ------------------------------ epilogue ---------------------------------
    const int qrow = lane >> 2, qcol = (lane & 3) * 2;
    const int mrow0 = m0 + wr * 32, ncol0 = n0 + wc * 32;

    float2 bias2[4], sB2[4];
    #pragma unroll
    for (int nj = 0; nj < 4; nj++) {
        int n = ncol0 + nj * 8 + qcol;
        bias2[nj] = *(const float2*)(bias + n);
        sB2[nj]   = *(const float2*)(sBm + n);
    }

    #pragma unroll
    for (int mi = 0; mi < 2; mi++) {
        #pragma unroll
        for (int half = 0; half < 2; half++) {
            int m = mrow0 + mi * 16 + qrow + half * 8;
            float sA = sAm[m] * (1.f / 16129.f);
            #pragma unroll
            for (int nj = 0; nj < 4; nj++) {
                int n = ncol0 + nj * 8 + qcol;
                float r0 = (float)acc1[mi][nj][half * 2 + 0]
                         + (float)acc2[mi][nj][half * 2 + 0] * (1.f / 256.f);
                float r1 = (float)acc1[mi][nj][half * 2 + 1]
                         + (float)acc2[mi][nj][half * 2 + 1] * (1.f / 256.f);
                float v0 = r0 * sA * sB2[nj].x + bias2[nj].x;
                float v1 = r1 * sA * sB2[nj].y + bias2[nj].y;
                if constexpr (MODE <= 2) {
                    if constexpr (MODE == 0) { v0 *= 0.125f; v1 *= 0.125f; }
                    __nv_bfloat16 *oh, *ol;
                    if constexpr (MODE == 0) {
                        oh = (__nv_bfloat16*)(g_pool + OFF_QH); ol = (__nv_bfloat16*)(g_pool + OFF_QL);
                    } else if constexpr (MODE == 1) {
                        oh = (__nv_bfloat16*)(g_pool + OFF_KH); ol = (__nv_bfloat16*)(g_pool + OFF_KL);
                    } else {
                        oh = (__nv_bfloat16*)(g_pool + OFF_VH); ol = (__nv_bfloat16*)(g_pool + OFF_VL);
                    }
                    int b = m >> 11, si = m & 2047, h = n >> 6, e = n & 63;
                    size_t idx = (((size_t)(b * NHEAD + h) * SEQ) + si) * HDIM + e;
                    __nv_bfloat16 h0 = bf_hi(v0), h1 = bf_hi(v1);
                    *(__nv_bfloat162*)(oh + idx) = __nv_bfloat162(h0, h1);
                    *(__nv_bfloat162*)(ol + idx) = __nv_bfloat162(bf_lo(v0, h0), bf_lo(v1, h1));
                } else if constexpr (MODE == 3) {
                    size_t idx = (size_t)m * DMODEL + n;
                    float2 rv = *(const float2*)(resid + idx);
                    *(float2*)((float*)(g_pool + OFF_T1) + idx) = make_float2(v0 + rv.x, v1 + rv.y);
                } else if constexpr (MODE == 4) {
                    size_t idx = (size_t)m * FF + n;
                    *(float2*)((float*)(g_pool + OFF_FF) + idx) =
                        make_float2(fmaxf(v0, 0.f), fmaxf(v1, 0.f));
                } else {
                    size_t idx = (size_t)m * DMODEL + n;
                    float2 rv = *(const float2*)((const float*)(g_pool + OFF_Y) + idx);
                    *(float2*)((float*)(g_pool + OFF_Z) + idx) = make_float2(v0 + rv.x, v1 + rv.y);
                }
            }
        }
    }
}

// ======================= Flash attention (mma.sync bf16) =====================
__global__ __launch_bounds__(256, 2)
void attn_mma()
{
    extern __shared__ char smraw[];
    const uint32_t sb = smem_u32(smraw);
    const int tid = threadIdx.x, lane = tid & 31, w = tid >> 5;
    const int bh = blockIdx.y;
    const int q0 = blockIdx.x * 128;

    const __nv_bfloat16* Qhb = (const __nv_bfloat16*)(g_pool + OFF_QH) + (size_t)bh * SEQ * HDIM;
    const __nv_bfloat16* Qlb = (const __nv_bfloat16*)(g_pool + OFF_QL) + (size_t)bh * SEQ * HDIM;
    const __nv_bfloat16* Khb = (const __nv_bfloat16*)(g_pool + OFF_KH) + (size_t)bh * SEQ * HDIM;
    const __nv_bfloat16* Klb = (const __nv_bfloat16*)(g_pool + OFF_KL) + (size_t)bh * SEQ * HDIM;
    const __nv_bfloat16* Vhb = (const __nv_bfloat16*)(g_pool + OFF_VH) + (size_t)bh * SEQ * HDIM;
    const __nv_bfloat16* Vlb = (const __nv_bfloat16*)(g_pool + OFF_VL) + (size_t)bh * SEQ * HDIM;

    {
        int row = tid >> 1, c0 = (tid & 1) * 4;
        const __nv_bfloat16* gh = Qhb + (size_t)(q0 + row) * HDIM;
        const __nv_bfloat16* gl = Qlb + (size_t)(q0 + row) * HDIM;
        #pragma unroll
        for (int i = 0; i < 4; i++) {
            uint32_t so = row * 144 + (c0 + i) * 16;
            cpasync16(sb + so,         gh + (c0 + i) * 8);
            cpasync16(sb + 18432 + so, gl + (c0 + i) * 8);
        }
    }

    auto kv_issue = [&](int j, int st) {
        uint32_t base = sb + 36864 + st * 36864;
        int row = tid >> 2, c4 = (tid & 3) * 2;
        size_t goff = (size_t)(j * 64 + row) * HDIM;
        const __nv_bfloat16* srcs[4] = { Khb + goff, Klb + goff, Vhb + goff, Vlb + goff };
        #pragma unroll
        for (int t = 0; t < 4; t++) {
            #pragma unroll
            for (int i = 0; i < 2; i++) {
                uint32_t so = t * 9216 + row * 144 + (c4 + i) * 16;
                cpasync16(base + so, srcs[t] + (c4 + i) * 8);
            }
        }
        asm volatile("cp.async.commit_group;" ::: "memory");
    };

    kv_issue(0, 0);

    const int arow = ((lane >> 3) & 1) * 8 + (lane & 7);
    const int achk = lane >> 4;
    const int brow = ((lane >> 4) & 1) * 8 + (lane & 7);
    const int bchk = (lane >> 3) & 1;
    const uint32_t qAddr0 = sb + (uint32_t)(w * 16 + arow) * 144 + achk * 16;
    const int vrow = ((lane >> 3) & 1) * 8 + (lane & 7);
    const int vcol = (lane >> 4) * 8;

    float acc[8][4];
    #pragma unroll
    for (int j = 0; j < 8; j++)
        #pragma unroll
        for (int q = 0; q < 4; q++) acc[j][q] = 0.f;
    float m0 = -1e30f, m1 = -1e30f, l0 = 0.f, l1 = 0.f;

    for (int jt = 0; jt < SEQ / 64; jt++) {
        if (jt + 1 < SEQ / 64) {
            kv_issue(jt + 1, (jt + 1) & 1);
            asm volatile("cp.async.wait_group 1;" ::: "memory");
        } else {
            asm volatile("cp.async.wait_group 0;" ::: "memory");
        }
        __syncthreads();
        const uint32_t stg = sb + 36864 + (jt & 1) * 36864;

        float s[8][4];
        #pragma unroll
        for (int j = 0; j < 8; j++)
            #pragma unroll
            for (int q = 0; q < 4; q++) s[j][q] = 0.f;

        #pragma unroll
        for (int t = 0; t < 4; t++) {
            uint32_t qh4[4], ql4[4];
            uint32_t qa = qAddr0 + t * 32;
            ldsm4(qh4, qa);
            ldsm4(ql4, qa + 18432);
            #pragma unroll
            for (int np = 0; np < 4; np++) {
                uint32_t kh4[4], kl4[4];
                uint32_t ka = stg + (uint32_t)(np * 16 + brow) * 144 + t * 32 + bchk * 16;
                ldsm4(kh4, ka);
                ldsm4(kl4, ka + 9216);
                mma_bf16(s[2 * np],     qh4, &kh4[0]);
                mma_bf16(s[2 * np],     qh4, &kl4[0]);
                mma_bf16(s[2 * np],     ql4, &kh4[0]);
                mma_bf16(s[2 * np + 1], qh4, &kh4[2]);
                mma_bf16(s[2 * np + 1], qh4, &kl4[2]);
                mma_bf16(s[2 * np + 1], ql4, &kh4[2]);
            }
        }

        float mx0 = -1e30f, mx1 = -1e30f;
        #pragma unroll
        for (int j = 0; j < 8; j++) {
            mx0 = fmaxf(mx0, fmaxf(s[j][0], s[j][1]));
            mx1 = fmaxf(mx1, fmaxf(s[j][2], s[j][3]));
        }
        mx0 = fmaxf(mx0, __shfl_xor_sync(0xffffffffu, mx0, 1));
        mx0 = fmaxf(mx0, __shfl_xor_sync(0xffffffffu, mx0, 2));
        mx1 = fmaxf(mx1, __shfl_xor_sync(0xffffffffu, mx1, 1));
        mx1 = fmaxf(mx1, __shfl_xor_sync(0xffffffffu, mx1, 2));
        float mn0 = fmaxf(m0, mx0), mn1 = fmaxf(m1, mx1);
        float cr0 = __expf(m0 - mn0), cr1 = __expf(m1 - mn1);
        float sum0 = 0.f, sum1 = 0.f;
        #pragma unroll
        for (int j = 0; j < 8; j++) {
            s[j][0] = __expf(s[j][0] - mn0); sum0 += s[j][0];
            s[j][1] = __expf(s[j][1] - mn0); sum0 += s[j][1];
            s[j][2] = __expf(s[j][2] - mn1); sum1 += s[j][2];
            s[j][3] = __expf(s[j][3] - mn1); sum1 += s[j][3];
        }
        sum0 += __shfl_xor_sync(0xffffffffu, sum0, 1);
        sum0 += __shfl_xor_sync(0xffffffffu, sum0, 2);
        sum1 += __shfl_xor_sync(0xffffffffu, sum1, 1);
        sum1 += __shfl_xor_sync(0xffffffffu, sum1, 2);
        l0 = l0 * cr0 + sum0;  m0 = mn0;
        l1 = l1 * cr1 + sum1;  m1 = mn1;
        #pragma unroll
        for (int j = 0; j < 8; j++) {
            acc[j][0] *= cr0; acc[j][1] *= cr0;
            acc[j][2] *= cr1; acc[j][3] *= cr1;
        }

        #pragma unroll
        for (int t = 0; t < 4; t++) {
            uint32_t ph[4], pl[4];
            pack_hilo(ph[0], pl[0], s[2 * t][0],     s[2 * t][1]);
            pack_hilo(ph[1], pl[1], s[2 * t][2],     s[2 * t][3]);
            pack_hilo(ph[2], pl[2], s[2 * t + 1][0], s[2 * t + 1][1]);
            pack_hilo(ph[3], pl[3], s[2 * t + 1][2], s[2 * t + 1][3]);
            #pragma unroll
            for (int jp = 0; jp < 4; jp++) {
                uint32_t vh4[4], vl4[4];
                uint32_t va = stg + 18432
                            + (uint32_t)(16 * t + vrow) * 144 + (16 * jp + vcol) * 2;
                ldsm4t(vh4, va);
                ldsm4t(vl4, va + 9216);
                mma_bf16(acc[2 * jp],     ph, &vh4[0]);
                mma_bf16(acc[2 * jp],     ph, &vl4[0]);
                mma_bf16(acc[2 * jp],     pl, &vh4[0]);
                mma_bf16(acc[2 * jp + 1], ph, &vh4[2]);
                mma_bf16(acc[2 * jp + 1], ph, &vl4[2]);
                mma_bf16(acc[2 * jp + 1], pl, &vh4[2]);
            }
        }
        __syncthreads();
    }

    const int b = bh >> 4, h = bh & 15;
    const int r = lane >> 2, m2 = (lane & 3) * 2;
    const float inv0 = 1.f / l0, inv1 = 1.f / l1;
    const int row0 = q0 + w * 16 + r;
    float* OB = (float*)(g_pool + OFF_O) + ((size_t)b * SEQ) * DMODEL + (size_t)h * HDIM;
    #pragma unroll
    for (int j = 0; j < 8; j++) {
        int col = 8 * j + m2;
        *(float2*)(OB + (size_t)row0 * DMODEL + col) =
            make_float2(acc[j][0] * inv0, acc[j][1] * inv0);
        *(float2*)(OB + (size_t)(row0 + 8) * DMODEL + col) =
            make_float2(acc[j][2] * inv1, acc[j][3] * inv1);
    }
}

// =============================== LayerNorm ===================================
__global__ __launch_bounds__(256)
void ln_kernel(const float* __restrict__ g, const float* __restrict__ b,
               float* __restrict__ dstArg, int which)
{
    __shared__ float red[8];
    __shared__ float bc;
    const int tid = threadIdx.x;
    const int row = blockIdx.x;
    const float* src = (which == 0) ? (const float*)(g_pool + OFF_T1)
                                    : (const float*)(g_pool + OFF_Z);
    float* dst = (which == 0) ? (float*)(g_pool + OFF_Y) : dstArg;

    float4 v = ((const float4*)(src + (size_t)row * DMODEL))[tid];
    float s = v.x + v.y + v.z + v.w;
    #pragma unroll
    for (int o = 16; o >= 1; o >>= 1) s += __shfl_xor_sync(0xffffffffu, s, o);
    if ((tid & 31) == 0) red[tid >> 5] = s;
    __syncthreads();
    if (tid == 0) {
        float t = 0.f;
        #pragma unroll
        for (int i = 0; i < 8; i++) t += red[i];
        bc = t;
    }
    __syncthreads();
    float mu = bc * (1.f / DMODEL);
    float dx = v.x - mu, dy = v.y - mu, dz = v.z - mu, dw = v.w - mu;
    float s2 = dx * dx + dy * dy + dz * dz + dw * dw;
    #pragma unroll
    for (int o = 16; o >= 1; o >>= 1) s2 += __shfl_xor_sync(0xffffffffu, s2, o);
    __syncthreads();
    if ((tid & 31) == 0) red[tid >> 5] = s2;
    __syncthreads();
    if (tid == 0) {
        float t = 0.f;
        #pragma unroll
        for (int i = 0; i < 8; i++) t += red[i];
        bc = t;
    }
    __syncthreads();
    float rstd = rsqrtf(bc * (1.f / DMODEL) + 1e-5f);
    float4 gg = ((const float4*)g)[tid];
    float4 bb = ((const float4*)b)[tid];
    float4 o4;
    o4.x = dx * rstd * gg.x + bb.x;
    o4.y = dy * rstd * gg.y + bb.y;
    o4.z = dz * rstd * gg.z + bb.z;
    o4.w = dw * rstd * gg.w + bb.w;
    ((float4*)(dst + (size_t)row * DMODEL))[tid] = o4;

    if (which == 0) {   // also emit int8 hi/lo + row max for FFN1
        float am = fmaxf(fmaxf(fabsf(o4.x), fabsf(o4.y)), fmaxf(fabsf(o4.z), fabsf(o4.w)));
        #pragma unroll
        for (int o = 16; o >= 1; o >>= 1) am = fmaxf(am, __shfl_xor_sync(0xffffffffu, am, o));
        __syncthreads();
        if ((tid & 31) == 0) red[tid >> 5] = am;
        __syncthreads();
        if (tid == 0) {
            float t = 1e-20f;
            #pragma unroll
            for (int i = 0; i < 8; i++) t = fmaxf(t, red[i]);
            bc = t; g_sy[row] = t;
        }
        __syncthreads();
        float inv = 127.f / bc;
        char4 h4, l4;
        q_split(o4.x * inv, h4.x, l4.x);
        q_split(o4.y * inv, h4.y, l4.y);
        q_split(o4.z * inv, h4.z, l4.z);
        q_split(o4.w * inv, h4.w, l4.w);
        size_t idx = (size_t)row * DMODEL + tid * 4;
        *(char4*)((signed char*)(g_pool + OFF_YQH) + idx) = h4;
        *(char4*)((signed char*)(g_pool + OFF_YQL) + idx) = l4;
    }
}

// ================================ launch =====================================
extern "C" void kernel_launch(void* const* d_in, const int* in_sizes, int n_in,
                              void* d_out, int out_size)
{
    (void)in_sizes; (void)n_in; (void)out_size;
    const float* X   = (const float*)d_in[0];
    const float* Wq  = (const float*)d_in[1];
    const float* bq  = (const float*)d_in[2];
    const float* Wk  = (const float*)d_in[3];
    const float* bk  = (const float*)d_in[4];
    const float* Wv  = (const float*)d_in[5];
    const float* bv  = (const float*)d_in[6];
    const float* Wo  = (const float*)d_in[7];
    const float* bo  = (const float*)d_in[8];
    const float* l1g = (const float*)d_in[9];
    const float* l1b = (const float*)d_in[10];
    const float* W1  = (const float*)d_in[11];
    const float* b1  = (const float*)d_in[12];
    const float* W2  = (const float*)d_in[13];
    const float* b2  = (const float*)d_in[14];
    const float* l2g = (const float*)d_in[15];
    const float* l2b = (const float*)d_in[16];

    const int g8_smem = 2 * 30720;     // 61440
    cudaFuncSetAttribute(gemm_i8<0>, cudaFuncAttributeMaxDynamicSharedMemorySize, g8_smem);
    cudaFuncSetAttribute(gemm_i8<1>, cudaFuncAttributeMaxDynamicSharedMemorySize, g8_smem);
    cudaFuncSetAttribute(gemm_i8<2>, cudaFuncAttributeMaxDynamicSharedMemorySize, g8_smem);
    cudaFuncSetAttribute(gemm_i8<3>, cudaFuncAttributeMaxDynamicSharedMemorySize, g8_smem);
    cudaFuncSetAttribute(gemm_i8<4>, cudaFuncAttributeMaxDynamicSharedMemorySize, g8_smem);
    cudaFuncSetAttribute(gemm_i8<5>, cudaFuncAttributeMaxDynamicSharedMemorySize, g8_smem);
    const int attn_smem = 36864 + 2 * 36864;   // 110592
    cudaFuncSetAttribute(attn_mma, cudaFuncAttributeMaxDynamicSharedMemorySize, attn_smem);

    dim3 thr(256);

    quant_rows<1024, 0><<<MB, thr>>>(X);
    zero_wmax<<<36, thr>>>();
    wcolmax<<<dim3(4, 8),  thr>>>(Wq, 1024, 1024, 1, 0);
    wcolmax<<<dim3(4, 8),  thr>>>(Wk, 1024, 1024, 1, 1024);
    wcolmax<<<dim3(4, 8),  thr>>>(Wv, 1024, 1024, 1, 2048);
    wcolmax<<<dim3(4, 8),  thr>>>(Wo, 1024, 1024, 0, 3072);
    wcolmax<<<dim3(4, 8),  thr>>>(W2, 4096, 1024, 0, 4096);
    wcolmax<<<dim3(16, 8), thr>>>(W1, 1024, 4096, 0, 5120);
    conv_wq<<<dim3(32, 32),  thr>>>(Wq, 1024, 1024, 0, 0);
    conv_wq<<<dim3(32, 32),  thr>>>(Wk, 1024, 1024, 1, 1024);
    conv_wq<<<dim3(32, 32),  thr>>>(Wv, 1024, 1024, 2, 2048);
    conv_wq<<<dim3(32, 32),  thr>>>(Wo, 1024, 1024, 3, 3072);
    conv_wq<<<dim3(128, 32), thr>>>(W1, 1024, 4096, 4, 5120);
    conv_wq<<<dim3(32, 128), thr>>>(W2, 4096, 1024, 5, 4096);

    gemm_i8<0><<<dim3(16, 32), thr, g8_smem>>>(bq, nullptr);
    gemm_i8<1><<<dim3(16, 32), thr, g8_smem>>>(bk, nullptr);
    gemm_i8<2><<<dim3(16, 32), thr, g8_smem>>>(bv, nullptr);

    attn_mma<<<dim3(16, 32), thr, attn_smem>>>();

    quant_rows<1024, 1><<<MB, thr>>>(nullptr);
    gemm_i8<3><<<dim3(16, 32), thr, g8_smem>>>(bo, X);
    ln_kernel<<<MB, thr>>>(l1g, l1b, nullptr, 0);

    gemm_i8<4><<<dim3(64, 32), thr, g8_smem>>>(b1, nullptr);
    quant_rows<4096, 2><<<MB, thr>>>(nullptr);
    gemm_i8<5><<<dim3(16, 32), thr, g8_smem>>>(b2, nullptr);
    ln_kernel<<<MB, thr>>>(l2g, l2b, (float*)d_out, 1);
}

// round 11
// speedup vs baseline: 3.1451x; 1.0450x over previous
#include <cuda_runtime.h>
#include <cuda_bf16.h>
#include <cstdint>

#define MB      4096
#define DMODEL  1024
#define NHEAD   16
#define HDIM    64
#define SEQ     2048
#define FF      4096

// ------------------------- pooled scratch (lifetime-overlaid) ----------------
constexpr size_t MiB = 1024u * 1024u;
__device__ __align__(1024) unsigned char g_pool[136 * MiB];

constexpr size_t OFF_QF  = 0 * MiB;     // fp32 16MB   (phase 2-2.5)
constexpr size_t OFF_KF  = 16 * MiB;
constexpr size_t OFF_VF  = 32 * MiB;
constexpr size_t OFF_O   = 48 * MiB;    // fp32 16MB   (phase 3-4)
constexpr size_t OFF_FF  = 0 * MiB;     // fp32 64MB   (phase 7-8)
constexpr size_t OFF_QQH = 64 * MiB;    // s8 4MB each (phase 2.5-3)
constexpr size_t OFF_QQL = 68 * MiB;
constexpr size_t OFF_KQH = 72 * MiB;
constexpr size_t OFF_KQL = 76 * MiB;
constexpr size_t OFF_VTH = 80 * MiB;    // s8 [bh][HD][S]
constexpr size_t OFF_VTL = 84 * MiB;
constexpr size_t OFF_XQH = 88 * MiB;    // s8 4MB      (phase 1-2)
constexpr size_t OFF_XQL = 92 * MiB;
constexpr size_t OFF_FQH = 64 * MiB;    // s8 16MB each (phase 8-9)
constexpr size_t OFF_FQL = 80 * MiB;
constexpr size_t OFF_T1  = 96 * MiB;    // fp32 16MB   (phase 5-6)
constexpr size_t OFF_Z   = 96 * MiB;    // fp32 16MB   (phase 9-10)
constexpr size_t OFF_Y   = 112 * MiB;   // fp32 16MB   (phase 6-9)
constexpr size_t OFF_OQH = 128 * MiB;   // s8 4MB each (phase 4-5)
constexpr size_t OFF_OQL = 132 * MiB;
constexpr size_t OFF_YQH = 128 * MiB;   // s8 4MB each (phase 6-7)
constexpr size_t OFF_YQL = 132 * MiB;

// quantized transposed weights [N][K] + scales
__device__ __align__(128) signed char g_Wqh_q[DMODEL * DMODEL], g_Wql_q[DMODEL * DMODEL];
__device__ __align__(128) signed char g_Wkh_q[DMODEL * DMODEL], g_Wkl_q[DMODEL * DMODEL];
__device__ __align__(128) signed char g_Wvh_q[DMODEL * DMODEL], g_Wvl_q[DMODEL * DMODEL];
__device__ __align__(128) signed char g_Woh_q[DMODEL * DMODEL], g_Wol_q[DMODEL * DMODEL];
__device__ __align__(128) signed char g_W1h_q[FF * DMODEL],     g_W1l_q[FF * DMODEL];
__device__ __align__(128) signed char g_W2h_q[DMODEL * FF],     g_W2l_q[DMODEL * FF];
__device__ __align__(128) float g_wmax[9216];
__device__ __align__(128) float g_qkvmax[96];   // Q 0..31, K 32..63, V 64..95
__device__ __align__(128) float g_sX [MB];
__device__ __align__(128) float g_sO [MB];
__device__ __align__(128) float g_sy [MB];
__device__ __align__(128) float g_sff[MB];

// ------------------------------ helpers --------------------------------------
__device__ __forceinline__ uint32_t smem_u32(const void* p) {
    uint32_t a;
    asm("{ .reg .u64 t; cvta.to.shared.u64 t, %1; cvt.u32.u64 %0, t; }"
        : "=r"(a) : "l"(p));
    return a;
}
__device__ __forceinline__ void cpasync16(uint32_t s, const void* g) {
    asm volatile("cp.async.cg.shared.global [%0], [%1], 16;"
                 :: "r"(s), "l"(g) : "memory");
}
__device__ __forceinline__ void ldsm4(uint32_t* r, uint32_t addr) {
    asm volatile("ldmatrix.sync.aligned.m8n8.x4.shared.b16 {%0,%1,%2,%3}, [%4];"
        : "=r"(r[0]), "=r"(r[1]), "=r"(r[2]), "=r"(r[3]) : "r"(addr));
}
__device__ __forceinline__ void sts_u16(uint32_t addr, uint32_t v) {
    asm volatile("st.shared.u16 [%0], %1;" :: "r"(addr), "r"(v) : "memory");
}
__device__ __forceinline__ void mma_s8(int* c, const uint32_t* a, const uint32_t* b) {
    asm volatile("mma.sync.aligned.m16n8k32.row.col.s32.s8.s8.s32 "
        "{%0,%1,%2,%3}, {%4,%5,%6,%7}, {%8,%9}, {%0,%1,%2,%3};"
        : "+r"(c[0]), "+r"(c[1]), "+r"(c[2]), "+r"(c[3])
        : "r"(a[0]), "r"(a[1]), "r"(a[2]), "r"(a[3]), "r"(b[0]), "r"(b[1]));
}
__device__ __forceinline__ void q_split(float q, signed char& hi, signed char& lo) {
    int h = __float2int_rn(q);
    int l = __float2int_rn((q - (float)h) * 256.f);
    l = max(-127, min(127, l));
    hi = (signed char)h;
    lo = (signed char)l;
}

// ------------------------- quantization kernels ------------------------------
template<int C, int SEL>   // 0: X(arg)->Xq/sX ; 1: O->Oq/sO ; 2: ff->fq/sff
__global__ __launch_bounds__(256)
void quant_rows(const float* __restrict__ srcArg)
{
    const float* src;
    signed char *qh, *ql;
    float* smax;
    if constexpr (SEL == 0) {
        src = srcArg;
        qh = (signed char*)(g_pool + OFF_XQH); ql = (signed char*)(g_pool + OFF_XQL);
        smax = g_sX;
    } else if constexpr (SEL == 1) {
        src = (const float*)(g_pool + OFF_O);
        qh = (signed char*)(g_pool + OFF_OQH); ql = (signed char*)(g_pool + OFF_OQL);
        smax = g_sO;
    } else {
        src = (const float*)(g_pool + OFF_FF);
        qh = (signed char*)(g_pool + OFF_FQH); ql = (signed char*)(g_pool + OFF_FQL);
        smax = g_sff;
    }

    __shared__ float red[8];
    __shared__ float bc;
    const int tid = threadIdx.x, row = blockIdx.x;
    constexpr int V = C / 1024;
    const float4* s4 = (const float4*)(src + (size_t)row * C);
    float4 v[V];
    float mx = 0.f;
    #pragma unroll
    for (int i = 0; i < V; i++) {
        v[i] = s4[tid + i * 256];
        mx = fmaxf(mx, fmaxf(fmaxf(fabsf(v[i].x), fabsf(v[i].y)),
                             fmaxf(fabsf(v[i].z), fabsf(v[i].w))));
    }
    #pragma unroll
    for (int o = 16; o >= 1; o >>= 1) mx = fmaxf(mx, __shfl_xor_sync(0xffffffffu, mx, o));
    if ((tid & 31) == 0) red[tid >> 5] = mx;
    __syncthreads();
    if (tid == 0) {
        float t = 1e-20f;
        #pragma unroll
        for (int i = 0; i < 8; i++) t = fmaxf(t, red[i]);
        bc = t; smax[row] = t;
    }
    __syncthreads();
    const float inv = 127.f / bc;
    #pragma unroll
    for (int i = 0; i < V; i++) {
        char4 h4, l4;
        q_split(v[i].x * inv, h4.x, l4.x);
        q_split(v[i].y * inv, h4.y, l4.y);
        q_split(v[i].z * inv, h4.z, l4.z);
        q_split(v[i].w * inv, h4.w, l4.w);
        size_t idx = (size_t)row * C + (tid + i * 256) * 4;
        *(char4*)(qh + idx) = h4;
        *(char4*)(ql + idx) = l4;
    }
}

__global__ __launch_bounds__(256)
void zero_scales() {
    int i = blockIdx.x * 256 + threadIdx.x;
    if (i < 9216) g_wmax[i] = 0.f;
    if (i < 96)   g_qkvmax[i] = 0.f;
}

__global__ __launch_bounds__(256)
void wcolmax(const float* __restrict__ w, int K, int N, int qkv, int moff)
{
    int n = blockIdx.x * 256 + threadIdx.x;
    int kspan = K / 8;
    int k0 = blockIdx.y * kspan;
    float m = 0.f;
    for (int k = k0; k < k0 + kspan; k++) {
        size_t idx = qkv ? ((size_t)(n >> 6) * K * 64 + (size_t)k * 64 + (n & 63))
                         : ((size_t)k * N + n);
        m = fmaxf(m, fabsf(w[idx]));
    }
    atomicMax((unsigned int*)&g_wmax[moff + n], __float_as_uint(m));
}

__global__ __launch_bounds__(256)
void conv_wq(const float* __restrict__ in, int K, int N, int sel, int moff)
{
    signed char *oh, *ol;
    switch (sel) {
        case 0: oh = g_Wqh_q; ol = g_Wql_q; break;
        case 1: oh = g_Wkh_q; ol = g_Wkl_q; break;
        case 2: oh = g_Wvh_q; ol = g_Wvl_q; break;
        case 3: oh = g_Woh_q; ol = g_Wol_q; break;
        case 4: oh = g_W1h_q; ol = g_W1l_q; break;
        default: oh = g_W2h_q; ol = g_W2l_q; break;
    }
    const bool qkv = sel < 3;
    __shared__ float tile[32][33];
    int tx = threadIdx.x & 31, ty = threadIdx.x >> 5;
    int n0 = blockIdx.x * 32, k0 = blockIdx.y * 32;
    #pragma unroll
    for (int j = 0; j < 4; j++) {
        int k = k0 + ty + j * 8, n = n0 + tx;
        size_t idx = qkv ? ((size_t)(n >> 6) * K * 64 + (size_t)k * 64 + (n & 63))
                         : ((size_t)k * N + n);
        tile[ty + j * 8][tx] = in[idx];
    }
    __syncthreads();
    #pragma unroll
    for (int j = 0; j < 4; j++) {
        int n = n0 + ty + j * 8, k = k0 + tx;
        float inv = 127.f / fmaxf(g_wmax[moff + n], 1e-20f);
        signed char hi, lo;
        q_split(tile[tx][ty + j * 8] * inv, hi, lo);
        oh[(size_t)n * K + k] = hi;
        ol[(size_t)n * K + k] = lo;
    }
}

// per-(array,bh) absmax over the contiguous fp32 QF/KF/VF region (48MB)
__global__ __launch_bounds__(256)
void qkv_absmax()
{
    __shared__ float red[8];
    const float4* src = (const float4*)g_pool;   // OFF_QF == 0
    int idx = blockIdx.x * 256 + threadIdx.x;
    float4 v = src[idx];
    float m = fmaxf(fmaxf(fabsf(v.x), fabsf(v.y)), fmaxf(fabsf(v.z), fabsf(v.w)));
    #pragma unroll
    for (int o = 16; o >= 1; o >>= 1) m = fmaxf(m, __shfl_xor_sync(0xffffffffu, m, o));
    if ((threadIdx.x & 31) == 0) red[threadIdx.x >> 5] = m;
    __syncthreads();
    if (threadIdx.x == 0) {
        float t = 1e-20f;
        #pragma unroll
        for (int i = 0; i < 8; i++) t = fmaxf(t, red[i]);
        int slot = (blockIdx.x * 1024) >> 17;
        atomicMax((unsigned int*)&g_qkvmax[slot], __float_as_uint(t));
    }
}

template<int SEL>    // 0: Q, 1: K
__global__ __launch_bounds__(256)
void quant_qk()
{
    const float* src = (const float*)(g_pool + (SEL == 0 ? OFF_QF : OFF_KF));
    signed char* qh  = (signed char*)(g_pool + (SEL == 0 ? OFF_QQH : OFF_KQH));
    signed char* ql  = (signed char*)(g_pool + (SEL == 0 ? OFF_QQL : OFF_KQL));
    int fi = (blockIdx.x * 256 + threadIdx.x) * 4;
    int bh = fi >> 17;
    float inv = 127.f / g_qkvmax[(SEL == 0 ? 0 : 32) + bh];
    float4 v = *(const float4*)(src + fi);
    char4 h4, l4;
    q_split(v.x * inv, h4.x, l4.x);
    q_split(v.y * inv, h4.y, l4.y);
    q_split(v.z * inv, h4.z, l4.z);
    q_split(v.w * inv, h4.w, l4.w);
    *(char4*)(qh + fi) = h4;
    *(char4*)(ql + fi) = l4;
}

// V fp32 [bh][s][hd] -> transposed s8 hi/lo [bh][hd][s]
__global__ __launch_bounds__(256)
void quant_vt()
{
    __shared__ float tile[32][33];
    const int bh = blockIdx.z;
    const int s0 = blockIdx.x * 32, h0 = blockIdx.y * 32;
    const int tx = threadIdx.x & 31, ty = threadIdx.x >> 5;
    const float* VF = (const float*)(g_pool + OFF_VF) + (size_t)bh * SEQ * HDIM;
    signed char* TH = (signed char*)(g_pool + OFF_VTH) + (size_t)bh * HDIM * SEQ;
    signed char* TL = (signed char*)(g_pool + OFF_VTL) + (size_t)bh * HDIM * SEQ;
    #pragma unroll
    for (int j = 0; j < 4; j++)
        tile[ty + j * 8][tx] = VF[(size_t)(s0 + ty + j * 8) * HDIM + h0 + tx];
    __syncthreads();
    float inv = 127.f / g_qkvmax[64 + bh];
    #pragma unroll
    for (int j = 0; j < 4; j++) {
        int r = ty + j * 8;
        signed char hi, lo;
        q_split(tile[tx][r] * inv, hi, lo);
        size_t o = (size_t)(h0 + r) * SEQ + s0 + tx;
        TH[o] = hi; TL[o] = lo;
    }
}

// ------------------------------ int8 GEMM ------------------------------------
template<int MODE>
__global__ __launch_bounds__(256)
void gemm_i8(const float* __restrict__ bias, const float* __restrict__ resid)
{
    constexpr int KD  = (MODE == 5) ? FF : DMODEL;
    constexpr int NC  = KD / 64;
    constexpr int STG = 30720;

    extern __shared__ char smraw[];
    const uint32_t sb = smem_u32(smraw);

    const int tid = threadIdx.x, wid = tid >> 5, lane = tid & 31;
    const int wr = wid >> 1, wc = wid & 1;
    const int m0 = blockIdx.y * 128, n0 = blockIdx.x * 64;

    const signed char *Ah, *Al, *Bh, *Bl;
    const float *sAm, *sBm;
    if constexpr (MODE == 0) {
        Ah = (const signed char*)(g_pool + OFF_XQH); Al = (const signed char*)(g_pool + OFF_XQL);
        Bh = g_Wqh_q; Bl = g_Wql_q; sAm = g_sX; sBm = g_wmax + 0;
    } else if constexpr (MODE == 1) {
        Ah = (const signed char*)(g_pool + OFF_XQH); Al = (const signed char*)(g_pool + OFF_XQL);
        Bh = g_Wkh_q; Bl = g_Wkl_q; sAm = g_sX; sBm = g_wmax + 1024;
    } else if constexpr (MODE == 2) {
        Ah = (const signed char*)(g_pool + OFF_XQH); Al = (const signed char*)(g_pool + OFF_XQL);
        Bh = g_Wvh_q; Bl = g_Wvl_q; sAm = g_sX; sBm = g_wmax + 2048;
    } else if constexpr (MODE == 3) {
        Ah = (const signed char*)(g_pool + OFF_OQH); Al = (const signed char*)(g_pool + OFF_OQL);
        Bh = g_Woh_q; Bl = g_Wol_q; sAm = g_sO; sBm = g_wmax + 3072;
    } else if constexpr (MODE == 4) {
        Ah = (const signed char*)(g_pool + OFF_YQH); Al = (const signed char*)(g_pool + OFF_YQL);
        Bh = g_W1h_q; Bl = g_W1l_q; sAm = g_sy; sBm = g_wmax + 5120;
    } else {
        Ah = (const signed char*)(g_pool + OFF_FQH); Al = (const signed char*)(g_pool + OFF_FQL);
        Bh = g_W2h_q; Bl = g_W2l_q; sAm = g_sff; sBm = g_wmax + 4096;
    }

    const signed char* rAh = Ah + (size_t)m0 * KD;
    const signed char* rAl = Al + (size_t)m0 * KD;
    const signed char* rBh = Bh + (size_t)n0 * KD;
    const signed char* rBl = Bl + (size_t)n0 * KD;

    const int aldRow = tid >> 1, aldC0 = (tid & 1) * 2;
    const int bldRow = tid >> 2, bldC  = tid & 3;

    auto issue = [&](int k0, int st) {
        uint32_t base = sb + st * STG;
        #pragma unroll
        for (int i = 0; i < 2; i++) {
            int c = aldC0 + i;
            cpasync16(base + aldRow * 80 + c * 16,
                      rAh + (size_t)aldRow * KD + k0 + c * 16);
            cpasync16(base + 10240 + aldRow * 80 + c * 16,
                      rAl + (size_t)aldRow * KD + k0 + c * 16);
        }
        cpasync16(base + 20480 + bldRow * 80 + bldC * 16,
                  rBh + (size_t)bldRow * KD + k0 + bldC * 16);
        cpasync16(base + 25600 + bldRow * 80 + bldC * 16,
                  rBl + (size_t)bldRow * KD + k0 + bldC * 16);
        asm volatile("cp.async.commit_group;" ::: "memory");
    };

    int acc1[2][4][4], acc2[2][4][4];
    #pragma unroll
    for (int i = 0; i < 2; i++)
        #pragma unroll
        for (int j = 0; j < 4; j++)
            #pragma unroll
            for (int q = 0; q < 4; q++) { acc1[i][j][q] = 0; acc2[i][j][q] = 0; }

    const int arow = ((lane >> 3) & 1) * 8 + (lane & 7);
    const int achk = lane >> 4;
    const uint32_t aA0 = sb + (uint32_t)(wr * 32 + arow) * 80 + achk * 16;
    const uint32_t bA0 = sb + 20480 + (uint32_t)(wc * 32 + arow) * 80 + achk * 16;

    issue(0, 0);

    for (int ct = 0; ct < NC; ct++) {
        if (ct + 1 < NC) {
            issue((ct + 1) * 64, (ct + 1) & 1);
            asm volatile("cp.async.wait_group 1;" ::: "memory");
        } else {
            asm volatile("cp.async.wait_group 0;" ::: "memory");
        }
        __syncthreads();
        const uint32_t off = (ct & 1) ? (uint32_t)STG : 0u;
        #pragma unroll
        for (int s = 0; s < 2; s++) {
            uint32_t bh[2][4], bl[2][4];
            #pragma unroll
            for (int bj = 0; bj < 2; bj++) {
                uint32_t ba = bA0 + off + bj * (16 * 80) + s * 32;
                ldsm4(bh[bj], ba);
                ldsm4(bl[bj], ba + 5120);
            }
            #pragma unroll
            for (int mi = 0; mi < 2; mi++) {
                uint32_t ah[4], al[4];
                uint32_t aa = aA0 + off + mi * (16 * 80) + s * 32;
                ldsm4(ah, aa);
                ldsm4(al, aa + 10240);
                #pragma unroll
                for (int nj = 0; nj < 4; nj++) {
                    int bj = nj >> 1, oc = nj & 1;
                    uint32_t bfh[2] = { bh[bj][oc], bh[bj][oc + 2] };
                    uint32_t bfl[2] = { bl[bj][oc], bl[bj][oc + 2] };
                    mma_s8(acc1[mi][nj], ah, bfh);
                    mma_s8(acc2[mi][nj], ah, bfl);
                    mma_s8(acc2[mi][nj], al, bfh);
                }
            }
        }
        __syncthreads();
    }

    const int qrow = lane >> 2, qcol = (lane & 3) * 2;
    const int mrow0 = m0 + wr * 32, ncol0 = n0 + wc * 32;

    float2 bias2[4], sB2[4];
    #pragma unroll
    for (int nj = 0; nj < 4; nj++) {
        int n = ncol0 + nj * 8 + qcol;
        bias2[nj] = *(const float2*)(bias + n);
        sB2[nj]   = *(const float2*)(sBm + n);
    }

    #pragma unroll
    for (int mi = 0; mi < 2; mi++) {
        #pragma unroll
        for (int half = 0; half < 2; half++) {
            int m = mrow0 + mi * 16 + qrow + half * 8;
            float sA = sAm[m] * (1.f / 16129.f);
            #pragma unroll
            for (int nj = 0; nj < 4; nj++) {
                int n = ncol0 + nj * 8 + qcol;
                float r0 = (float)acc1[mi][nj][half * 2 + 0]
                         + (float)acc2[mi][nj][half * 2 + 0] * (1.f / 256.f);
                float r1 = (float)acc1[mi][nj][half * 2 + 1]
                         + (float)acc2[mi][nj][half * 2 + 1] * (1.f / 256.f);
                float v0 = r0 * sA * sB2[nj].x + bias2[nj].x;
                float v1 = r1 * sA * sB2[nj].y + bias2[nj].y;
                if constexpr (MODE <= 2) {
                    float* outf = (float*)(g_pool +
                        (MODE == 0 ? OFF_QF : MODE == 1 ? OFF_KF : OFF_VF));
                    int b = m >> 11, si = m & 2047, h = n >> 6, e = n & 63;
                    size_t idx = (((size_t)(b * NHEAD + h) * SEQ) + si) * HDIM + e;
                    *(float2*)(outf + idx) = make_float2(v0, v1);
                } else if constexpr (MODE == 3) {
                    size_t idx = (size_t)m * DMODEL + n;
                    float2 rv = *(const float2*)(resid + idx);
                    *(float2*)((float*)(g_pool + OFF_T1) + idx) = make_float2(v0 + rv.x, v1 + rv.y);
                } else if constexpr (MODE == 4) {
                    size_t idx = (size_t)m * FF + n;
                    *(float2*)((float*)(g_pool + OFF_FF) + idx) =
                        make_float2(fmaxf(v0, 0.f), fmaxf(v1, 0.f));
                } else {
                    size_t idx = (size_t)m * DMODEL + n;
                    float2 rv = *(const float2*)((const float*)(g_pool + OFF_Y) + idx);
                    *(float2*)((float*)(g_pool + OFF_Z) + idx) = make_float2(v0 + rv.x, v1 + rv.y);
                }
            }
        }
    }
}

// ======================= Flash attention (int8 dual-word) ====================
// CTA: 128 threads, 4 warps, 64 q-rows x one bh. Warp = 16 q-rows x 64-wide KV.
// NOTE fragment pairing: K/V ldsm uses brow/bchk mapping, so matrices land as
// m0=(r0-7,k0-15), m1=(r0-7,k16-31), m2=(r8-15,k0-15), m3=(r8-15,k16-31)
// => B-fragments are {f0,f1} (rows 0-7) and {f2,f3} (rows 8-15).
__global__ __launch_bounds__(128, 3)
void attn_s8()
{
    extern __shared__ char smraw[];
    const uint32_t sb = smem_u32(smraw);
    const int tid = threadIdx.x, lane = tid & 31, w = tid >> 5;
    const int bh = blockIdx.y;
    const int q0 = blockIdx.x * 64;

    const signed char* Qh = (const signed char*)(g_pool + OFF_QQH) + (size_t)bh * SEQ * HDIM;
    const signed char* Ql = (const signed char*)(g_pool + OFF_QQL) + (size_t)bh * SEQ * HDIM;
    const signed char* Kh = (const signed char*)(g_pool + OFF_KQH) + (size_t)bh * SEQ * HDIM;
    const signed char* Kl = (const signed char*)(g_pool + OFF_KQL) + (size_t)bh * SEQ * HDIM;
    const signed char* Th = (const signed char*)(g_pool + OFF_VTH) + (size_t)bh * HDIM * SEQ;
    const signed char* Tl = (const signed char*)(g_pool + OFF_VTL) + (size_t)bh * HDIM * SEQ;

    const float cS = g_qkvmax[bh] * g_qkvmax[32 + bh] * (1.f / (16129.f * 8.f));
    const float cV = g_qkvmax[64 + bh] * (1.f / 16129.f);

    {   // Q tile: 64 rows x 64B, hi+lo
        int row = tid >> 1;
        #pragma unroll
        for (int i = 0; i < 2; i++) {
            int c = (tid & 1) * 2 + i;
            cpasync16(sb + row * 80 + c * 16,        Qh + (size_t)(q0 + row) * HDIM + c * 16);
            cpasync16(sb + 5120 + row * 80 + c * 16, Ql + (size_t)(q0 + row) * HDIM + c * 16);
        }
    }

    auto kv_issue = [&](int j, int st) {
        uint32_t base = sb + 10240 + st * 20480;
        int row = tid >> 1;
        #pragma unroll
        for (int i = 0; i < 2; i++) {
            int c = (tid & 1) * 2 + i;
            cpasync16(base + row * 80 + c * 16,
                      Kh + (size_t)(j * 64 + row) * HDIM + c * 16);
            cpasync16(base + 5120 + row * 80 + c * 16,
                      Kl + (size_t)(j * 64 + row) * HDIM + c * 16);
            cpasync16(base + 10240 + row * 80 + c * 16,
                      Th + (size_t)row * SEQ + j * 64 + c * 16);
            cpasync16(base + 15360 + row * 80 + c * 16,
                      Tl + (size_t)row * SEQ + j * 64 + c * 16);
        }
        asm volatile("cp.async.commit_group;" ::: "memory");
    };

    kv_issue(0, 0);

    const int arow = ((lane >> 3) & 1) * 8 + (lane & 7);
    const int achk = lane >> 4;
    const int brow = ((lane >> 4) & 1) * 8 + (lane & 7);
    const int bchk = (lane >> 3) & 1;
    const uint32_t qA0 = sb + (uint32_t)(w * 16 + arow) * 80 + achk * 16;
    const uint32_t Pw  = sb + 51200 + (uint32_t)w * 2560;
    const uint32_t pA0 = Pw + (uint32_t)arow * 80 + achk * 16;
    const int r = lane >> 2, cbase = (lane & 3) * 2;

    float acc[8][4];
    #pragma unroll
    for (int j = 0; j < 8; j++)
        #pragma unroll
        for (int q = 0; q < 4; q++) acc[j][q] = 0.f;
    float m0 = -1e30f, m1 = -1e30f, l0 = 0.f, l1 = 0.f;

    for (int jt = 0; jt < SEQ / 64; jt++) {
        if (jt + 1 < SEQ / 64) {
            kv_issue(jt + 1, (jt + 1) & 1);
            asm volatile("cp.async.wait_group 1;" ::: "memory");
        } else {
            asm volatile("cp.async.wait_group 0;" ::: "memory");
        }
        __syncthreads();
        const uint32_t stg = sb + 10240 + (jt & 1) * 20480;

        uint32_t qfh[2][4], qfl[2][4];
        #pragma unroll
        for (int t = 0; t < 2; t++) {
            ldsm4(qfh[t], qA0 + t * 32);
            ldsm4(qfl[t], qA0 + 5120 + t * 32);
        }

        // ---- S = QK^T   (fragments: {f0,f1} rows0-7, {f2,f3} rows8-15)
        float s[8][4];
        #pragma unroll
        for (int np = 0; np < 4; np++) {
            int a1[2][4] = {{0,0,0,0},{0,0,0,0}};
            int a2[2][4] = {{0,0,0,0},{0,0,0,0}};
            #pragma unroll
            for (int t = 0; t < 2; t++) {
                uint32_t kfh[4], kfl[4];
                uint32_t ka = stg + (uint32_t)(np * 16 + brow) * 80 + bchk * 16 + t * 32;
                ldsm4(kfh, ka);
                ldsm4(kfl, ka + 5120);
                uint32_t bh0[2] = { kfh[0], kfh[1] }, bh1[2] = { kfh[2], kfh[3] };
                uint32_t bl0[2] = { kfl[0], kfl[1] }, bl1[2] = { kfl[2], kfl[3] };
                mma_s8(a1[0], qfh[t], bh0); mma_s8(a2[0], qfh[t], bl0); mma_s8(a2[0], qfl[t], bh0);
                mma_s8(a1[1], qfh[t], bh1); mma_s8(a2[1], qfh[t], bl1); mma_s8(a2[1], qfl[t], bh1);
            }
            #pragma unroll
            for (int o = 0; o < 2; o++)
                #pragma unroll
                for (int q = 0; q < 4; q++)
                    s[2 * np + o][q] = cS * ((float)a1[o][q] + (float)a2[o][q] * (1.f / 256.f));
        }

        // ---- online softmax (rows r, r+8)
        float mx0 = -1e30f, mx1 = -1e30f;
        #pragma unroll
        for (int j = 0; j < 8; j++) {
            mx0 = fmaxf(mx0, fmaxf(s[j][0], s[j][1]));
            mx1 = fmaxf(mx1, fmaxf(s[j][2], s[j][3]));
        }
        mx0 = fmaxf(mx0, __shfl_xor_sync(0xffffffffu, mx0, 1));
        mx0 = fmaxf(mx0, __shfl_xor_sync(0xffffffffu, mx0, 2));
        mx1 = fmaxf(mx1, __shfl_xor_sync(0xffffffffu, mx1, 1));
        mx1 = fmaxf(mx1, __shfl_xor_sync(0xffffffffu, mx1, 2));
        float mn0 = fmaxf(m0, mx0), mn1 = fmaxf(m1, mx1);
        float cr0 = __expf(m0 - mn0), cr1 = __expf(m1 - mn1);
        float sum0 = 0.f, sum1 = 0.f;
        #pragma unroll
        for (int j = 0; j < 8; j++) {
            s[j][0] = __expf(s[j][0] - mn0); sum0 += s[j][0];
            s[j][1] = __expf(s[j][1] - mn0); sum0 += s[j][1];
            s[j][2] = __expf(s[j][2] - mn1); sum1 += s[j][2];
            s[j][3] = __expf(s[j][3] - mn1); sum1 += s[j][3];
        }
        sum0 += __shfl_xor_sync(0xffffffffu, sum0, 1);
        sum0 += __shfl_xor_sync(0xffffffffu, sum0, 2);
        sum1 += __shfl_xor_sync(0xffffffffu, sum1, 1);
        sum1 += __shfl_xor_sync(0xffffffffu, sum1, 2);
        l0 = l0 * cr0 + sum0;  m0 = mn0;
        l1 = l1 * cr1 + sum1;  m1 = mn1;
        #pragma unroll
        for (int j = 0; j < 8; j++) {
            acc[j][0] *= cr0; acc[j][1] *= cr0;
            acc[j][2] *= cr1; acc[j][3] *= cr1;
        }

        // ---- quantize P (scale 127) and stage via warp-private smem
        #pragma unroll
        for (int j = 0; j < 8; j++) {
            int h0i = __float2int_rn(s[j][0] * 127.f);
            int l0i = min(127, max(-127, __float2int_rn((s[j][0] * 127.f - h0i) * 256.f)));
            int h1i = __float2int_rn(s[j][1] * 127.f);
            int l1i = min(127, max(-127, __float2int_rn((s[j][1] * 127.f - h1i) * 256.f)));
            int h2i = __float2int_rn(s[j][2] * 127.f);
            int l2i = min(127, max(-127, __float2int_rn((s[j][2] * 127.f - h2i) * 256.f)));
            int h3i = __float2int_rn(s[j][3] * 127.f);
            int l3i = min(127, max(-127, __float2int_rn((s[j][3] * 127.f - h3i) * 256.f)));
            uint32_t col = 8 * j + cbase;
            sts_u16(Pw + r * 80 + col,          (h0i & 0xFF) | ((h1i & 0xFF) << 8));
            sts_u16(Pw + 1280 + r * 80 + col,   (l0i & 0xFF) | ((l1i & 0xFF) << 8));
            sts_u16(Pw + (r + 8) * 80 + col,        (h2i & 0xFF) | ((h3i & 0xFF) << 8));
            sts_u16(Pw + 1280 + (r + 8) * 80 + col, (l2i & 0xFF) | ((l3i & 0xFF) << 8));
        }
        __syncwarp();

        uint32_t pfh[2][4], pfl[2][4];
        #pragma unroll
        for (int t = 0; t < 2; t++) {
            ldsm4(pfh[t], pA0 + t * 32);
            ldsm4(pfl[t], pA0 + 1280 + t * 32);
        }

        // ---- acc += P V  ({f0,f1} / {f2,f3} pairing)
        #pragma unroll
        for (int np = 0; np < 4; np++) {
            int a1[2][4] = {{0,0,0,0},{0,0,0,0}};
            int a2[2][4] = {{0,0,0,0},{0,0,0,0}};
            #pragma unroll
            for (int t = 0; t < 2; t++) {
                uint32_t vfh[4], vfl[4];
                uint32_t va = stg + 10240 + (uint32_t)(np * 16 + brow) * 80 + bchk * 16 + t * 32;
                ldsm4(vfh, va);
                ldsm4(vfl, va + 5120);
                uint32_t bh0[2] = { vfh[0], vfh[1] }, bh1[2] = { vfh[2], vfh[3] };
                uint32_t bl0[2] = { vfl[0], vfl[1] }, bl1[2] = { vfl[2], vfl[3] };
                mma_s8(a1[0], pfh[t], bh0); mma_s8(a2[0], pfh[t], bl0); mma_s8(a2[0], pfl[t], bh0);
                mma_s8(a1[1], pfh[t], bh1); mma_s8(a2[1], pfh[t], bl1); mma_s8(a2[1], pfl[t], bh1);
            }
            #pragma unroll
            for (int o = 0; o < 2; o++)
                #pragma unroll
                for (int q = 0; q < 4; q++)
                    acc[2 * np + o][q] += (float)a1[o][q] + (float)a2[o][q] * (1.f / 256.f);
        }
        __syncthreads();
    }

    // ---- epilogue: O fp32 in [M, H*HD]
    const int b = bh >> 4, h = bh & 15;
    const float inv0 = cV / l0, inv1 = cV / l1;
    const int row0 = q0 + w * 16 + r;
    float* OB = (float*)(g_pool + OFF_O) + ((size_t)b * SEQ) * DMODEL + (size_t)h * HDIM;
    #pragma unroll
    for (int j = 0; j < 8; j++) {
        int col = 8 * j + cbase;
        *(float2*)(OB + (size_t)row0 * DMODEL + col) =
            make_float2(acc[j][0] * inv0, acc[j][1] * inv0);
        *(float2*)(OB + (size_t)(row0 + 8) * DMODEL + col) =
            make_float2(acc[j][2] * inv1, acc[j][3] * inv1);
    }
}

// =============================== LayerNorm ===================================
__global__ __launch_bounds__(256)
void ln_kernel(const float* __restrict__ g, const float* __restrict__ b,
               float* __restrict__ dstArg, int which)
{
    __shared__ float red[8];
    __shared__ float bc;
    const int tid = threadIdx.x;
    const int row = blockIdx.x;
    const float* src = (which == 0) ? (const float*)(g_pool + OFF_T1)
                                    : (const float*)(g_pool + OFF_Z);
    float* dst = (which == 0) ? (float*)(g_pool + OFF_Y) : dstArg;

    float4 v = ((const float4*)(src + (size_t)row * DMODEL))[tid];
    float s = v.x + v.y + v.z + v.w;
    #pragma unroll
    for (int o = 16; o >= 1; o >>= 1) s += __shfl_xor_sync(0xffffffffu, s, o);
    if ((tid & 31) == 0) red[tid >> 5] = s;
    __syncthreads();
    if (tid == 0) {
        float t = 0.f;
        #pragma unroll
        for (int i = 0; i < 8; i++) t += red[i];
        bc = t;
    }
    __syncthreads();
    float mu = bc * (1.f / DMODEL);
    float dx = v.x - mu, dy = v.y - mu, dz = v.z - mu, dw = v.w - mu;
    float s2 = dx * dx + dy * dy + dz * dz + dw * dw;
    #pragma unroll
    for (int o = 16; o >= 1; o >>= 1) s2 += __shfl_xor_sync(0xffffffffu, s2, o);
    __syncthreads();
    if ((tid & 31) == 0) red[tid >> 5] = s2;
    __syncthreads();
    if (tid == 0) {
        float t = 0.f;
        #pragma unroll
        for (int i = 0; i < 8; i++) t += red[i];
        bc = t;
    }
    __syncthreads();
    float rstd = rsqrtf(bc * (1.f / DMODEL) + 1e-5f);
    float4 gg = ((const float4*)g)[tid];
    float4 bb = ((const float4*)b)[tid];
    float4 o4;
    o4.x = dx * rstd * gg.x + bb.x;
    o4.y = dy * rstd * gg.y + bb.y;
    o4.z = dz * rstd * gg.z + bb.z;
    o4.w = dw * rstd * gg.w + bb.w;
    ((float4*)(dst + (size_t)row * DMODEL))[tid] = o4;

    if (which == 0) {
        float am = fmaxf(fmaxf(fabsf(o4.x), fabsf(o4.y)), fmaxf(fabsf(o4.z), fabsf(o4.w)));
        #pragma unroll
        for (int o = 16; o >= 1; o >>= 1) am = fmaxf(am, __shfl_xor_sync(0xffffffffu, am, o));
        __syncthreads();
        if ((tid & 31) == 0) red[tid >> 5] = am;
        __syncthreads();
        if (tid == 0) {
            float t = 1e-20f;
            #pragma unroll
            for (int i = 0; i < 8; i++) t = fmaxf(t, red[i]);
            bc = t; g_sy[row] = t;
        }
        __syncthreads();
        float inv = 127.f / bc;
        char4 h4, l4;
        q_split(o4.x * inv, h4.x, l4.x);
        q_split(o4.y * inv, h4.y, l4.y);
        q_split(o4.z * inv, h4.z, l4.z);
        q_split(o4.w * inv, h4.w, l4.w);
        size_t idx = (size_t)row * DMODEL + tid * 4;
        *(char4*)((signed char*)(g_pool + OFF_YQH) + idx) = h4;
        *(char4*)((signed char*)(g_pool + OFF_YQL) + idx) = l4;
    }
}

// ================================ launch =====================================
extern "C" void kernel_launch(void* const* d_in, const int* in_sizes, int n_in,
                              void* d_out, int out_size)
{
    (void)in_sizes; (void)n_in; (void)out_size;
    const float* X   = (const float*)d_in[0];
    const float* Wq  = (const float*)d_in[1];
    const float* bq  = (const float*)d_in[2];
    const float* Wk  = (const float*)d_in[3];
    const float* bk  = (const float*)d_in[4];
    const float* Wv  = (const float*)d_in[5];
    const float* bv  = (const float*)d_in[6];
    const float* Wo  = (const float*)d_in[7];
    const float* bo  = (const float*)d_in[8];
    const float* l1g = (const float*)d_in[9];
    const float* l1b = (const float*)d_in[10];
    const float* W1  = (const float*)d_in[11];
    const float* b1  = (const float*)d_in[12];
    const float* W2  = (const float*)d_in[13];
    const float* b2  = (const float*)d_in[14];
    const float* l2g = (const float*)d_in[15];
    const float* l2b = (const float*)d_in[16];

    const int g8_smem = 2 * 30720;
    cudaFuncSetAttribute(gemm_i8<0>, cudaFuncAttributeMaxDynamicSharedMemorySize, g8_smem);
    cudaFuncSetAttribute(gemm_i8<1>, cudaFuncAttributeMaxDynamicSharedMemorySize, g8_smem);
    cudaFuncSetAttribute(gemm_i8<2>, cudaFuncAttributeMaxDynamicSharedMemorySize, g8_smem);
    cudaFuncSetAttribute(gemm_i8<3>, cudaFuncAttributeMaxDynamicSharedMemorySize, g8_smem);
    cudaFuncSetAttribute(gemm_i8<4>, cudaFuncAttributeMaxDynamicSharedMemorySize, g8_smem);
    cudaFuncSetAttribute(gemm_i8<5>, cudaFuncAttributeMaxDynamicSharedMemorySize, g8_smem);
    const int attn_smem = 61440;
    cudaFuncSetAttribute(attn_s8, cudaFuncAttributeMaxDynamicSharedMemorySize, attn_smem);

    dim3 thr(256);

    zero_scales<<<37, thr>>>();
    quant_rows<1024, 0><<<MB, thr>>>(X);
    wcolmax<<<dim3(4, 8),  thr>>>(Wq, 1024, 1024, 1, 0);
    wcolmax<<<dim3(4, 8),  thr>>>(Wk, 1024, 1024, 1, 1024);
    wcolmax<<<dim3(4, 8),  thr>>>(Wv, 1024, 1024, 1, 2048);
    wcolmax<<<dim3(4, 8),  thr>>>(Wo, 1024, 1024, 0, 3072);
    wcolmax<<<dim3(4, 8),  thr>>>(W2, 4096, 1024, 0, 4096);
    wcolmax<<<dim3(16, 8), thr>>>(W1, 1024, 4096, 0, 5120);
    conv_wq<<<dim3(32, 32),  thr>>>(Wq, 1024, 1024, 0, 0);
    conv_wq<<<dim3(32, 32),  thr>>>(Wk, 1024, 1024, 1, 1024);
    conv_wq<<<dim3(32, 32),  thr>>>(Wv, 1024, 1024, 2, 2048);
    conv_wq<<<dim3(32, 32),  thr>>>(Wo, 1024, 1024, 3, 3072);
    conv_wq<<<dim3(128, 32), thr>>>(W1, 1024, 4096, 4, 5120);
    conv_wq<<<dim3(32, 128), thr>>>(W2, 4096, 1024, 5, 4096);

    gemm_i8<0><<<dim3(16, 32), thr, g8_smem>>>(bq, nullptr);
    gemm_i8<1><<<dim3(16, 32), thr, g8_smem>>>(bk, nullptr);
    gemm_i8<2><<<dim3(16, 32), thr, g8_smem>>>(bv, nullptr);

    qkv_absmax<<<12288, thr>>>();
    quant_qk<0><<<4096, thr>>>();
    quant_qk<1><<<4096, thr>>>();
    quant_vt<<<dim3(64, 2, 32), thr>>>();

    attn_s8<<<dim3(32, 32), dim3(128), attn_smem>>>();

    quant_rows<1024, 1><<<MB, thr>>>(nullptr);
    gemm_i8<3><<<dim3(16, 32), thr, g8_smem>>>(bo, X);
    ln_kernel<<<MB, thr>>>(l1g, l1b, nullptr, 0);

    gemm_i8<4><<<dim3(64, 32), thr, g8_smem>>>(b1, nullptr);
    quant_rows<4096, 2><<<MB, thr>>>(nullptr);
    gemm_i8<5><<<dim3(16, 32), thr, g8_smem>>>(b2, nullptr);
    ln_kernel<<<MB, thr>>>(l2g, l2b, (float*)d_out, 1);
}

// round 12
// speedup vs baseline: 3.5876x; 1.1407x over previous
#include <cuda_runtime.h>
#include <cuda_bf16.h>
#include <cstdint>

#define MB      4096
#define DMODEL  1024
#define NHEAD   16
#define HDIM    64
#define SEQ     2048
#define FF      4096

// ------------------------- pooled scratch (lifetime-overlaid) ----------------
constexpr size_t MiB = 1024u * 1024u;
__device__ __align__(1024) unsigned char g_pool[136 * MiB];

constexpr size_t OFF_QF  = 0 * MiB;     // fp32 16MB   (phase 2-2.5)
constexpr size_t OFF_KF  = 16 * MiB;
constexpr size_t OFF_VF  = 32 * MiB;
constexpr size_t OFF_O   = 48 * MiB;    // fp32 16MB   (phase 3-4)
constexpr size_t OFF_FF  = 0 * MiB;     // fp32 64MB   (phase 7-8)
constexpr size_t OFF_QQH = 64 * MiB;    // s8 4MB (phase 2.5-3; single-word)
constexpr size_t OFF_KQH = 68 * MiB;
constexpr size_t OFF_VTH = 72 * MiB;    // s8 [bh][HD][S]
constexpr size_t OFF_XQH = 88 * MiB;    // s8 4MB      (phase 1-2)
constexpr size_t OFF_XQL = 92 * MiB;
constexpr size_t OFF_FQH = 64 * MiB;    // s8 16MB each (phase 8-9)
constexpr size_t OFF_FQL = 80 * MiB;
constexpr size_t OFF_T1  = 96 * MiB;    // fp32 16MB   (phase 5-6)
constexpr size_t OFF_Z   = 96 * MiB;    // fp32 16MB   (phase 9-10)
constexpr size_t OFF_Y   = 112 * MiB;   // fp32 16MB   (phase 6-9)
constexpr size_t OFF_OQH = 128 * MiB;   // s8 4MB each (phase 4-5)
constexpr size_t OFF_OQL = 132 * MiB;
constexpr size_t OFF_YQH = 128 * MiB;   // s8 4MB each (phase 6-7)
constexpr size_t OFF_YQL = 132 * MiB;

// quantized transposed weights [N][K] + scales
__device__ __align__(128) signed char g_Wqh_q[DMODEL * DMODEL], g_Wql_q[DMODEL * DMODEL];
__device__ __align__(128) signed char g_Wkh_q[DMODEL * DMODEL], g_Wkl_q[DMODEL * DMODEL];
__device__ __align__(128) signed char g_Wvh_q[DMODEL * DMODEL], g_Wvl_q[DMODEL * DMODEL];
__device__ __align__(128) signed char g_Woh_q[DMODEL * DMODEL], g_Wol_q[DMODEL * DMODEL];
__device__ __align__(128) signed char g_W1h_q[FF * DMODEL],     g_W1l_q[FF * DMODEL];
__device__ __align__(128) signed char g_W2h_q[DMODEL * FF],     g_W2l_q[DMODEL * FF];
__device__ __align__(128) float g_wmax[9216];
__device__ __align__(128) float g_qkvmax[96];   // Q 0..31, K 32..63, V 64..95
__device__ __align__(128) float g_sX [MB];
__device__ __align__(128) float g_sO [MB];
__device__ __align__(128) float g_sy [MB];
__device__ __align__(128) float g_sff[MB];

// ------------------------------ helpers --------------------------------------
__device__ __forceinline__ uint32_t smem_u32(const void* p) {
    uint32_t a;
    asm("{ .reg .u64 t; cvta.to.shared.u64 t, %1; cvt.u32.u64 %0, t; }"
        : "=r"(a) : "l"(p));
    return a;
}
__device__ __forceinline__ void cpasync16(uint32_t s, const void* g) {
    asm volatile("cp.async.cg.shared.global [%0], [%1], 16;"
                 :: "r"(s), "l"(g) : "memory");
}
__device__ __forceinline__ void ldsm4(uint32_t* r, uint32_t addr) {
    asm volatile("ldmatrix.sync.aligned.m8n8.x4.shared.b16 {%0,%1,%2,%3}, [%4];"
        : "=r"(r[0]), "=r"(r[1]), "=r"(r[2]), "=r"(r[3]) : "r"(addr));
}
__device__ __forceinline__ void sts_u16(uint32_t addr, uint32_t v) {
    asm volatile("st.shared.u16 [%0], %1;" :: "r"(addr), "r"(v) : "memory");
}
__device__ __forceinline__ void mma_s8(int* c, const uint32_t* a, const uint32_t* b) {
    asm volatile("mma.sync.aligned.m16n8k32.row.col.s32.s8.s8.s32 "
        "{%0,%1,%2,%3}, {%4,%5,%6,%7}, {%8,%9}, {%0,%1,%2,%3};"
        : "+r"(c[0]), "+r"(c[1]), "+r"(c[2]), "+r"(c[3])
        : "r"(a[0]), "r"(a[1]), "r"(a[2]), "r"(a[3]), "r"(b[0]), "r"(b[1]));
}
__device__ __forceinline__ void q_split(float q, signed char& hi, signed char& lo) {
    int h = __float2int_rn(q);
    int l = __float2int_rn((q - (float)h) * 256.f);
    l = max(-127, min(127, l));
    hi = (signed char)h;
    lo = (signed char)l;
}

// ------------------------- quantization kernels ------------------------------
template<int C, int SEL>   // 0: X(arg)->Xq/sX ; 1: O->Oq/sO ; 2: ff->fq/sff
__global__ __launch_bounds__(256)
void quant_rows(const float* __restrict__ srcArg)
{
    const float* src;
    signed char *qh, *ql;
    float* smax;
    if constexpr (SEL == 0) {
        src = srcArg;
        qh = (signed char*)(g_pool + OFF_XQH); ql = (signed char*)(g_pool + OFF_XQL);
        smax = g_sX;
    } else if constexpr (SEL == 1) {
        src = (const float*)(g_pool + OFF_O);
        qh = (signed char*)(g_pool + OFF_OQH); ql = (signed char*)(g_pool + OFF_OQL);
        smax = g_sO;
    } else {
        src = (const float*)(g_pool + OFF_FF);
        qh = (signed char*)(g_pool + OFF_FQH); ql = (signed char*)(g_pool + OFF_FQL);
        smax = g_sff;
    }

    __shared__ float red[8];
    __shared__ float bc;
    const int tid = threadIdx.x, row = blockIdx.x;
    constexpr int V = C / 1024;
    const float4* s4 = (const float4*)(src + (size_t)row * C);
    float4 v[V];
    float mx = 0.f;
    #pragma unroll
    for (int i = 0; i < V; i++) {
        v[i] = s4[tid + i * 256];
        mx = fmaxf(mx, fmaxf(fmaxf(fabsf(v[i].x), fabsf(v[i].y)),
                             fmaxf(fabsf(v[i].z), fabsf(v[i].w))));
    }
    #pragma unroll
    for (int o = 16; o >= 1; o >>= 1) mx = fmaxf(mx, __shfl_xor_sync(0xffffffffu, mx, o));
    if ((tid & 31) == 0) red[tid >> 5] = mx;
    __syncthreads();
    if (tid == 0) {
        float t = 1e-20f;
        #pragma unroll
        for (int i = 0; i < 8; i++) t = fmaxf(t, red[i]);
        bc = t; smax[row] = t;
    }
    __syncthreads();
    const float inv = 127.f / bc;
    #pragma unroll
    for (int i = 0; i < V; i++) {
        char4 h4, l4;
        q_split(v[i].x * inv, h4.x, l4.x);
        q_split(v[i].y * inv, h4.y, l4.y);
        q_split(v[i].z * inv, h4.z, l4.z);
        q_split(v[i].w * inv, h4.w, l4.w);
        size_t idx = (size_t)row * C + (tid + i * 256) * 4;
        *(char4*)(qh + idx) = h4;
        *(char4*)(ql + idx) = l4;
    }
}

__global__ __launch_bounds__(256)
void zero_scales() {
    int i = blockIdx.x * 256 + threadIdx.x;
    if (i < 9216) g_wmax[i] = 0.f;
    if (i < 96)   g_qkvmax[i] = 0.f;
}

__global__ __launch_bounds__(256)
void wcolmax(const float* __restrict__ w, int K, int N, int qkv, int moff)
{
    int n = blockIdx.x * 256 + threadIdx.x;
    int kspan = K / 32;
    int k0 = blockIdx.y * kspan;
    float m = 0.f;
    for (int k = k0; k < k0 + kspan; k++) {
        size_t idx = qkv ? ((size_t)(n >> 6) * K * 64 + (size_t)k * 64 + (n & 63))
                         : ((size_t)k * N + n);
        m = fmaxf(m, fabsf(w[idx]));
    }
    atomicMax((unsigned int*)&g_wmax[moff + n], __float_as_uint(m));
}

__global__ __launch_bounds__(256)
void conv_wq(const float* __restrict__ in, int K, int N, int sel, int moff)
{
    signed char *oh, *ol;
    switch (sel) {
        case 0: oh = g_Wqh_q; ol = g_Wql_q; break;
        case 1: oh = g_Wkh_q; ol = g_Wkl_q; break;
        case 2: oh = g_Wvh_q; ol = g_Wvl_q; break;
        case 3: oh = g_Woh_q; ol = g_Wol_q; break;
        case 4: oh = g_W1h_q; ol = g_W1l_q; break;
        default: oh = g_W2h_q; ol = g_W2l_q; break;
    }
    const bool qkv = sel < 3;
    __shared__ float tile[32][33];
    int tx = threadIdx.x & 31, ty = threadIdx.x >> 5;
    int n0 = blockIdx.x * 32, k0 = blockIdx.y * 32;
    #pragma unroll
    for (int j = 0; j < 4; j++) {
        int k = k0 + ty + j * 8, n = n0 + tx;
        size_t idx = qkv ? ((size_t)(n >> 6) * K * 64 + (size_t)k * 64 + (n & 63))
                         : ((size_t)k * N + n);
        tile[ty + j * 8][tx] = in[idx];
    }
    __syncthreads();
    #pragma unroll
    for (int j = 0; j < 4; j++) {
        int n = n0 + ty + j * 8, k = k0 + tx;
        float inv = 127.f / fmaxf(g_wmax[moff + n], 1e-20f);
        signed char hi, lo;
        q_split(tile[tx][ty + j * 8] * inv, hi, lo);
        oh[(size_t)n * K + k] = hi;
        ol[(size_t)n * K + k] = lo;
    }
}

// per-(array,bh) absmax over the contiguous fp32 QF/KF/VF region (48MB)
__global__ __launch_bounds__(256)
void qkv_absmax()
{
    __shared__ float red[8];
    const float4* src = (const float4*)g_pool;   // OFF_QF == 0
    int idx = blockIdx.x * 256 + threadIdx.x;
    float4 v = src[idx];
    float m = fmaxf(fmaxf(fabsf(v.x), fabsf(v.y)), fmaxf(fabsf(v.z), fabsf(v.w)));
    #pragma unroll
    for (int o = 16; o >= 1; o >>= 1) m = fmaxf(m, __shfl_xor_sync(0xffffffffu, m, o));
    if ((threadIdx.x & 31) == 0) red[threadIdx.x >> 5] = m;
    __syncthreads();
    if (threadIdx.x == 0) {
        float t = 1e-20f;
        #pragma unroll
        for (int i = 0; i < 8; i++) t = fmaxf(t, red[i]);
        int slot = (blockIdx.x * 1024) >> 17;
        atomicMax((unsigned int*)&g_qkvmax[slot], __float_as_uint(t));
    }
}

template<int SEL>    // 0: Q, 1: K  (single-word s8)
__global__ __launch_bounds__(256)
void quant_qk()
{
    const float* src = (const float*)(g_pool + (SEL == 0 ? OFF_QF : OFF_KF));
    signed char* qh  = (signed char*)(g_pool + (SEL == 0 ? OFF_QQH : OFF_KQH));
    int fi = (blockIdx.x * 256 + threadIdx.x) * 4;
    int bh = fi >> 17;
    float inv = 127.f / g_qkvmax[(SEL == 0 ? 0 : 32) + bh];
    float4 v = *(const float4*)(src + fi);
    char4 h4;
    h4.x = (signed char)__float2int_rn(v.x * inv);
    h4.y = (signed char)__float2int_rn(v.y * inv);
    h4.z = (signed char)__float2int_rn(v.z * inv);
    h4.w = (signed char)__float2int_rn(v.w * inv);
    *(char4*)(qh + fi) = h4;
}

// V fp32 [bh][s][hd] -> transposed single-word s8 [bh][hd][s]
__global__ __launch_bounds__(256)
void quant_vt()
{
    __shared__ float tile[32][33];
    const int bh = blockIdx.z;
    const int s0 = blockIdx.x * 32, h0 = blockIdx.y * 32;
    const int tx = threadIdx.x & 31, ty = threadIdx.x >> 5;
    const float* VF = (const float*)(g_pool + OFF_VF) + (size_t)bh * SEQ * HDIM;
    signed char* TH = (signed char*)(g_pool + OFF_VTH) + (size_t)bh * HDIM * SEQ;
    #pragma unroll
    for (int j = 0; j < 4; j++)
        tile[ty + j * 8][tx] = VF[(size_t)(s0 + ty + j * 8) * HDIM + h0 + tx];
    __syncthreads();
    float inv = 127.f / g_qkvmax[64 + bh];
    #pragma unroll
    for (int j = 0; j < 4; j++) {
        int r = ty + j * 8;
        TH[(size_t)(h0 + r) * SEQ + s0 + tx] =
            (signed char)__float2int_rn(tile[tx][r] * inv);
    }
}

// ------------------------------ int8 GEMM ------------------------------------
template<int MODE>
__global__ __launch_bounds__(256)
void gemm_i8(const float* __restrict__ bias, const float* __restrict__ resid)
{
    constexpr int KD  = (MODE == 5) ? FF : DMODEL;
    constexpr int NC  = KD / 64;
    constexpr int STG = 30720;

    extern __shared__ char smraw[];
    const uint32_t sb = smem_u32(smraw);

    const int tid = threadIdx.x, wid = tid >> 5, lane = tid & 31;
    const int wr = wid >> 1, wc = wid & 1;
    const int m0 = blockIdx.y * 128, n0 = blockIdx.x * 64;

    const signed char *Ah, *Al, *Bh, *Bl;
    const float *sAm, *sBm;
    if constexpr (MODE == 0) {
        Ah = (const signed char*)(g_pool + OFF_XQH); Al = (const signed char*)(g_pool + OFF_XQL);
        Bh = g_Wqh_q; Bl = g_Wql_q; sAm = g_sX; sBm = g_wmax + 0;
    } else if constexpr (MODE == 1) {
        Ah = (const signed char*)(g_pool + OFF_XQH); Al = (const signed char*)(g_pool + OFF_XQL);
        Bh = g_Wkh_q; Bl = g_Wkl_q; sAm = g_sX; sBm = g_wmax + 1024;
    } else if constexpr (MODE == 2) {
        Ah = (const signed char*)(g_pool + OFF_XQH); Al = (const signed char*)(g_pool + OFF_XQL);
        Bh = g_Wvh_q; Bl = g_Wvl_q; sAm = g_sX; sBm = g_wmax + 2048;
    } else if constexpr (MODE == 3) {
        Ah = (const signed char*)(g_pool + OFF_OQH); Al = (const signed char*)(g_pool + OFF_OQL);
        Bh = g_Woh_q; Bl = g_Wol_q; sAm = g_sO; sBm = g_wmax + 3072;
    } else if constexpr (MODE == 4) {
        Ah = (const signed char*)(g_pool + OFF_YQH); Al = (const signed char*)(g_pool + OFF_YQL);
        Bh = g_W1h_q; Bl = g_W1l_q; sAm = g_sy; sBm = g_wmax + 5120;
    } else {
        Ah = (const signed char*)(g_pool + OFF_FQH); Al = (const signed char*)(g_pool + OFF_FQL);
        Bh = g_W2h_q; Bl = g_W2l_q; sAm = g_sff; sBm = g_wmax + 4096;
    }

    const signed char* rAh = Ah + (size_t)m0 * KD;
    const signed char* rAl = Al + (size_t)m0 * KD;
    const signed char* rBh = Bh + (size_t)n0 * KD;
    const signed char* rBl = Bl + (size_t)n0 * KD;

    const int aldRow = tid >> 1, aldC0 = (tid & 1) * 2;
    const int bldRow = tid >> 2, bldC  = tid & 3;

    auto issue = [&](int k0, int st) {
        uint32_t base = sb + st * STG;
        #pragma unroll
        for (int i = 0; i < 2; i++) {
            int c = aldC0 + i;
            cpasync16(base + aldRow * 80 + c * 16,
                      rAh + (size_t)aldRow * KD + k0 + c * 16);
            cpasync16(base + 10240 + aldRow * 80 + c * 16,
                      rAl + (size_t)aldRow * KD + k0 + c * 16);
        }
        cpasync16(base + 20480 + bldRow * 80 + bldC * 16,
                  rBh + (size_t)bldRow * KD + k0 + bldC * 16);
        cpasync16(base + 25600 + bldRow * 80 + bldC * 16,
                  rBl + (size_t)bldRow * KD + k0 + bldC * 16);
        asm volatile("cp.async.commit_group;" ::: "memory");
    };

    int acc1[2][4][4], acc2[2][4][4];
    #pragma unroll
    for (int i = 0; i < 2; i++)
        #pragma unroll
        for (int j = 0; j < 4; j++)
            #pragma unroll
            for (int q = 0; q < 4; q++) { acc1[i][j][q] = 0; acc2[i][j][q] = 0; }

    const int arow = ((lane >> 3) & 1) * 8 + (lane & 7);
    const int achk = lane >> 4;
    const uint32_t aA0 = sb + (uint32_t)(wr * 32 + arow) * 80 + achk * 16;
    const uint32_t bA0 = sb + 20480 + (uint32_t)(wc * 32 + arow) * 80 + achk * 16;

    issue(0, 0);

    for (int ct = 0; ct < NC; ct++) {
        if (ct + 1 < NC) {
            issue((ct + 1) * 64, (ct + 1) & 1);
            asm volatile("cp.async.wait_group 1;" ::: "memory");
        } else {
            asm volatile("cp.async.wait_group 0;" ::: "memory");
        }
        __syncthreads();
        const uint32_t off = (ct & 1) ? (uint32_t)STG : 0u;
        #pragma unroll
        for (int s = 0; s < 2; s++) {
            uint32_t bh[2][4], bl[2][4];
            #pragma unroll
            for (int bj = 0; bj < 2; bj++) {
                uint32_t ba = bA0 + off + bj * (16 * 80) + s * 32;
                ldsm4(bh[bj], ba);
                ldsm4(bl[bj], ba + 5120);
            }
            #pragma unroll
            for (int mi = 0; mi < 2; mi++) {
                uint32_t ah[4], al[4];
                uint32_t aa = aA0 + off + mi * (16 * 80) + s * 32;
                ldsm4(ah, aa);
                ldsm4(al, aa + 10240);
                #pragma unroll
                for (int nj = 0; nj < 4; nj++) {
                    int bj = nj >> 1, oc = nj & 1;
                    uint32_t bfh[2] = { bh[bj][oc], bh[bj][oc + 2] };
                    uint32_t bfl[2] = { bl[bj][oc], bl[bj][oc + 2] };
                    mma_s8(acc1[mi][nj], ah, bfh);
                    mma_s8(acc2[mi][nj], ah, bfl);
                    mma_s8(acc2[mi][nj], al, bfh);
                }
            }
        }
        __syncthreads();
    }

    const int qrow = lane >> 2, qcol = (lane & 3) * 2;
    const int mrow0 = m0 + wr * 32, ncol0 = n0 + wc * 32;

    float2 bias2[4], sB2[4];
    #pragma unroll
    for (int nj = 0; nj < 4; nj++) {
        int n = ncol0 + nj * 8 + qcol;
        bias2[nj] = *(const float2*)(bias + n);
        sB2[nj]   = *(const float2*)(sBm + n);
    }

    #pragma unroll
    for (int mi = 0; mi < 2; mi++) {
        #pragma unroll
        for (int half = 0; half < 2; half++) {
            int m = mrow0 + mi * 16 + qrow + half * 8;
            float sA = sAm[m] * (1.f / 16129.f);
            #pragma unroll
            for (int nj = 0; nj < 4; nj++) {
                int n = ncol0 + nj * 8 + qcol;
                float r0 = (float)acc1[mi][nj][half * 2 + 0]
                         + (float)acc2[mi][nj][half * 2 + 0] * (1.f / 256.f);
                float r1 = (float)acc1[mi][nj][half * 2 + 1]
                         + (float)acc2[mi][nj][half * 2 + 1] * (1.f / 256.f);
                float v0 = r0 * sA * sB2[nj].x + bias2[nj].x;
                float v1 = r1 * sA * sB2[nj].y + bias2[nj].y;
                if constexpr (MODE <= 2) {
                    float* outf = (float*)(g_pool +
                        (MODE == 0 ? OFF_QF : MODE == 1 ? OFF_KF : OFF_VF));
                    int b = m >> 11, si = m & 2047, h = n >> 6, e = n & 63;
                    size_t idx = (((size_t)(b * NHEAD + h) * SEQ) + si) * HDIM + e;
                    *(float2*)(outf + idx) = make_float2(v0, v1);
                } else if constexpr (MODE == 3) {
                    size_t idx = (size_t)m * DMODEL + n;
                    float2 rv = *(const float2*)(resid + idx);
                    *(float2*)((float*)(g_pool + OFF_T1) + idx) = make_float2(v0 + rv.x, v1 + rv.y);
                } else if constexpr (MODE == 4) {
                    size_t idx = (size_t)m * FF + n;
                    *(float2*)((float*)(g_pool + OFF_FF) + idx) =
                        make_float2(fmaxf(v0, 0.f), fmaxf(v1, 0.f));
                } else {
                    size_t idx = (size_t)m * DMODEL + n;
                    float2 rv = *(const float2*)((const float*)(g_pool + OFF_Y) + idx);
                    *(float2*)((float*)(g_pool + OFF_Z) + idx) = make_float2(v0 + rv.x, v1 + rv.y);
                }
            }
        }
    }
}

// ======================= Flash attention (s8; single-word QKV, dual P) =======
// CTA: 128 threads, 4 warps, 64 q-rows x one bh. Warp = 16 q-rows x 64-wide KV.
// B-fragment pairing for brow/bchk mapping: {f0,f1} rows0-7, {f2,f3} rows8-15.
// smem: Q 0..5120 (64x80 s8); KV stages at 5120 + st*10240: K +0, Vt +5120;
// P at 25600 + w*2560 (hi 1280, lo 1280). Total 35840.
__global__ __launch_bounds__(128, 4)
void attn_s8()
{
    extern __shared__ char smraw[];
    const uint32_t sb = smem_u32(smraw);
    const int tid = threadIdx.x, lane = tid & 31, w = tid >> 5;
    const int bh = blockIdx.y;
    const int q0 = blockIdx.x * 64;

    const signed char* Qh = (const signed char*)(g_pool + OFF_QQH) + (size_t)bh * SEQ * HDIM;
    const signed char* Kh = (const signed char*)(g_pool + OFF_KQH) + (size_t)bh * SEQ * HDIM;
    const signed char* Th = (const signed char*)(g_pool + OFF_VTH) + (size_t)bh * HDIM * SEQ;

    const float cS = g_qkvmax[bh] * g_qkvmax[32 + bh] * (1.f / (16129.f * 8.f));
    const float cV = g_qkvmax[64 + bh] * (1.f / 16129.f);

    {   // Q tile: 64 rows x 64B
        int row = tid >> 1;
        #pragma unroll
        for (int i = 0; i < 2; i++) {
            int c = (tid & 1) * 2 + i;
            cpasync16(sb + row * 80 + c * 16, Qh + (size_t)(q0 + row) * HDIM + c * 16);
        }
    }

    auto kv_issue = [&](int j, int st) {
        uint32_t base = sb + 5120 + st * 10240;
        int row = tid >> 1;
        #pragma unroll
        for (int i = 0; i < 2; i++) {
            int c = (tid & 1) * 2 + i;
            cpasync16(base + row * 80 + c * 16,
                      Kh + (size_t)(j * 64 + row) * HDIM + c * 16);
            cpasync16(base + 5120 + row * 80 + c * 16,
                      Th + (size_t)row * SEQ + j * 64 + c * 16);
        }
        asm volatile("cp.async.commit_group;" ::: "memory");
    };

    kv_issue(0, 0);

    const int arow = ((lane >> 3) & 1) * 8 + (lane & 7);
    const int achk = lane >> 4;
    const int brow = ((lane >> 4) & 1) * 8 + (lane & 7);
    const int bchk = (lane >> 3) & 1;
    const uint32_t qA0 = sb + (uint32_t)(w * 16 + arow) * 80 + achk * 16;
    const uint32_t Pw  = sb + 25600 + (uint32_t)w * 2560;
    const uint32_t pA0 = Pw + (uint32_t)arow * 80 + achk * 16;
    const int r = lane >> 2, cbase = (lane & 3) * 2;

    float acc[8][4];
    #pragma unroll
    for (int j = 0; j < 8; j++)
        #pragma unroll
        for (int q = 0; q < 4; q++) acc[j][q] = 0.f;
    float m0 = -1e30f, m1 = -1e30f, l0 = 0.f, l1 = 0.f;

    for (int jt = 0; jt < SEQ / 64; jt++) {
        if (jt + 1 < SEQ / 64) {
            kv_issue(jt + 1, (jt + 1) & 1);
            asm volatile("cp.async.wait_group 1;" ::: "memory");
        } else {
            asm volatile("cp.async.wait_group 0;" ::: "memory");
        }
        __syncthreads();
        const uint32_t stg = sb + 5120 + (jt & 1) * 10240;

        uint32_t qf[2][4];
        #pragma unroll
        for (int t = 0; t < 2; t++) ldsm4(qf[t], qA0 + t * 32);

        // ---- S = QK^T (single-word)
        float s[8][4];
        #pragma unroll
        for (int np = 0; np < 4; np++) {
            int a1[2][4] = {{0,0,0,0},{0,0,0,0}};
            #pragma unroll
            for (int t = 0; t < 2; t++) {
                uint32_t kf[4];
                uint32_t ka = stg + (uint32_t)(np * 16 + brow) * 80 + bchk * 16 + t * 32;
                ldsm4(kf, ka);
                uint32_t b0[2] = { kf[0], kf[1] }, b1[2] = { kf[2], kf[3] };
                mma_s8(a1[0], qf[t], b0);
                mma_s8(a1[1], qf[t], b1);
            }
            #pragma unroll
            for (int o = 0; o < 2; o++)
                #pragma unroll
                for (int q = 0; q < 4; q++)
                    s[2 * np + o][q] = cS * (float)a1[o][q];
        }

        // ---- online softmax (rows r, r+8)
        float mx0 = -1e30f, mx1 = -1e30f;
        #pragma unroll
        for (int j = 0; j < 8; j++) {
            mx0 = fmaxf(mx0, fmaxf(s[j][0], s[j][1]));
            mx1 = fmaxf(mx1, fmaxf(s[j][2], s[j][3]));
        }
        mx0 = fmaxf(mx0, __shfl_xor_sync(0xffffffffu, mx0, 1));
        mx0 = fmaxf(mx0, __shfl_xor_sync(0xffffffffu, mx0, 2));
        mx1 = fmaxf(mx1, __shfl_xor_sync(0xffffffffu, mx1, 1));
        mx1 = fmaxf(mx1, __shfl_xor_sync(0xffffffffu, mx1, 2));
        float mn0 = fmaxf(m0, mx0), mn1 = fmaxf(m1, mx1);
        float cr0 = __expf(m0 - mn0), cr1 = __expf(m1 - mn1);
        float sum0 = 0.f, sum1 = 0.f;
        #pragma unroll
        for (int j = 0; j < 8; j++) {
            s[j][0] = __expf(s[j][0] - mn0); sum0 += s[j][0];
            s[j][1] = __expf(s[j][1] - mn0); sum0 += s[j][1];
            s[j][2] = __expf(s[j][2] - mn1); sum1 += s[j][2];
            s[j][3] = __expf(s[j][3] - mn1); sum1 += s[j][3];
        }
        sum0 += __shfl_xor_sync(0xffffffffu, sum0, 1);
        sum0 += __shfl_xor_sync(0xffffffffu, sum0, 2);
        sum1 += __shfl_xor_sync(0xffffffffu, sum1, 1);
        sum1 += __shfl_xor_sync(0xffffffffu, sum1, 2);
        l0 = l0 * cr0 + sum0;  m0 = mn0;
        l1 = l1 * cr1 + sum1;  m1 = mn1;
        #pragma unroll
        for (int j = 0; j < 8; j++) {
            acc[j][0] *= cr0; acc[j][1] *= cr0;
            acc[j][2] *= cr1; acc[j][3] *= cr1;
        }

        // ---- quantize P dual-word (scale 127) and stage via warp-private smem
        #pragma unroll
        for (int j = 0; j < 8; j++) {
            int h0i = __float2int_rn(s[j][0] * 127.f);
            int l0i = min(127, max(-127, __float2int_rn((s[j][0] * 127.f - h0i) * 256.f)));
            int h1i = __float2int_rn(s[j][1] * 127.f);
            int l1i = min(127, max(-127, __float2int_rn((s[j][1] * 127.f - h1i) * 256.f)));
            int h2i = __float2int_rn(s[j][2] * 127.f);
            int l2i = min(127, max(-127, __float2int_rn((s[j][2] * 127.f - h2i) * 256.f)));
            int h3i = __float2int_rn(s[j][3] * 127.f);
            int l3i = min(127, max(-127, __float2int_rn((s[j][3] * 127.f - h3i) * 256.f)));
            uint32_t col = 8 * j + cbase;
            sts_u16(Pw + r * 80 + col,          (h0i & 0xFF) | ((h1i & 0xFF) << 8));
            sts_u16(Pw + 1280 + r * 80 + col,   (l0i & 0xFF) | ((l1i & 0xFF) << 8));
            sts_u16(Pw + (r + 8) * 80 + col,        (h2i & 0xFF) | ((h3i & 0xFF) << 8));
            sts_u16(Pw + 1280 + (r + 8) * 80 + col, (l2i & 0xFF) | ((l3i & 0xFF) << 8));
        }
        __syncwarp();

        uint32_t pfh[2][4], pfl[2][4];
        #pragma unroll
        for (int t = 0; t < 2; t++) {
            ldsm4(pfh[t], pA0 + t * 32);
            ldsm4(pfl[t], pA0 + 1280 + t * 32);
        }

        // ---- acc += P V  (dual P x single V)
        #pragma unroll
        for (int np = 0; np < 4; np++) {
            int a1[2][4] = {{0,0,0,0},{0,0,0,0}};
            int a2[2][4] = {{0,0,0,0},{0,0,0,0}};
            #pragma unroll
            for (int t = 0; t < 2; t++) {
                uint32_t vf[4];
                uint32_t va = stg + 5120 + (uint32_t)(np * 16 + brow) * 80 + bchk * 16 + t * 32;
                ldsm4(vf, va);
                uint32_t b0[2] = { vf[0], vf[1] }, b1[2] = { vf[2], vf[3] };
                mma_s8(a1[0], pfh[t], b0); mma_s8(a2[0], pfl[t], b0);
                mma_s8(a1[1], pfh[t], b1); mma_s8(a2[1], pfl[t], b1);
            }
            #pragma unroll
            for (int o = 0; o < 2; o++)
                #pragma unroll
                for (int q = 0; q < 4; q++)
                    acc[2 * np + o][q] += (float)a1[o][q] + (float)a2[o][q] * (1.f / 256.f);
        }
        __syncthreads();
    }

    // ---- epilogue: O fp32 in [M, H*HD]
    const int b = bh >> 4, h = bh & 15;
    const float inv0 = cV / l0, inv1 = cV / l1;
    const int row0 = q0 + w * 16 + r;
    float* OB = (float*)(g_pool + OFF_O) + ((size_t)b * SEQ) * DMODEL + (size_t)h * HDIM;
    #pragma unroll
    for (int j = 0; j < 8; j++) {
        int col = 8 * j + cbase;
        *(float2*)(OB + (size_t)row0 * DMODEL + col) =
            make_float2(acc[j][0] * inv0, acc[j][1] * inv0);
        *(float2*)(OB + (size_t)(row0 + 8) * DMODEL + col) =
            make_float2(acc[j][2] * inv1, acc[j][3] * inv1);
    }
}

// =============================== LayerNorm ===================================
__global__ __launch_bounds__(256)
void ln_kernel(const float* __restrict__ g, const float* __restrict__ b,
               float* __restrict__ dstArg, int which)
{
    __shared__ float red[8];
    __shared__ float bc;
    const int tid = threadIdx.x;
    const int row = blockIdx.x;
    const float* src = (which == 0) ? (const float*)(g_pool + OFF_T1)
                                    : (const float*)(g_pool + OFF_Z);
    float* dst = (which == 0) ? (float*)(g_pool + OFF_Y) : dstArg;

    float4 v = ((const float4*)(src + (size_t)row * DMODEL))[tid];
    float s = v.x + v.y + v.z + v.w;
    #pragma unroll
    for (int o = 16; o >= 1; o >>= 1) s += __shfl_xor_sync(0xffffffffu, s, o);
    if ((tid & 31) == 0) red[tid >> 5] = s;
    __syncthreads();
    if (tid == 0) {
        float t = 0.f;
        #pragma unroll
        for (int i = 0; i < 8; i++) t += red[i];
        bc = t;
    }
    __syncthreads();
    float mu = bc * (1.f / DMODEL);
    float dx = v.x - mu, dy = v.y - mu, dz = v.z - mu, dw = v.w - mu;
    float s2 = dx * dx + dy * dy + dz * dz + dw * dw;
    #pragma unroll
    for (int o = 16; o >= 1; o >>= 1) s2 += __shfl_xor_sync(0xffffffffu, s2, o);
    __syncthreads();
    if ((tid & 31) == 0) red[tid >> 5] = s2;
    __syncthreads();
    if (tid == 0) {
        float t = 0.f;
        #pragma unroll
        for (int i = 0; i < 8; i++) t += red[i];
        bc = t;
    }
    __syncthreads();
    float rstd = rsqrtf(bc * (1.f / DMODEL) + 1e-5f);
    float4 gg = ((const float4*)g)[tid];
    float4 bb = ((const float4*)b)[tid];
    float4 o4;
    o4.x = dx * rstd * gg.x + bb.x;
    o4.y = dy * rstd * gg.y + bb.y;
    o4.z = dz * rstd * gg.z + bb.z;
    o4.w = dw * rstd * gg.w + bb.w;
    ((float4*)(dst + (size_t)row * DMODEL))[tid] = o4;

    if (which == 0) {
        float am = fmaxf(fmaxf(fabsf(o4.x), fabsf(o4.y)), fmaxf(fabsf(o4.z), fabsf(o4.w)));
        #pragma unroll
        for (int o = 16; o >= 1; o >>= 1) am = fmaxf(am, __shfl_xor_sync(0xffffffffu, am, o));
        __syncthreads();
        if ((tid & 31) == 0) red[tid >> 5] = am;
        __syncthreads();
        if (tid == 0) {
            float t = 1e-20f;
            #pragma unroll
            for (int i = 0; i < 8; i++) t = fmaxf(t, red[i]);
            bc = t; g_sy[row] = t;
        }
        __syncthreads();
        float inv = 127.f / bc;
        char4 h4, l4;
        q_split(o4.x * inv, h4.x, l4.x);
        q_split(o4.y * inv, h4.y, l4.y);
        q_split(o4.z * inv, h4.z, l4.z);
        q_split(o4.w * inv, h4.w, l4.w);
        size_t idx = (size_t)row * DMODEL + tid * 4;
        *(char4*)((signed char*)(g_pool + OFF_YQH) + idx) = h4;
        *(char4*)((signed char*)(g_pool + OFF_YQL) + idx) = l4;
    }
}

// ================================ launch =====================================
extern "C" void kernel_launch(void* const* d_in, const int* in_sizes, int n_in,
                              void* d_out, int out_size)
{
    (void)in_sizes; (void)n_in; (void)out_size;
    const float* X   = (const float*)d_in[0];
    const float* Wq  = (const float*)d_in[1];
    const float* bq  = (const float*)d_in[2];
    const float* Wk  = (const float*)d_in[3];
    const float* bk  = (const float*)d_in[4];
    const float* Wv  = (const float*)d_in[5];
    const float* bv  = (const float*)d_in[6];
    const float* Wo  = (const float*)d_in[7];
    const float* bo  = (const float*)d_in[8];
    const float* l1g = (const float*)d_in[9];
    const float* l1b = (const float*)d_in[10];
    const float* W1  = (const float*)d_in[11];
    const float* b1  = (const float*)d_in[12];
    const float* W2  = (const float*)d_in[13];
    const float* b2  = (const float*)d_in[14];
    const float* l2g = (const float*)d_in[15];
    const float* l2b = (const float*)d_in[16];

    const int g8_smem = 2 * 30720;
    cudaFuncSetAttribute(gemm_i8<0>, cudaFuncAttributeMaxDynamicSharedMemorySize, g8_smem);
    cudaFuncSetAttribute(gemm_i8<1>, cudaFuncAttributeMaxDynamicSharedMemorySize, g8_smem);
    cudaFuncSetAttribute(gemm_i8<2>, cudaFuncAttributeMaxDynamicSharedMemorySize, g8_smem);
    cudaFuncSetAttribute(gemm_i8<3>, cudaFuncAttributeMaxDynamicSharedMemorySize, g8_smem);
    cudaFuncSetAttribute(gemm_i8<4>, cudaFuncAttributeMaxDynamicSharedMemorySize, g8_smem);
    cudaFuncSetAttribute(gemm_i8<5>, cudaFuncAttributeMaxDynamicSharedMemorySize, g8_smem);
    const int attn_smem = 35840;
    cudaFuncSetAttribute(attn_s8, cudaFuncAttributeMaxDynamicSharedMemorySize, attn_smem);

    dim3 thr(256);

    zero_scales<<<37, thr>>>();
    quant_rows<1024, 0><<<MB, thr>>>(X);
    wcolmax<<<dim3(4, 32),  thr>>>(Wq, 1024, 1024, 1, 0);
    wcolmax<<<dim3(4, 32),  thr>>>(Wk, 1024, 1024, 1, 1024);
    wcolmax<<<dim3(4, 32),  thr>>>(Wv, 1024, 1024, 1, 2048);
    wcolmax<<<dim3(4, 32),  thr>>>(Wo, 1024, 1024, 0, 3072);
    wcolmax<<<dim3(4, 32),  thr>>>(W2, 4096, 1024, 0, 4096);
    wcolmax<<<dim3(16, 32), thr>>>(W1, 1024, 4096, 0, 5120);
    conv_wq<<<dim3(32, 32),  thr>>>(Wq, 1024, 1024, 0, 0);
    conv_wq<<<dim3(32, 32),  thr>>>(Wk, 1024, 1024, 1, 1024);
    conv_wq<<<dim3(32, 32),  thr>>>(Wv, 1024, 1024, 2, 2048);
    conv_wq<<<dim3(32, 32),  thr>>>(Wo, 1024, 1024, 3, 3072);
    conv_wq<<<dim3(128, 32), thr>>>(W1, 1024, 4096, 4, 5120);
    conv_wq<<<dim3(32, 128), thr>>>(W2, 4096, 1024, 5, 4096);

    gemm_i8<0><<<dim3(16, 32), thr, g8_smem>>>(bq, nullptr);
    gemm_i8<1><<<dim3(16, 32), thr, g8_smem>>>(bk, nullptr);
    gemm_i8<2><<<dim3(16, 32), thr, g8_smem>>>(bv, nullptr);

    qkv_absmax<<<12288, thr>>>();
    quant_qk<0><<<4096, thr>>>();
    quant_qk<1><<<4096, thr>>>();
    quant_vt<<<dim3(64, 2, 32), thr>>>();

    attn_s8<<<dim3(32, 32), dim3(128), attn_smem>>>();

    quant_rows<1024, 1><<<MB, thr>>>(nullptr);
    gemm_i8<3><<<dim3(16, 32), thr, g8_smem>>>(bo, X);
    ln_kernel<<<MB, thr>>>(l1g, l1b, nullptr, 0);

    gemm_i8<4><<<dim3(64, 32), thr, g8_smem>>>(b1, nullptr);
    quant_rows<4096, 2><<<MB, thr>>>(nullptr);
    gemm_i8<5><<<dim3(16, 32), thr, g8_smem>>>(b2, nullptr);
    ln_kernel<<<MB, thr>>>(l2g, l2b, (float*)d_out, 1);
}

// round 13
// speedup vs baseline: 4.0999x; 1.1428x over previous
#include <cuda_runtime.h>
#include <cuda_bf16.h>
#include <cstdint>

#define MB      4096
#define DMODEL  1024
#define NHEAD   16
#define HDIM    64
#define SEQ     2048
#define FF      4096

// ------------------------- pooled scratch (lifetime-overlaid) ----------------
constexpr size_t MiB = 1024u * 1024u;
__device__ __align__(1024) unsigned char g_pool[136 * MiB];

constexpr size_t OFF_QF  = 0 * MiB;     // fp32 16MB   (phase 2-2.5)
constexpr size_t OFF_KF  = 16 * MiB;
constexpr size_t OFF_VF  = 32 * MiB;
constexpr size_t OFF_O   = 48 * MiB;    // fp32 16MB   (phase 3-4)
constexpr size_t OFF_FF  = 0 * MiB;     // fp32 64MB   (phase 7-8)
constexpr size_t OFF_QQH = 64 * MiB;    // s8 4MB (single-word)
constexpr size_t OFF_KQH = 68 * MiB;
constexpr size_t OFF_VTH = 72 * MiB;    // s8 [bh][HD][S]
constexpr size_t OFF_XQH = 88 * MiB;    // s8 4MB (single-word; phase 1-2)
constexpr size_t OFF_FQH = 64 * MiB;    // s8 16MB each (phase 8-9)
constexpr size_t OFF_FQL = 80 * MiB;
constexpr size_t OFF_T1  = 96 * MiB;    // fp32 16MB   (phase 5-6)
constexpr size_t OFF_Z   = 96 * MiB;    // fp32 16MB   (phase 9-10)
constexpr size_t OFF_Y   = 112 * MiB;   // fp32 16MB   (phase 6-9)
constexpr size_t OFF_OQH = 128 * MiB;   // s8 4MB (single-word; phase 4-5)
constexpr size_t OFF_YQH = 128 * MiB;   // s8 4MB each (phase 6-7; Oq dead)
constexpr size_t OFF_YQL = 132 * MiB;

// quantized transposed weights [N][K] + scales
__device__ __align__(128) signed char g_Wqh_q[DMODEL * DMODEL], g_Wql_q[DMODEL * DMODEL];
__device__ __align__(128) signed char g_Wkh_q[DMODEL * DMODEL], g_Wkl_q[DMODEL * DMODEL];
__device__ __align__(128) signed char g_Wvh_q[DMODEL * DMODEL], g_Wvl_q[DMODEL * DMODEL];
__device__ __align__(128) signed char g_Woh_q[DMODEL * DMODEL], g_Wol_q[DMODEL * DMODEL];
__device__ __align__(128) signed char g_W1h_q[FF * DMODEL],     g_W1l_q[FF * DMODEL];
__device__ __align__(128) signed char g_W2h_q[DMODEL * FF],     g_W2l_q[DMODEL * FF];
__device__ __align__(128) float g_wmax[9216];
__device__ __align__(128) float g_qkvmax[96];   // Q 0..31, K 32..63, V 64..95
__device__ __align__(128) float g_sX [MB];
__device__ __align__(128) float g_sO [MB];
__device__ __align__(128) float g_sy [MB];
__device__ __align__(128) float g_sff[MB];

// ------------------------------ helpers --------------------------------------
__device__ __forceinline__ uint32_t smem_u32(const void* p) {
    uint32_t a;
    asm("{ .reg .u64 t; cvta.to.shared.u64 t, %1; cvt.u32.u64 %0, t; }"
        : "=r"(a) : "l"(p));
    return a;
}
__device__ __forceinline__ void cpasync16(uint32_t s, const void* g) {
    asm volatile("cp.async.cg.shared.global [%0], [%1], 16;"
                 :: "r"(s), "l"(g) : "memory");
}
__device__ __forceinline__ void ldsm4(uint32_t* r, uint32_t addr) {
    asm volatile("ldmatrix.sync.aligned.m8n8.x4.shared.b16 {%0,%1,%2,%3}, [%4];"
        : "=r"(r[0]), "=r"(r[1]), "=r"(r[2]), "=r"(r[3]) : "r"(addr));
}
__device__ __forceinline__ void sts_u16(uint32_t addr, uint32_t v) {
    asm volatile("st.shared.u16 [%0], %1;" :: "r"(addr), "r"(v) : "memory");
}
__device__ __forceinline__ void mma_s8(int* c, const uint32_t* a, const uint32_t* b) {
    asm volatile("mma.sync.aligned.m16n8k32.row.col.s32.s8.s8.s32 "
        "{%0,%1,%2,%3}, {%4,%5,%6,%7}, {%8,%9}, {%0,%1,%2,%3};"
        : "+r"(c[0]), "+r"(c[1]), "+r"(c[2]), "+r"(c[3])
        : "r"(a[0]), "r"(a[1]), "r"(a[2]), "r"(a[3]), "r"(b[0]), "r"(b[1]));
}
__device__ __forceinline__ void q_split(float q, signed char& hi, signed char& lo) {
    int h = __float2int_rn(q);
    int l = __float2int_rn((q - (float)h) * 256.f);
    l = max(-127, min(127, l));
    hi = (signed char)h;
    lo = (signed char)l;
}

// ------------------------- quantization kernels ------------------------------
// SEL 0: X(arg)->Xq single/sX ; SEL 1: O->Oq single/sO ; SEL 2: ff->fq dual/sff
template<int C, int SEL>
__global__ __launch_bounds__(256)
void quant_rows(const float* __restrict__ srcArg)
{
    const float* src;
    signed char *qh, *ql;
    float* smax;
    if constexpr (SEL == 0) {
        src = srcArg;
        qh = (signed char*)(g_pool + OFF_XQH); ql = nullptr;
        smax = g_sX;
    } else if constexpr (SEL == 1) {
        src = (const float*)(g_pool + OFF_O);
        qh = (signed char*)(g_pool + OFF_OQH); ql = nullptr;
        smax = g_sO;
    } else {
        src = (const float*)(g_pool + OFF_FF);
        qh = (signed char*)(g_pool + OFF_FQH); ql = (signed char*)(g_pool + OFF_FQL);
        smax = g_sff;
    }

    __shared__ float red[8];
    __shared__ float bc;
    const int tid = threadIdx.x, row = blockIdx.x;
    constexpr int V = C / 1024;
    const float4* s4 = (const float4*)(src + (size_t)row * C);
    float4 v[V];
    float mx = 0.f;
    #pragma unroll
    for (int i = 0; i < V; i++) {
        v[i] = s4[tid + i * 256];
        mx = fmaxf(mx, fmaxf(fmaxf(fabsf(v[i].x), fabsf(v[i].y)),
                             fmaxf(fabsf(v[i].z), fabsf(v[i].w))));
    }
    #pragma unroll
    for (int o = 16; o >= 1; o >>= 1) mx = fmaxf(mx, __shfl_xor_sync(0xffffffffu, mx, o));
    if ((tid & 31) == 0) red[tid >> 5] = mx;
    __syncthreads();
    if (tid == 0) {
        float t = 1e-20f;
        #pragma unroll
        for (int i = 0; i < 8; i++) t = fmaxf(t, red[i]);
        bc = t; smax[row] = t;
    }
    __syncthreads();
    const float inv = 127.f / bc;
    #pragma unroll
    for (int i = 0; i < V; i++) {
        size_t idx = (size_t)row * C + (tid + i * 256) * 4;
        if constexpr (SEL == 2) {
            char4 h4, l4;
            q_split(v[i].x * inv, h4.x, l4.x);
            q_split(v[i].y * inv, h4.y, l4.y);
            q_split(v[i].z * inv, h4.z, l4.z);
            q_split(v[i].w * inv, h4.w, l4.w);
            *(char4*)(qh + idx) = h4;
            *(char4*)(ql + idx) = l4;
        } else {
            char4 h4;
            h4.x = (signed char)__float2int_rn(v[i].x * inv);
            h4.y = (signed char)__float2int_rn(v[i].y * inv);
            h4.z = (signed char)__float2int_rn(v[i].z * inv);
            h4.w = (signed char)__float2int_rn(v[i].w * inv);
            *(char4*)(qh + idx) = h4;
        }
    }
}

__global__ __launch_bounds__(256)
void zero_scales() {
    int i = blockIdx.x * 256 + threadIdx.x;
    if (i < 9216) g_wmax[i] = 0.f;
    if (i < 96)   g_qkvmax[i] = 0.f;
}

__global__ __launch_bounds__(256)
void wcolmax(const float* __restrict__ w, int K, int N, int qkv, int moff)
{
    int n = blockIdx.x * 256 + threadIdx.x;
    int kspan = K / 32;
    int k0 = blockIdx.y * kspan;
    float m = 0.f;
    for (int k = k0; k < k0 + kspan; k++) {
        size_t idx = qkv ? ((size_t)(n >> 6) * K * 64 + (size_t)k * 64 + (n & 63))
                         : ((size_t)k * N + n);
        m = fmaxf(m, fabsf(w[idx]));
    }
    atomicMax((unsigned int*)&g_wmax[moff + n], __float_as_uint(m));
}

__global__ __launch_bounds__(256)
void conv_wq(const float* __restrict__ in, int K, int N, int sel, int moff)
{
    signed char *oh, *ol;
    switch (sel) {
        case 0: oh = g_Wqh_q; ol = g_Wql_q; break;
        case 1: oh = g_Wkh_q; ol = g_Wkl_q; break;
        case 2: oh = g_Wvh_q; ol = g_Wvl_q; break;
        case 3: oh = g_Woh_q; ol = g_Wol_q; break;
        case 4: oh = g_W1h_q; ol = g_W1l_q; break;
        default: oh = g_W2h_q; ol = g_W2l_q; break;
    }
    const bool qkv = sel < 3;
    __shared__ float tile[32][33];
    int tx = threadIdx.x & 31, ty = threadIdx.x >> 5;
    int n0 = blockIdx.x * 32, k0 = blockIdx.y * 32;
    #pragma unroll
    for (int j = 0; j < 4; j++) {
        int k = k0 + ty + j * 8, n = n0 + tx;
        size_t idx = qkv ? ((size_t)(n >> 6) * K * 64 + (size_t)k * 64 + (n & 63))
                         : ((size_t)k * N + n);
        tile[ty + j * 8][tx] = in[idx];
    }
    __syncthreads();
    #pragma unroll
    for (int j = 0; j < 4; j++) {
        int n = n0 + ty + j * 8, k = k0 + tx;
        float inv = 127.f / fmaxf(g_wmax[moff + n], 1e-20f);
        signed char hi, lo;
        q_split(tile[tx][ty + j * 8] * inv, hi, lo);
        oh[(size_t)n * K + k] = hi;
        ol[(size_t)n * K + k] = lo;
    }
}

template<int SEL>    // 0: Q, 1: K  (single-word s8)
__global__ __launch_bounds__(256)
void quant_qk()
{
    const float* src = (const float*)(g_pool + (SEL == 0 ? OFF_QF : OFF_KF));
    signed char* qh  = (signed char*)(g_pool + (SEL == 0 ? OFF_QQH : OFF_KQH));
    int fi = (blockIdx.x * 256 + threadIdx.x) * 4;
    int bh = fi >> 17;
    float inv = 127.f / g_qkvmax[(SEL == 0 ? 0 : 32) + bh];
    float4 v = *(const float4*)(src + fi);
    char4 h4;
    h4.x = (signed char)__float2int_rn(v.x * inv);
    h4.y = (signed char)__float2int_rn(v.y * inv);
    h4.z = (signed char)__float2int_rn(v.z * inv);
    h4.w = (signed char)__float2int_rn(v.w * inv);
    *(char4*)(qh + fi) = h4;
}

// V fp32 [bh][s][hd] -> transposed single-word s8 [bh][hd][s]
__global__ __launch_bounds__(256)
void quant_vt()
{
    __shared__ float tile[32][33];
    const int bh = blockIdx.z;
    const int s0 = blockIdx.x * 32, h0 = blockIdx.y * 32;
    const int tx = threadIdx.x & 31, ty = threadIdx.x >> 5;
    const float* VF = (const float*)(g_pool + OFF_VF) + (size_t)bh * SEQ * HDIM;
    signed char* TH = (signed char*)(g_pool + OFF_VTH) + (size_t)bh * HDIM * SEQ;
    #pragma unroll
    for (int j = 0; j < 4; j++)
        tile[ty + j * 8][tx] = VF[(size_t)(s0 + ty + j * 8) * HDIM + h0 + tx];
    __syncthreads();
    float inv = 127.f / g_qkvmax[64 + bh];
    #pragma unroll
    for (int j = 0; j < 4; j++) {
        int r = ty + j * 8;
        TH[(size_t)(h0 + r) * SEQ + s0 + tx] =
            (signed char)__float2int_rn(tile[tx][r] * inv);
    }
}

// ------------------------------ int8 GEMM ------------------------------------
// LIMBS: 1 (A single x B single), 2 (A single x B dual), 3 (A dual x B dual)
template<int MODE>
__global__ __launch_bounds__(256)
void gemm_i8(const float* __restrict__ bias, const float* __restrict__ resid)
{
    constexpr int KD    = (MODE == 5) ? FF : DMODEL;
    constexpr int NC    = KD / 64;
    constexpr int STG   = 30720;
    constexpr int LIMBS = (MODE <= 2) ? 1 : (MODE == 3) ? 2 : 3;

    extern __shared__ char smraw[];
    const uint32_t sb = smem_u32(smraw);

    const int tid = threadIdx.x, wid = tid >> 5, lane = tid & 31;
    const int wr = wid >> 1, wc = wid & 1;
    const int m0 = blockIdx.y * 128, n0 = blockIdx.x * 64;

    const signed char *Ah, *Al, *Bh, *Bl;
    const float *sAm, *sBm;
    if constexpr (MODE == 0) {
        Ah = (const signed char*)(g_pool + OFF_XQH); Al = nullptr;
        Bh = g_Wqh_q; Bl = nullptr; sAm = g_sX; sBm = g_wmax + 0;
    } else if constexpr (MODE == 1) {
        Ah = (const signed char*)(g_pool + OFF_XQH); Al = nullptr;
        Bh = g_Wkh_q; Bl = nullptr; sAm = g_sX; sBm = g_wmax + 1024;
    } else if constexpr (MODE == 2) {
        Ah = (const signed char*)(g_pool + OFF_XQH); Al = nullptr;
        Bh = g_Wvh_q; Bl = nullptr; sAm = g_sX; sBm = g_wmax + 2048;
    } else if constexpr (MODE == 3) {
        Ah = (const signed char*)(g_pool + OFF_OQH); Al = nullptr;
        Bh = g_Woh_q; Bl = g_Wol_q; sAm = g_sO; sBm = g_wmax + 3072;
    } else if constexpr (MODE == 4) {
        Ah = (const signed char*)(g_pool + OFF_YQH); Al = (const signed char*)(g_pool + OFF_YQL);
        Bh = g_W1h_q; Bl = g_W1l_q; sAm = g_sy; sBm = g_wmax + 5120;
    } else {
        Ah = (const signed char*)(g_pool + OFF_FQH); Al = (const signed char*)(g_pool + OFF_FQL);
        Bh = g_W2h_q; Bl = g_W2l_q; sAm = g_sff; sBm = g_wmax + 4096;
    }

    const signed char* rAh = Ah + (size_t)m0 * KD;
    const signed char* rAl = (LIMBS == 3) ? Al + (size_t)m0 * KD : nullptr;
    const signed char* rBh = Bh + (size_t)n0 * KD;
    const signed char* rBl = (LIMBS >= 2) ? Bl + (size_t)n0 * KD : nullptr;

    const int aldRow = tid >> 1, aldC0 = (tid & 1) * 2;
    const int bldRow = tid >> 2, bldC  = tid & 3;

    auto issue = [&](int k0, int st) {
        uint32_t base = sb + st * STG;
        #pragma unroll
        for (int i = 0; i < 2; i++) {
            int c = aldC0 + i;
            cpasync16(base + aldRow * 80 + c * 16,
                      rAh + (size_t)aldRow * KD + k0 + c * 16);
            if constexpr (LIMBS == 3)
                cpasync16(base + 10240 + aldRow * 80 + c * 16,
                          rAl + (size_t)aldRow * KD + k0 + c * 16);
        }
        cpasync16(base + 20480 + bldRow * 80 + bldC * 16,
                  rBh + (size_t)bldRow * KD + k0 + bldC * 16);
        if constexpr (LIMBS >= 2)
            cpasync16(base + 25600 + bldRow * 80 + bldC * 16,
                      rBl + (size_t)bldRow * KD + k0 + bldC * 16);
        asm volatile("cp.async.commit_group;" ::: "memory");
    };

    int acc1[2][4][4], acc2[2][4][4];
    #pragma unroll
    for (int i = 0; i < 2; i++)
        #pragma unroll
        for (int j = 0; j < 4; j++)
            #pragma unroll
            for (int q = 0; q < 4; q++) { acc1[i][j][q] = 0; acc2[i][j][q] = 0; }

    const int arow = ((lane >> 3) & 1) * 8 + (lane & 7);
    const int achk = lane >> 4;
    const uint32_t aA0 = sb + (uint32_t)(wr * 32 + arow) * 80 + achk * 16;
    const uint32_t bA0 = sb + 20480 + (uint32_t)(wc * 32 + arow) * 80 + achk * 16;

    issue(0, 0);

    for (int ct = 0; ct < NC; ct++) {
        if (ct + 1 < NC) {
            issue((ct + 1) * 64, (ct + 1) & 1);
            asm volatile("cp.async.wait_group 1;" ::: "memory");
        } else {
            asm volatile("cp.async.wait_group 0;" ::: "memory");
        }
        __syncthreads();
        const uint32_t off = (ct & 1) ? (uint32_t)STG : 0u;
        #pragma unroll
        for (int s = 0; s < 2; s++) {
            uint32_t bh[2][4], bl[2][4];
            #pragma unroll
            for (int bj = 0; bj < 2; bj++) {
                uint32_t ba = bA0 + off + bj * (16 * 80) + s * 32;
                ldsm4(bh[bj], ba);
                if constexpr (LIMBS >= 2) ldsm4(bl[bj], ba + 5120);
            }
            #pragma unroll
            for (int mi = 0; mi < 2; mi++) {
                uint32_t ah[4], al[4];
                uint32_t aa = aA0 + off + mi * (16 * 80) + s * 32;
                ldsm4(ah, aa);
                if constexpr (LIMBS == 3) ldsm4(al, aa + 10240);
                #pragma unroll
                for (int nj = 0; nj < 4; nj++) {
                    int bj = nj >> 1, oc = nj & 1;
                    uint32_t bfh[2] = { bh[bj][oc], bh[bj][oc + 2] };
                    mma_s8(acc1[mi][nj], ah, bfh);
                    if constexpr (LIMBS >= 2) {
                        uint32_t bfl[2] = { bl[bj][oc], bl[bj][oc + 2] };
                        mma_s8(acc2[mi][nj], ah, bfl);
                        if constexpr (LIMBS == 3) mma_s8(acc2[mi][nj], al, bfh);
                    }
                }
            }
        }
        __syncthreads();
    }

    const int qrow = lane >> 2, qcol = (lane & 3) * 2;
    const int mrow0 = m0 + wr * 32, ncol0 = n0 + wc * 32;

    float2 bias2[4], sB2[4];
    #pragma unroll
    for (int nj = 0; nj < 4; nj++) {
        int n = ncol0 + nj * 8 + qcol;
        bias2[nj] = *(const float2*)(bias + n);
        sB2[nj]   = *(const float2*)(sBm + n);
    }

    float vmax = 0.f;
    #pragma unroll
    for (int mi = 0; mi < 2; mi++) {
        #pragma unroll
        for (int half = 0; half < 2; half++) {
            int m = mrow0 + mi * 16 + qrow + half * 8;
            float sA = sAm[m] * (1.f / 16129.f);
            #pragma unroll
            for (int nj = 0; nj < 4; nj++) {
                int n = ncol0 + nj * 8 + qcol;
                float r0 = (float)acc1[mi][nj][half * 2 + 0];
                float r1 = (float)acc1[mi][nj][half * 2 + 1];
                if constexpr (LIMBS >= 2) {
                    r0 += (float)acc2[mi][nj][half * 2 + 0] * (1.f / 256.f);
                    r1 += (float)acc2[mi][nj][half * 2 + 1] * (1.f / 256.f);
                }
                float v0 = r0 * sA * sB2[nj].x + bias2[nj].x;
                float v1 = r1 * sA * sB2[nj].y + bias2[nj].y;
                if constexpr (MODE <= 2) {
                    float* outf = (float*)(g_pool +
                        (MODE == 0 ? OFF_QF : MODE == 1 ? OFF_KF : OFF_VF));
                    int b = m >> 11, si = m & 2047, h = n >> 6, e = n & 63;
                    size_t idx = (((size_t)(b * NHEAD + h) * SEQ) + si) * HDIM + e;
                    *(float2*)(outf + idx) = make_float2(v0, v1);
                    vmax = fmaxf(vmax, fmaxf(fabsf(v0), fabsf(v1)));
                } else if constexpr (MODE == 3) {
                    size_t idx = (size_t)m * DMODEL + n;
                    float2 rv = *(const float2*)(resid + idx);
                    *(float2*)((float*)(g_pool + OFF_T1) + idx) = make_float2(v0 + rv.x, v1 + rv.y);
                } else if constexpr (MODE == 4) {
                    size_t idx = (size_t)m * FF + n;
                    *(float2*)((float*)(g_pool + OFF_FF) + idx) =
                        make_float2(fmaxf(v0, 0.f), fmaxf(v1, 0.f));
                } else {
                    size_t idx = (size_t)m * DMODEL + n;
                    float2 rv = *(const float2*)((const float*)(g_pool + OFF_Y) + idx);
                    *(float2*)((float*)(g_pool + OFF_Z) + idx) = make_float2(v0 + rv.x, v1 + rv.y);
                }
            }
        }
    }
    if constexpr (MODE <= 2) {   // fused per-bh absmax (b, h constant per warp tile)
        #pragma unroll
        for (int o = 16; o >= 1; o >>= 1)
            vmax = fmaxf(vmax, __shfl_xor_sync(0xffffffffu, vmax, o));
        if (lane == 0) {
            int b = mrow0 >> 11, h = ncol0 >> 6;
            atomicMax((unsigned int*)&g_qkvmax[MODE * 32 + b * NHEAD + h],
                      __float_as_uint(fmaxf(vmax, 1e-20f)));
        }
    }
}

// ======================= Flash attention (s8; single-word QKV, dual P) =======
// B-fragment pairing for brow/bchk mapping: {f0,f1} rows0-7, {f2,f3} rows8-15.
__global__ __launch_bounds__(128, 4)
void attn_s8()
{
    extern __shared__ char smraw[];
    const uint32_t sb = smem_u32(smraw);
    const int tid = threadIdx.x, lane = tid & 31, w = tid >> 5;
    const int bh = blockIdx.y;
    const int q0 = blockIdx.x * 64;

    const signed char* Qh = (const signed char*)(g_pool + OFF_QQH) + (size_t)bh * SEQ * HDIM;
    const signed char* Kh = (const signed char*)(g_pool + OFF_KQH) + (size_t)bh * SEQ * HDIM;
    const signed char* Th = (const signed char*)(g_pool + OFF_VTH) + (size_t)bh * HDIM * SEQ;

    const float cS = g_qkvmax[bh] * g_qkvmax[32 + bh] * (1.f / (16129.f * 8.f));
    const float cV = g_qkvmax[64 + bh] * (1.f / 16129.f);

    {
        int row = tid >> 1;
        #pragma unroll
        for (int i = 0; i < 2; i++) {
            int c = (tid & 1) * 2 + i;
            cpasync16(sb + row * 80 + c * 16, Qh + (size_t)(q0 + row) * HDIM + c * 16);
        }
    }

    auto kv_issue = [&](int j, int st) {
        uint32_t base = sb + 5120 + st * 10240;
        int row = tid >> 1;
        #pragma unroll
        for (int i = 0; i < 2; i++) {
            int c = (tid & 1) * 2 + i;
            cpasync16(base + row * 80 + c * 16,
                      Kh + (size_t)(j * 64 + row) * HDIM + c * 16);
            cpasync16(base + 5120 + row * 80 + c * 16,
                      Th + (size_t)row * SEQ + j * 64 + c * 16);
        }
        asm volatile("cp.async.commit_group;" ::: "memory");
    };

    kv_issue(0, 0);

    const int arow = ((lane >> 3) & 1) * 8 + (lane & 7);
    const int achk = lane >> 4;
    const int brow = ((lane >> 4) & 1) * 8 + (lane & 7);
    const int bchk = (lane >> 3) & 1;
    const uint32_t qA0 = sb + (uint32_t)(w * 16 + arow) * 80 + achk * 16;
    const uint32_t Pw  = sb + 25600 + (uint32_t)w * 2560;
    const uint32_t pA0 = Pw + (uint32_t)arow * 80 + achk * 16;
    const int r = lane >> 2, cbase = (lane & 3) * 2;

    float acc[8][4];
    #pragma unroll
    for (int j = 0; j < 8; j++)
        #pragma unroll
        for (int q = 0; q < 4; q++) acc[j][q] = 0.f;
    float m0 = -1e30f, m1 = -1e30f, l0 = 0.f, l1 = 0.f;

    for (int jt = 0; jt < SEQ / 64; jt++) {
        if (jt + 1 < SEQ / 64) {
            kv_issue(jt + 1, (jt + 1) & 1);
            asm volatile("cp.async.wait_group 1;" ::: "memory");
        } else {
            asm volatile("cp.async.wait_group 0;" ::: "memory");
        }
        __syncthreads();
        const uint32_t stg = sb + 5120 + (jt & 1) * 10240;

        uint32_t qf[2][4];
        #pragma unroll
        for (int t = 0; t < 2; t++) ldsm4(qf[t], qA0 + t * 32);

        float s[8][4];
        #pragma unroll
        for (int np = 0; np < 4; np++) {
            int a1[2][4] = {{0,0,0,0},{0,0,0,0}};
            #pragma unroll
            for (int t = 0; t < 2; t++) {
                uint32_t kf[4];
                uint32_t ka = stg + (uint32_t)(np * 16 + brow) * 80 + bchk * 16 + t * 32;
                ldsm4(kf, ka);
                uint32_t b0[2] = { kf[0], kf[1] }, b1[2] = { kf[2], kf[3] };
                mma_s8(a1[0], qf[t], b0);
                mma_s8(a1[1], qf[t], b1);
            }
            #pragma unroll
            for (int o = 0; o < 2; o++)
                #pragma unroll
                for (int q = 0; q < 4; q++)
                    s[2 * np + o][q] = cS * (float)a1[o][q];
        }

        float mx0 = -1e30f, mx1 = -1e30f;
        #pragma unroll
        for (int j = 0; j < 8; j++) {
            mx0 = fmaxf(mx0, fmaxf(s[j][0], s[j][1]));
            mx1 = fmaxf(mx1, fmaxf(s[j][2], s[j][3]));
        }
        mx0 = fmaxf(mx0, __shfl_xor_sync(0xffffffffu, mx0, 1));
        mx0 = fmaxf(mx0, __shfl_xor_sync(0xffffffffu, mx0, 2));
        mx1 = fmaxf(mx1, __shfl_xor_sync(0xffffffffu, mx1, 1));
        mx1 = fmaxf(mx1, __shfl_xor_sync(0xffffffffu, mx1, 2));
        float mn0 = fmaxf(m0, mx0), mn1 = fmaxf(m1, mx1);
        float cr0 = __expf(m0 - mn0), cr1 = __expf(m1 - mn1);
        float sum0 = 0.f, sum1 = 0.f;
        #pragma unroll
        for (int j = 0; j < 8; j++) {
            s[j][0] = __expf(s[j][0] - mn0); sum0 += s[j][0];
            s[j][1] = __expf(s[j][1] - mn0); sum0 += s[j][1];
            s[j][2] = __expf(s[j][2] - mn1); sum1 += s[j][2];
            s[j][3] = __expf(s[j][3] - mn1); sum1 += s[j][3];
        }
        sum0 += __shfl_xor_sync(0xffffffffu, sum0, 1);
        sum0 += __shfl_xor_sync(0xffffffffu, sum0, 2);
        sum1 += __shfl_xor_sync(0xffffffffu, sum1, 1);
        sum1 += __shfl_xor_sync(0xffffffffu, sum1, 2);
        l0 = l0 * cr0 + sum0;  m0 = mn0;
        l1 = l1 * cr1 + sum1;  m1 = mn1;
        #pragma unroll
        for (int j = 0; j < 8; j++) {
            acc[j][0] *= cr0; acc[j][1] *= cr0;
            acc[j][2] *= cr1; acc[j][3] *= cr1;
        }

        #pragma unroll
        for (int j = 0; j < 8; j++) {
            int h0i = __float2int_rn(s[j][0] * 127.f);
            int l0i = min(127, max(-127, __float2int_rn((s[j][0] * 127.f - h0i) * 256.f)));
            int h1i = __float2int_rn(s[j][1] * 127.f);
            int l1i = min(127, max(-127, __float2int_rn((s[j][1] * 127.f - h1i) * 256.f)));
            int h2i = __float2int_rn(s[j][2] * 127.f);
            int l2i = min(127, max(-127, __float2int_rn((s[j][2] * 127.f - h2i) * 256.f)));
            int h3i = __float2int_rn(s[j][3] * 127.f);
            int l3i = min(127, max(-127, __float2int_rn((s[j][3] * 127.f - h3i) * 256.f)));
            uint32_t col = 8 * j + cbase;
            sts_u16(Pw + r * 80 + col,          (h0i & 0xFF) | ((h1i & 0xFF) << 8));
            sts_u16(Pw + 1280 + r * 80 + col,   (l0i & 0xFF) | ((l1i & 0xFF) << 8));
            sts_u16(Pw + (r + 8) * 80 + col,        (h2i & 0xFF) | ((h3i & 0xFF) << 8));
            sts_u16(Pw + 1280 + (r + 8) * 80 + col, (l2i & 0xFF) | ((l3i & 0xFF) << 8));
        }
        __syncwarp();

        uint32_t pfh[2][4], pfl[2][4];
        #pragma unroll
        for (int t = 0; t < 2; t++) {
            ldsm4(pfh[t], pA0 + t * 32);
            ldsm4(pfl[t], pA0 + 1280 + t * 32);
        }

        #pragma unroll
        for (int np = 0; np < 4; np++) {
            int a1[2][4] = {{0,0,0,0},{0,0,0,0}};
            int a2[2][4] = {{0,0,0,0},{0,0,0,0}};
            #pragma unroll
            for (int t = 0; t < 2; t++) {
                uint32_t vf[4];
                uint32_t va = stg + 5120 + (uint32_t)(np * 16 + brow) * 80 + bchk * 16 + t * 32;
                ldsm4(vf, va);
                uint32_t b0[2] = { vf[0], vf[1] }, b1[2] = { vf[2], vf[3] };
                mma_s8(a1[0], pfh[t], b0); mma_s8(a2[0], pfl[t], b0);
                mma_s8(a1[1], pfh[t], b1); mma_s8(a2[1], pfl[t], b1);
            }
            #pragma unroll
            for (int o = 0; o < 2; o++)
                #pragma unroll
                for (int q = 0; q < 4; q++)
                    acc[2 * np + o][q] += (float)a1[o][q] + (float)a2[o][q] * (1.f / 256.f);
        }
        __syncthreads();
    }

    const int b = bh >> 4, h = bh & 15;
    const float inv0 = cV / l0, inv1 = cV / l1;
    const int row0 = q0 + w * 16 + r;
    float* OB = (float*)(g_pool + OFF_O) + ((size_t)b * SEQ) * DMODEL + (size_t)h * HDIM;
    #pragma unroll
    for (int j = 0; j < 8; j++) {
        int col = 8 * j + cbase;
        *(float2*)(OB + (size_t)row0 * DMODEL + col) =
            make_float2(acc[j][0] * inv0, acc[j][1] * inv0);
        *(float2*)(OB + (size_t)(row0 + 8) * DMODEL + col) =
            make_float2(acc[j][2] * inv1, acc[j][3] * inv1);
    }
}

// =============================== LayerNorm ===================================
__global__ __launch_bounds__(256)
void ln_kernel(const float* __restrict__ g, const float* __restrict__ b,
               float* __restrict__ dstArg, int which)
{
    __shared__ float red[8];
    __shared__ float bc;
    const int tid = threadIdx.x;
    const int row = blockIdx.x;
    const float* src = (which == 0) ? (const float*)(g_pool + OFF_T1)
                                    : (const float*)(g_pool + OFF_Z);
    float* dst = (which == 0) ? (float*)(g_pool + OFF_Y) : dstArg;

    float4 v = ((const float4*)(src + (size_t)row * DMODEL))[tid];
    float s = v.x + v.y + v.z + v.w;
    #pragma unroll
    for (int o = 16; o >= 1; o >>= 1) s += __shfl_xor_sync(0xffffffffu, s, o);
    if ((tid & 31) == 0) red[tid >> 5] = s;
    __syncthreads();
    if (tid == 0) {
        float t = 0.f;
        #pragma unroll
        for (int i = 0; i < 8; i++) t += red[i];
        bc = t;
    }
    __syncthreads();
    float mu = bc * (1.f / DMODEL);
    float dx = v.x - mu, dy = v.y - mu, dz = v.z - mu, dw = v.w - mu;
    float s2 = dx * dx + dy * dy + dz * dz + dw * dw;
    #pragma unroll
    for (int o = 16; o >= 1; o >>= 1) s2 += __shfl_xor_sync(0xffffffffu, s2, o);
    __syncthreads();
    if ((tid & 31) == 0) red[tid >> 5] = s2;
    __syncthreads();
    if (tid == 0) {
        float t = 0.f;
        #pragma unroll
        for (int i = 0; i < 8; i++) t += red[i];
        bc = t;
    }
    __syncthreads();
    float rstd = rsqrtf(bc * (1.f / DMODEL) + 1e-5f);
    float4 gg = ((const float4*)g)[tid];
    float4 bb = ((const float4*)b)[tid];
    float4 o4;
    o4.x = dx * rstd * gg.x + bb.x;
    o4.y = dy * rstd * gg.y + bb.y;
    o4.z = dz * rstd * gg.z + bb.z;
    o4.w = dw * rstd * gg.w + bb.w;
    ((float4*)(dst + (size_t)row * DMODEL))[tid] = o4;

    if (which == 0) {
        float am = fmaxf(fmaxf(fabsf(o4.x), fabsf(o4.y)), fmaxf(fabsf(o4.z), fabsf(o4.w)));
        #pragma unroll
        for (int o = 16; o >= 1; o >>= 1) am = fmaxf(am, __shfl_xor_sync(0xffffffffu, am, o));
        __syncthreads();
        if ((tid & 31) == 0) red[tid >> 5] = am;
        __syncthreads();
        if (tid == 0) {
            float t = 1e-20f;
            #pragma unroll
            for (int i = 0; i < 8; i++) t = fmaxf(t, red[i]);
            bc = t; g_sy[row] = t;
        }
        __syncthreads();
        float inv = 127.f / bc;
        char4 h4, l4;
        q_split(o4.x * inv, h4.x, l4.x);
        q_split(o4.y * inv, h4.y, l4.y);
        q_split(o4.z * inv, h4.z, l4.z);
        q_split(o4.w * inv, h4.w, l4.w);
        size_t idx = (size_t)row * DMODEL + tid * 4;
        *(char4*)((signed char*)(g_pool + OFF_YQH) + idx) = h4;
        *(char4*)((signed char*)(g_pool + OFF_YQL) + idx) = l4;
    }
}

// ================================ launch =====================================
extern "C" void kernel_launch(void* const* d_in, const int* in_sizes, int n_in,
                              void* d_out, int out_size)
{
    (void)in_sizes; (void)n_in; (void)out_size;
    const float* X   = (const float*)d_in[0];
    const float* Wq  = (const float*)d_in[1];
    const float* bq  = (const float*)d_in[2];
    const float* Wk  = (const float*)d_in[3];
    const float* bk  = (const float*)d_in[4];
    const float* Wv  = (const float*)d_in[5];
    const float* bv  = (const float*)d_in[6];
    const float* Wo  = (const float*)d_in[7];
    const float* bo  = (const float*)d_in[8];
    const float* l1g = (const float*)d_in[9];
    const float* l1b = (const float*)d_in[10];
    const float* W1  = (const float*)d_in[11];
    const float* b1  = (const float*)d_in[12];
    const float* W2  = (const float*)d_in[13];
    const float* b2  = (const float*)d_in[14];
    const float* l2g = (const float*)d_in[15];
    const float* l2b = (const float*)d_in[16];

    const int g8_smem = 2 * 30720;
    cudaFuncSetAttribute(gemm_i8<0>, cudaFuncAttributeMaxDynamicSharedMemorySize, g8_smem);
    cudaFuncSetAttribute(gemm_i8<1>, cudaFuncAttributeMaxDynamicSharedMemorySize, g8_smem);
    cudaFuncSetAttribute(gemm_i8<2>, cudaFuncAttributeMaxDynamicSharedMemorySize, g8_smem);
    cudaFuncSetAttribute(gemm_i8<3>, cudaFuncAttributeMaxDynamicSharedMemorySize, g8_smem);
    cudaFuncSetAttribute(gemm_i8<4>, cudaFuncAttributeMaxDynamicSharedMemorySize, g8_smem);
    cudaFuncSetAttribute(gemm_i8<5>, cudaFuncAttributeMaxDynamicSharedMemorySize, g8_smem);
    const int attn_smem = 35840;
    cudaFuncSetAttribute(attn_s8, cudaFuncAttributeMaxDynamicSharedMemorySize, attn_smem);

    dim3 thr(256);

    zero_scales<<<37, thr>>>();
    quant_rows<1024, 0><<<MB, thr>>>(X);
    wcolmax<<<dim3(4, 32),  thr>>>(Wq, 1024, 1024, 1, 0);
    wcolmax<<<dim3(4, 32),  thr>>>(Wk, 1024, 1024, 1, 1024);
    wcolmax<<<dim3(4, 32),  thr>>>(Wv, 1024, 1024, 1, 2048);
    wcolmax<<<dim3(4, 32),  thr>>>(Wo, 1024, 1024, 0, 3072);
    wcolmax<<<dim3(4, 32),  thr>>>(W2, 4096, 1024, 0, 4096);
    wcolmax<<<dim3(16, 32), thr>>>(W1, 1024, 4096, 0, 5120);
    conv_wq<<<dim3(32, 32),  thr>>>(Wq, 1024, 1024, 0, 0);
    conv_wq<<<dim3(32, 32),  thr>>>(Wk, 1024, 1024, 1, 1024);
    conv_wq<<<dim3(32, 32),  thr>>>(Wv, 1024, 1024, 2, 2048);
    conv_wq<<<dim3(32, 32),  thr>>>(Wo, 1024, 1024, 3, 3072);
    conv_wq<<<dim3(128, 32), thr>>>(W1, 1024, 4096, 4, 5120);
    conv_wq<<<dim3(32, 128), thr>>>(W2, 4096, 1024, 5, 4096);

    // QKV projections (1-limb) with fused per-bh absmax
    gemm_i8<0><<<dim3(16, 32), thr, g8_smem>>>(bq, nullptr);
    gemm_i8<1><<<dim3(16, 32), thr, g8_smem>>>(bk, nullptr);
    gemm_i8<2><<<dim3(16, 32), thr, g8_smem>>>(bv, nullptr);

    quant_qk<0><<<4096, thr>>>();
    quant_qk<1><<<4096, thr>>>();
    quant_vt<<<dim3(64, 2, 32), thr>>>();

    attn_s8<<<dim3(32, 32), dim3(128), attn_smem>>>();

    quant_rows<1024, 1><<<MB, thr>>>(nullptr);
    gemm_i8<3><<<dim3(16, 32), thr, g8_smem>>>(bo, X);
    ln_kernel<<<MB, thr>>>(l1g, l1b, nullptr, 0);

    gemm_i8<4><<<dim3(64, 32), thr, g8_smem>>>(b1, nullptr);
    quant_rows<4096, 2><<<MB, thr>>>(nullptr);
    gemm_i8<5><<<dim3(16, 32), thr, g8_smem>>>(b2, nullptr);
    ln_kernel<<<MB, thr>>>(l2g, l2b, (float*)d_out, 1);
}